// round 1
// baseline (speedup 1.0000x reference)
#include <cuda_runtime.h>

// Problem constants
constexpr int BATCH = 4;
constexpr int SEQ   = 2048;
constexpr int DIM   = 128;
constexpr int HEADS = 8;
constexpr int HD    = 16;
constexpr int ROWS  = BATCH * SEQ;   // 8192

// Scratch (device globals — no allocation allowed)
__device__ float g_q[ROWS * DIM];
__device__ float g_k[ROWS * DIM];
__device__ float g_v[ROWS * DIM];
__device__ float g_o[ROWS * DIM];
__device__ float g_lwT[DIM * DIM];
__device__ float g_maskf[ROWS];

__constant__ int c_head_order[8] = {0, 1, 1, 2, 3, 4, 5, 6};

// ---------------------------------------------------------------------------
// Kernel 1: fused QKV projection.  out[row, j] = sum_d x[row,d] * W[d,j]
// blockIdx.y selects which of (Wq, Wk, Wv) / (g_q, g_k, g_v).
// 256 threads, 32 rows per block. x tile in smem, W read coalesced (L1/L2 hit).
// ---------------------------------------------------------------------------
__global__ __launch_bounds__(256) void qkv_kernel(
    const float* __restrict__ x,
    const float* __restrict__ wq,
    const float* __restrict__ wk,
    const float* __restrict__ wv)
{
    __shared__ float xs[32][128];
    const int tid  = threadIdx.x;
    const int row0 = blockIdx.x * 32;

    const float* W   = (blockIdx.y == 0) ? wq : (blockIdx.y == 1) ? wk : wv;
    float*       out = (blockIdx.y == 0) ? g_q : (blockIdx.y == 1) ? g_k : g_v;

    // load 32x128 x-tile as float4 (1024 float4s, 4 per thread)
    const float4* x4  = (const float4*)(x + (size_t)row0 * DIM);
    float4*       xs4 = (float4*)&xs[0][0];
    for (int i = tid; i < 1024; i += 256) xs4[i] = x4[i];
    __syncthreads();

    const int j  = tid & 127;   // output column
    const int rr = tid >> 7;    // 0 or 1; thread owns rows rr, rr+2, ..., rr+30

    float acc[16];
#pragma unroll
    for (int r = 0; r < 16; r++) acc[r] = 0.f;

#pragma unroll 4
    for (int d = 0; d < 128; d++) {
        float wval = W[d * 128 + j];        // coalesced across warp
#pragma unroll
        for (int r = 0; r < 16; r++)
            acc[r] = fmaf(xs[rr + r * 2][d], wval, acc[r]);  // smem broadcast
    }
#pragma unroll
    for (int r = 0; r < 16; r++)
        out[(size_t)(row0 + rr + r * 2) * DIM + j] = acc[r];
}

// ---------------------------------------------------------------------------
// Kernel 2: prep — transpose lin_w and convert mask to additive float.
// Mask dtype is auto-detected: if stored as int64 (LE), all high 32-bit words
// are zero; random 0/1 int32 data fails that test with prob ~2^-64.
// ---------------------------------------------------------------------------
__global__ __launch_bounds__(256) void prep_kernel(
    const float* __restrict__ lin_w,
    const int*   __restrict__ mraw)
{
    __shared__ int is64;
    if (threadIdx.x == 0) {
        int acc = 0;
        for (int i = 0; i < 64; i++) acc |= mraw[2 * i + 1];
        is64 = (acc == 0);
    }
    __syncthreads();

    // transpose lin_w: g_lwT[c*128 + j] = lin_w[j*128 + c]
    for (int idx = blockIdx.x * 256 + threadIdx.x; idx < DIM * DIM;
         idx += gridDim.x * 256) {
        int j = idx >> 7, c = idx & 127;
        g_lwT[c * 128 + j] = lin_w[idx];
    }
    // mask -> -1000 / 0
    for (int idx = blockIdx.x * 256 + threadIdx.x; idx < ROWS;
         idx += gridDim.x * 256) {
        int v = is64 ? mraw[2 * idx] : mraw[idx];
        g_maskf[idx] = (v == 0) ? -1000.0f : 0.0f;
    }
}

// ---------------------------------------------------------------------------
// Kernel 3: flash attention. One query row per thread, 128 threads/CTA.
// grid = (SEQ/128 query blocks, BATCH*HEADS pairs).
// K/V tiles of 256 keys x 16 fp32 staged in smem; broadcast float4 LDS reads.
// Online softmax with branchy max update (rare after warm-up).
// ---------------------------------------------------------------------------
__global__ __launch_bounds__(128) void attn_kernel()
{
    __shared__ float4 Ks[256 * 4];
    __shared__ float4 Vs[256 * 4];
    __shared__ float  ms[256];

    const int tid  = threadIdx.x;
    const int pair = blockIdx.y;          // 0..31
    const int b    = pair >> 3;
    const int h    = pair & 7;
    const int row  = blockIdx.x * 128 + tid;   // query index in [0, SEQ)

    const float* qp = g_q + ((size_t)(b * SEQ + row) * DIM + h * HD);
    const float4 q0 = ((const float4*)qp)[0];
    const float4 q1 = ((const float4*)qp)[1];
    const float4 q2 = ((const float4*)qp)[2];
    const float4 q3 = ((const float4*)qp)[3];

    float m = -1e30f, l = 0.f;
    float o[16];
#pragma unroll
    for (int d = 0; d < 16; d++) o[d] = 0.f;

    const float scale = 0.08838834764831845f;  // 1/sqrt(128)

    for (int t0 = 0; t0 < SEQ; t0 += 256) {
        __syncthreads();
        // cooperative tile load: 4 consecutive float4 per key (64B contiguous)
        for (int idx = tid; idx < 1024; idx += 128) {
            int key  = idx >> 2;
            int part = idx & 3;
            size_t base = (size_t)(b * SEQ + t0 + key) * DIM + h * HD;
            Ks[idx] = ((const float4*)(g_k + base))[part];
            Vs[idx] = ((const float4*)(g_v + base))[part];
        }
        for (int i2 = tid; i2 < 256; i2 += 128)
            ms[i2] = g_maskf[b * SEQ + t0 + i2];
        __syncthreads();

        for (int jj = 0; jj < 256; jj++) {
            const float4 ka = Ks[jj * 4 + 0];
            const float4 kb = Ks[jj * 4 + 1];
            const float4 kc = Ks[jj * 4 + 2];
            const float4 kd = Ks[jj * 4 + 3];

            float s0 = q0.x * ka.x + q0.y * ka.y + q0.z * ka.z + q0.w * ka.w;
            float s1 = q1.x * kb.x + q1.y * kb.y + q1.z * kb.z + q1.w * kb.w;
            float s2 = q2.x * kc.x + q2.y * kc.y + q2.z * kc.z + q2.w * kc.w;
            float s3 = q3.x * kd.x + q3.y * kd.y + q3.z * kd.z + q3.w * kd.w;
            float s  = (s0 + s1) + (s2 + s3);
            s = fmaf(s, scale, ms[jj]);

            if (s > m) {                    // rare after a few keys
                float corr = __expf(m - s);
                l *= corr;
#pragma unroll
                for (int d = 0; d < 16; d++) o[d] *= corr;
                m = s;
            }
            float p = __expf(s - m);
            l += p;

            const float4 va = Vs[jj * 4 + 0];
            const float4 vb = Vs[jj * 4 + 1];
            const float4 vc = Vs[jj * 4 + 2];
            const float4 vd = Vs[jj * 4 + 3];
            o[0]  = fmaf(p, va.x, o[0]);  o[1]  = fmaf(p, va.y, o[1]);
            o[2]  = fmaf(p, va.z, o[2]);  o[3]  = fmaf(p, va.w, o[3]);
            o[4]  = fmaf(p, vb.x, o[4]);  o[5]  = fmaf(p, vb.y, o[5]);
            o[6]  = fmaf(p, vb.z, o[6]);  o[7]  = fmaf(p, vb.w, o[7]);
            o[8]  = fmaf(p, vc.x, o[8]);  o[9]  = fmaf(p, vc.y, o[9]);
            o[10] = fmaf(p, vc.z, o[10]); o[11] = fmaf(p, vc.w, o[11]);
            o[12] = fmaf(p, vd.x, o[12]); o[13] = fmaf(p, vd.y, o[13]);
            o[14] = fmaf(p, vd.z, o[14]); o[15] = fmaf(p, vd.w, o[15]);
        }
    }

    const float inv = 1.0f / l;
    float* op = g_o + ((size_t)(b * SEQ + row) * DIM + h * HD);
    float4* op4 = (float4*)op;
#pragma unroll
    for (int k4 = 0; k4 < 4; k4++) {
        float4 v;
        v.x = o[k4 * 4 + 0] * inv;
        v.y = o[k4 * 4 + 1] * inv;
        v.z = o[k4 * 4 + 2] * inv;
        v.w = o[k4 * 4 + 3] * inv;
        op4[k4] = v;
    }
}

// ---------------------------------------------------------------------------
// Kernel 4: head-reordered gather + output projection.
// y[row, j] = lin_b[j] + sum_c attn[row, c] * lin_w[j, c]
// attn[row, c] = g_o[row, head_order[c/16]*16 + c%16]
// ---------------------------------------------------------------------------
__global__ __launch_bounds__(256) void proj_kernel(
    const float* __restrict__ lin_b,
    float* __restrict__ y)
{
    __shared__ float xs[32][128];
    const int tid  = threadIdx.x;
    const int row0 = blockIdx.x * 32;

    // load 32x128 attn tile with head reorder applied
    for (int i = tid; i < 4096; i += 256) {
        int r = i >> 7, c = i & 127;
        int src = c_head_order[c >> 4] * HD + (c & 15);
        xs[r][c] = g_o[(size_t)(row0 + r) * DIM + src];
    }
    __syncthreads();

    const int j  = tid & 127;
    const int rr = tid >> 7;

    float acc[16];
    const float bias = lin_b[j];
#pragma unroll
    for (int r = 0; r < 16; r++) acc[r] = bias;

#pragma unroll 4
    for (int c = 0; c < 128; c++) {
        float w = g_lwT[c * 128 + j];       // coalesced, L1/L2 hit
#pragma unroll
        for (int r = 0; r < 16; r++)
            acc[r] = fmaf(xs[rr + r * 2][c], w, acc[r]);
    }
#pragma unroll
    for (int r = 0; r < 16; r++)
        y[(size_t)(row0 + rr + r * 2) * DIM + j] = acc[r];
}

// ---------------------------------------------------------------------------
extern "C" void kernel_launch(void* const* d_in, const int* in_sizes, int n_in,
                              void* d_out, int out_size)
{
    const float* x    = (const float*)d_in[0];
    const int*   mraw = (const int*)  d_in[1];   // int32 or int64 view; auto-detected
    const float* wq   = (const float*)d_in[2];
    const float* wk   = (const float*)d_in[3];
    const float* wv   = (const float*)d_in[4];
    const float* lw   = (const float*)d_in[5];
    const float* lb   = (const float*)d_in[6];
    float*       y    = (float*)d_out;

    qkv_kernel<<<dim3(ROWS / 32, 3), 256>>>(x, wq, wk, wv);
    prep_kernel<<<64, 256>>>(lw, mraw);
    attn_kernel<<<dim3(SEQ / 128, BATCH * HEADS), 128>>>();
    proj_kernel<<<ROWS / 32, 256>>>(lb, y);
}

// round 2
// speedup vs baseline: 1.1749x; 1.1749x over previous
#include <cuda_runtime.h>

// Problem constants
constexpr int BATCH = 4;
constexpr int SEQ   = 2048;
constexpr int DIM   = 128;
constexpr int HD    = 16;
constexpr int ROWS  = BATCH * SEQ;   // 8192

// Scratch (device globals — no allocation allowed)
__device__ float g_q[ROWS * DIM];
__device__ float g_k[ROWS * DIM];
__device__ float g_v[ROWS * DIM];
__device__ float g_o[ROWS * DIM];
__device__ float g_lwT[DIM * DIM];
__device__ float g_maskf[ROWS];

__constant__ int c_head_order[8] = {0, 1, 1, 2, 3, 4, 5, 6};

// ---------------------------------------------------------------------------
// Packed fp32x2 helpers (FFMA2 path — ptxas never emits these from C++)
// ---------------------------------------------------------------------------
typedef unsigned long long u64;

__device__ __forceinline__ u64 pk2(float lo, float hi) {
    u64 r; asm("mov.b64 %0,{%1,%2};" : "=l"(r) : "f"(lo), "f"(hi)); return r;
}
__device__ __forceinline__ void upk2(float& lo, float& hi, u64 v) {
    asm("mov.b64 {%0,%1},%2;" : "=f"(lo), "=f"(hi) : "l"(v));
}
__device__ __forceinline__ u64 fma2_(u64 a, u64 b, u64 c) {
    u64 d; asm("fma.rn.f32x2 %0,%1,%2,%3;" : "=l"(d) : "l"(a), "l"(b), "l"(c)); return d;
}
__device__ __forceinline__ u64 mul2_(u64 a, u64 b) {
    u64 d; asm("mul.rn.f32x2 %0,%1,%2;" : "=l"(d) : "l"(a), "l"(b)); return d;
}
__device__ __forceinline__ u64 add2_(u64 a, u64 b) {
    u64 d; asm("add.rn.f32x2 %0,%1,%2;" : "=l"(d) : "l"(a), "l"(b)); return d;
}
__device__ __forceinline__ float ex2f(float x) {
    float y; asm("ex2.approx.ftz.f32 %0,%1;" : "=f"(y) : "f"(x)); return y;
}

// ---------------------------------------------------------------------------
// Kernel 1: fused QKV projection, f32x2 packed over column pairs.
// 16-row tiles, 256 threads; thread owns cols (2c, 2c+1) x 4 rows.
// ---------------------------------------------------------------------------
__global__ __launch_bounds__(256) void qkv_kernel(
    const float* __restrict__ x,
    const float* __restrict__ wq,
    const float* __restrict__ wk,
    const float* __restrict__ wv)
{
    __shared__ float xs[16][128];
    const int tid  = threadIdx.x;
    const int row0 = blockIdx.x * 16;

    const float* W   = (blockIdx.y == 0) ? wq : (blockIdx.y == 1) ? wk : wv;
    float*       out = (blockIdx.y == 0) ? g_q : (blockIdx.y == 1) ? g_k : g_v;

    // load 16x128 x-tile (512 float4s, 2 per thread)
    const float4* x4  = (const float4*)(x + (size_t)row0 * DIM);
    float4*       xs4 = (float4*)&xs[0][0];
    xs4[tid]       = x4[tid];
    xs4[tid + 256] = x4[tid + 256];
    __syncthreads();

    const int j  = (tid & 63) * 2;   // column pair
    const int rg = tid >> 6;         // 0..3; rows rg, rg+4, rg+8, rg+12

    u64 acc[4] = {0ull, 0ull, 0ull, 0ull};

#pragma unroll 4
    for (int d = 0; d < 128; d++) {
        float2 w2 = *(const float2*)&W[d * 128 + j];   // coalesced, pre-packed pair
        u64 wp = pk2(w2.x, w2.y);
#pragma unroll
        for (int r = 0; r < 4; r++) {
            float xv = xs[rg + r * 4][d];              // smem broadcast
            acc[r] = fma2_(pk2(xv, xv), wp, acc[r]);
        }
    }
#pragma unroll
    for (int r = 0; r < 4; r++) {
        float lo, hi; upk2(lo, hi, acc[r]);
        *(float2*)&out[(size_t)(row0 + rg + r * 4) * DIM + j] = make_float2(lo, hi);
    }
}

// ---------------------------------------------------------------------------
// Kernel 2: prep — transpose lin_w; mask -> additive log2-scale float.
// Mask dtype auto-detect (int64 LE -> high words all zero).
// ---------------------------------------------------------------------------
__global__ __launch_bounds__(256) void prep_kernel(
    const float* __restrict__ lin_w,
    const int*   __restrict__ mraw)
{
    __shared__ int is64;
    if (threadIdx.x == 0) {
        int acc = 0;
        for (int i = 0; i < 64; i++) acc |= mraw[2 * i + 1];
        is64 = (acc == 0);
    }
    __syncthreads();

    for (int idx = blockIdx.x * 256 + threadIdx.x; idx < DIM * DIM;
         idx += gridDim.x * 256) {
        int j = idx >> 7, c = idx & 127;
        g_lwT[c * 128 + j] = lin_w[idx];
    }
    // -1000 in natural log-space == -1000*log2(e) in base-2 space
    for (int idx = blockIdx.x * 256 + threadIdx.x; idx < ROWS;
         idx += gridDim.x * 256) {
        int v = is64 ? mraw[2 * idx] : mraw[idx];
        g_maskf[idx] = (v == 0) ? -1442.6950408889634f : 0.0f;
    }
}

// ---------------------------------------------------------------------------
// Kernel 3: flash attention with packed f32x2 math throughout.
// One query row per thread, 128 threads/CTA, grid (16, 32).
// K/V tiles (256 keys x 16 fp32) in smem as ulonglong2 -> operands land packed.
// Softmax in base 2: scale' = (1/sqrt(128))*log2(e), exp == single MUFU.EX2.
// ---------------------------------------------------------------------------
__global__ __launch_bounds__(128) void attn_kernel()
{
    __shared__ ulonglong2 Ks[256 * 4];   // 16KB
    __shared__ ulonglong2 Vs[256 * 4];   // 16KB
    __shared__ float      ms[256];

    const int tid  = threadIdx.x;
    const int pair = blockIdx.y;
    const int b    = pair >> 3;
    const int h    = pair & 7;
    const int row  = blockIdx.x * 128 + tid;

    const float* qp = g_q + ((size_t)(b * SEQ + row) * DIM + h * HD);
    const ulonglong2* qv = (const ulonglong2*)qp;     // 64B-aligned
    const ulonglong2 qA = qv[0], qB = qv[1], qC = qv[2], qD = qv[3];
    const u64 q0 = qA.x, q1 = qA.y, q2 = qB.x, q3 = qB.y;
    const u64 q4 = qC.x, q5 = qC.y, q6 = qD.x, q7 = qD.y;

    float m = -1e30f, l = 0.f;
    u64 o0 = 0, o1 = 0, o2 = 0, o3 = 0, o4 = 0, o5 = 0, o6 = 0, o7 = 0;

    const float scale = 0.08838834764831845f * 1.4426950408889634f; // 1/sqrt(128)*log2(e)

    for (int t0 = 0; t0 < SEQ; t0 += 256) {
        __syncthreads();
        float4* Ksf = (float4*)Ks;
        float4* Vsf = (float4*)Vs;
        for (int idx = tid; idx < 1024; idx += 128) {
            int key  = idx >> 2;
            int part = idx & 3;
            size_t base = (size_t)(b * SEQ + t0 + key) * DIM + h * HD;
            Ksf[idx] = ((const float4*)(g_k + base))[part];
            Vsf[idx] = ((const float4*)(g_v + base))[part];
        }
        for (int i2 = tid; i2 < 256; i2 += 128)
            ms[i2] = g_maskf[b * SEQ + t0 + i2];
        __syncthreads();

#pragma unroll 2
        for (int jj = 0; jj < 256; jj++) {
            const ulonglong2 ka = Ks[jj * 4 + 0];
            const ulonglong2 kb = Ks[jj * 4 + 1];
            const ulonglong2 kc = Ks[jj * 4 + 2];
            const ulonglong2 kd = Ks[jj * 4 + 3];

            u64 sa = mul2_(q0, ka.x);
            u64 sb = mul2_(q2, kb.x);
            sa = fma2_(q1, ka.y, sa);
            sb = fma2_(q3, kb.y, sb);
            sa = fma2_(q4, kc.x, sa);
            sb = fma2_(q5, kc.y, sb);
            sa = fma2_(q6, kd.x, sa);
            sb = fma2_(q7, kd.y, sb);
            u64 st = add2_(sa, sb);
            float slo, shi; upk2(slo, shi, st);
            float s = fmaf(slo + shi, scale, ms[jj]);

            if (s > m) {                       // rare after warm-up
                float corr = ex2f(m - s);
                u64 c2 = pk2(corr, corr);
                l *= corr;
                o0 = mul2_(o0, c2); o1 = mul2_(o1, c2);
                o2 = mul2_(o2, c2); o3 = mul2_(o3, c2);
                o4 = mul2_(o4, c2); o5 = mul2_(o5, c2);
                o6 = mul2_(o6, c2); o7 = mul2_(o7, c2);
                m = s;
            }
            float p = ex2f(s - m);             // single MUFU.EX2
            l += p;
            u64 pp = pk2(p, p);

            const ulonglong2 va = Vs[jj * 4 + 0];
            const ulonglong2 vb = Vs[jj * 4 + 1];
            const ulonglong2 vc = Vs[jj * 4 + 2];
            const ulonglong2 vd = Vs[jj * 4 + 3];
            o0 = fma2_(pp, va.x, o0); o1 = fma2_(pp, va.y, o1);
            o2 = fma2_(pp, vb.x, o2); o3 = fma2_(pp, vb.y, o3);
            o4 = fma2_(pp, vc.x, o4); o5 = fma2_(pp, vc.y, o5);
            o6 = fma2_(pp, vd.x, o6); o7 = fma2_(pp, vd.y, o7);
        }
    }

    const float inv = 1.0f / l;
    const u64 iv = pk2(inv, inv);
    float* op = g_o + ((size_t)(b * SEQ + row) * DIM + h * HD);
    ulonglong2* op2 = (ulonglong2*)op;
    ulonglong2 r0, r1, r2, r3;
    r0.x = mul2_(o0, iv); r0.y = mul2_(o1, iv);
    r1.x = mul2_(o2, iv); r1.y = mul2_(o3, iv);
    r2.x = mul2_(o4, iv); r2.y = mul2_(o5, iv);
    r3.x = mul2_(o6, iv); r3.y = mul2_(o7, iv);
    op2[0] = r0; op2[1] = r1; op2[2] = r2; op2[3] = r3;
}

// ---------------------------------------------------------------------------
// Kernel 4: head-reordered gather + output projection, f32x2 packed.
// 16-row tiles (grid 512), thread owns cols (2c, 2c+1) x 4 rows.
// ---------------------------------------------------------------------------
__global__ __launch_bounds__(256) void proj_kernel(
    const float* __restrict__ lin_b,
    float* __restrict__ y)
{
    __shared__ float xs[16][128];
    const int tid  = threadIdx.x;
    const int row0 = blockIdx.x * 16;

    // gather 16x128 attn tile with head reorder applied
    for (int i = tid; i < 2048; i += 256) {
        int r = i >> 7, c = i & 127;
        int src = c_head_order[c >> 4] * HD + (c & 15);
        xs[r][c] = g_o[(size_t)(row0 + r) * DIM + src];
    }
    __syncthreads();

    const int j  = (tid & 63) * 2;
    const int rg = tid >> 6;

    float2 b2 = *(const float2*)&lin_b[j];
    const u64 bias = pk2(b2.x, b2.y);
    u64 acc[4] = {bias, bias, bias, bias};

#pragma unroll 4
    for (int d = 0; d < 128; d++) {
        float2 w2 = *(const float2*)&g_lwT[d * 128 + j];
        u64 wp = pk2(w2.x, w2.y);
#pragma unroll
        for (int r = 0; r < 4; r++) {
            float xv = xs[rg + r * 4][d];
            acc[r] = fma2_(pk2(xv, xv), wp, acc[r]);
        }
    }
#pragma unroll
    for (int r = 0; r < 4; r++) {
        float lo, hi; upk2(lo, hi, acc[r]);
        *(float2*)&y[(size_t)(row0 + rg + r * 4) * DIM + j] = make_float2(lo, hi);
    }
}

// ---------------------------------------------------------------------------
extern "C" void kernel_launch(void* const* d_in, const int* in_sizes, int n_in,
                              void* d_out, int out_size)
{
    const float* x    = (const float*)d_in[0];
    const int*   mraw = (const int*)  d_in[1];   // int32/int64 auto-detected
    const float* wq   = (const float*)d_in[2];
    const float* wk   = (const float*)d_in[3];
    const float* wv   = (const float*)d_in[4];
    const float* lw   = (const float*)d_in[5];
    const float* lb   = (const float*)d_in[6];
    float*       y    = (float*)d_out;

    qkv_kernel<<<dim3(ROWS / 16, 3), 256>>>(x, wq, wk, wv);
    prep_kernel<<<64, 256>>>(lw, mraw);
    attn_kernel<<<dim3(SEQ / 128, BATCH * 8), 128>>>();
    proj_kernel<<<ROWS / 16, 256>>>(lb, y);
}

// round 3
// speedup vs baseline: 1.1819x; 1.0059x over previous
#include <cuda_runtime.h>

// Problem constants
constexpr int BATCH = 4;
constexpr int SEQ   = 2048;
constexpr int DIM   = 128;
constexpr int HD    = 16;
constexpr int ROWS  = BATCH * SEQ;        // 8192
constexpr int QH    = BATCH * 8 * SEQ;    // 65536 query-head rows
constexpr int KSPLIT = 2;

// Scratch (device globals — no allocation allowed)
__device__ float g_q[ROWS * DIM];
__device__ float g_k[ROWS * DIM];
__device__ float g_v[ROWS * DIM];
__device__ float g_o[ROWS * DIM];
__device__ float g_lwT[DIM * DIM];
__device__ float g_maskf[ROWS];
__device__ float g_po[KSPLIT * QH * HD];  // 8MB partial outputs (unnormalized)
__device__ float g_pm[KSPLIT * QH];
__device__ float g_pl[KSPLIT * QH];

__constant__ int c_head_order[8] = {0, 1, 1, 2, 3, 4, 5, 6};

// ---------------------------------------------------------------------------
// Packed fp32x2 helpers
// ---------------------------------------------------------------------------
typedef unsigned long long u64;

__device__ __forceinline__ u64 pk2(float lo, float hi) {
    u64 r; asm("mov.b64 %0,{%1,%2};" : "=l"(r) : "f"(lo), "f"(hi)); return r;
}
__device__ __forceinline__ void upk2(float& lo, float& hi, u64 v) {
    asm("mov.b64 {%0,%1},%2;" : "=f"(lo), "=f"(hi) : "l"(v));
}
__device__ __forceinline__ u64 fma2_(u64 a, u64 b, u64 c) {
    u64 d; asm("fma.rn.f32x2 %0,%1,%2,%3;" : "=l"(d) : "l"(a), "l"(b), "l"(c)); return d;
}
__device__ __forceinline__ u64 mul2_(u64 a, u64 b) {
    u64 d; asm("mul.rn.f32x2 %0,%1,%2;" : "=l"(d) : "l"(a), "l"(b)); return d;
}
__device__ __forceinline__ u64 add2_(u64 a, u64 b) {
    u64 d; asm("add.rn.f32x2 %0,%1,%2;" : "=l"(d) : "l"(a), "l"(b)); return d;
}
__device__ __forceinline__ float ex2f(float x) {
    float y; asm("ex2.approx.ftz.f32 %0,%1;" : "=f"(y) : "f"(x)); return y;
}

// ---------------------------------------------------------------------------
// Kernel 1: fused QKV projection. CTA = 32 rows x 128 cols, 256 threads.
// Thread owns col pair (2c,2c+1) x 8 rows. x-tile stored DUPLICATED (v,v) in
// smem so the inner loop is exactly LDS.64 + FFMA2 (no packing MOVs).
// W column pairs loaded directly as u64 (pre-packed).
// ---------------------------------------------------------------------------
__global__ __launch_bounds__(256) void qkv_kernel(
    const float* __restrict__ x,
    const float* __restrict__ wq,
    const float* __restrict__ wk,
    const float* __restrict__ wv)
{
    __shared__ u64 xd[32][128];   // 32KB duplicated x-tile
    const int tid  = threadIdx.x;
    const int row0 = blockIdx.x * 32;

    const float* W   = (blockIdx.y == 0) ? wq : (blockIdx.y == 1) ? wk : wv;
    float*       out = (blockIdx.y == 0) ? g_q : (blockIdx.y == 1) ? g_k : g_v;

    // load 32x128 x-tile: 1024 float4s, 4 per thread; write duplicated u64s
    const float4* x4 = (const float4*)(x + (size_t)row0 * DIM);
#pragma unroll
    for (int it = 0; it < 4; it++) {
        int i = tid + it * 256;
        float4 v = x4[i];
        int r = i >> 5, c = (i & 31) * 4;
        xd[r][c + 0] = pk2(v.x, v.x);
        xd[r][c + 1] = pk2(v.y, v.y);
        xd[r][c + 2] = pk2(v.z, v.z);
        xd[r][c + 3] = pk2(v.w, v.w);
    }
    __syncthreads();

    const int jh = tid & 63;    // column pair index (cols 2*jh, 2*jh+1)
    const int rg = tid >> 6;    // 0..3; rows rg, rg+4, ..., rg+28

    const u64* Wp = (const u64*)W;   // W row-pairs, 8B aligned

    u64 acc[8];
#pragma unroll
    for (int r = 0; r < 8; r++) acc[r] = 0ull;

#pragma unroll 4
    for (int d = 0; d < 128; d++) {
        u64 wp = Wp[d * 64 + jh];           // LDG.64, coalesced
#pragma unroll
        for (int r = 0; r < 8; r++)
            acc[r] = fma2_(xd[rg + r * 4][d], wp, acc[r]);  // LDS.64 + FFMA2
    }
    u64* outp = (u64*)out;
#pragma unroll
    for (int r = 0; r < 8; r++)
        outp[(size_t)(row0 + rg + r * 4) * 64 + jh] = acc[r];
}

// ---------------------------------------------------------------------------
// Kernel 2a: transpose lin_w -> g_lwT[c*128+j]
// ---------------------------------------------------------------------------
__global__ __launch_bounds__(256) void prepW_kernel(const float* __restrict__ lin_w)
{
    for (int idx = blockIdx.x * 256 + threadIdx.x; idx < DIM * DIM;
         idx += gridDim.x * 256) {
        int j = idx >> 7, c = idx & 127;
        g_lwT[c * 128 + j] = lin_w[idx];
    }
}

// ---------------------------------------------------------------------------
// Kernel 2b: mask -> additive log2-space float; dtype auto-detect
// (int64 LE -> high words all zero; prob of false positive ~2^-64).
// ---------------------------------------------------------------------------
__global__ __launch_bounds__(256) void prepM_kernel(const int* __restrict__ mraw)
{
    __shared__ int is64;
    if (threadIdx.x == 0) {
        int acc = 0;
        for (int i = 0; i < 64; i++) acc |= mraw[2 * i + 1];
        is64 = (acc == 0);
    }
    __syncthreads();
    for (int idx = blockIdx.x * 256 + threadIdx.x; idx < ROWS;
         idx += gridDim.x * 256) {
        int v = is64 ? mraw[2 * idx] : mraw[idx];
        g_maskf[idx] = (v == 0) ? -1442.6950408889634f : 0.0f; // -1000*log2(e)
    }
}

// ---------------------------------------------------------------------------
// Kernel 3: flash attention, 2 queries per thread, key-split by 2.
// grid (SEQ/256, 32 pairs, KSPLIT); block 128. Thread owns queries
// q0+tid and q0+tid+128 -> each K/V smem load serves both queries.
// Softmax in base 2 (single MUFU.EX2). Partials (o,m,l) to scratch.
// ---------------------------------------------------------------------------
__global__ __launch_bounds__(128) void attn_kernel()
{
    __shared__ ulonglong2 Ks[256 * 4];   // 16KB
    __shared__ ulonglong2 Vs[256 * 4];   // 16KB
    __shared__ float      ms[256];

    const int tid   = threadIdx.x;
    const int pair  = blockIdx.y;           // b*8 + h
    const int b     = pair >> 3;
    const int h     = pair & 7;
    const int rowA  = blockIdx.x * 256 + tid;
    const int rowB  = rowA + 128;
    const int zbase = blockIdx.z * (SEQ / KSPLIT);

    const ulonglong2* qvA = (const ulonglong2*)(g_q + ((size_t)(b * SEQ + rowA) * DIM + h * HD));
    const ulonglong2* qvB = (const ulonglong2*)(g_q + ((size_t)(b * SEQ + rowB) * DIM + h * HD));
    ulonglong2 qA0 = qvA[0], qA1 = qvA[1], qA2 = qvA[2], qA3 = qvA[3];
    ulonglong2 qB0 = qvB[0], qB1 = qvB[1], qB2 = qvB[2], qB3 = qvB[3];

    float mA = -1e30f, lA = 0.f, mB = -1e30f, lB = 0.f;
    u64 oA[8], oB[8];
#pragma unroll
    for (int d = 0; d < 8; d++) { oA[d] = 0; oB[d] = 0; }

    const float scale = 0.08838834764831845f * 1.4426950408889634f; // 1/sqrt(128)*log2(e)

    for (int t0 = 0; t0 < SEQ / KSPLIT; t0 += 256) {
        __syncthreads();
        float4* Ksf = (float4*)Ks;
        float4* Vsf = (float4*)Vs;
#pragma unroll
        for (int it = 0; it < 8; it++) {
            int idx  = tid + it * 128;
            int key  = idx >> 2;
            int part = idx & 3;
            size_t base = (size_t)(b * SEQ + zbase + t0 + key) * DIM + h * HD;
            Ksf[idx] = ((const float4*)(g_k + base))[part];
            Vsf[idx] = ((const float4*)(g_v + base))[part];
        }
        ms[tid]       = g_maskf[b * SEQ + zbase + t0 + tid];
        ms[tid + 128] = g_maskf[b * SEQ + zbase + t0 + tid + 128];
        __syncthreads();

#pragma unroll 2
        for (int jj = 0; jj < 256; jj++) {
            const ulonglong2 ka = Ks[jj * 4 + 0];
            const ulonglong2 kb = Ks[jj * 4 + 1];
            const ulonglong2 kc = Ks[jj * 4 + 2];
            const ulonglong2 kd = Ks[jj * 4 + 3];

            // scores for both queries off the same K registers
            u64 sa = mul2_(qA0.x, ka.x);
            u64 sb = mul2_(qB0.x, ka.x);
            sa = fma2_(qA0.y, ka.y, sa);  sb = fma2_(qB0.y, ka.y, sb);
            sa = fma2_(qA1.x, kb.x, sa);  sb = fma2_(qB1.x, kb.x, sb);
            sa = fma2_(qA1.y, kb.y, sa);  sb = fma2_(qB1.y, kb.y, sb);
            sa = fma2_(qA2.x, kc.x, sa);  sb = fma2_(qB2.x, kc.x, sb);
            sa = fma2_(qA2.y, kc.y, sa);  sb = fma2_(qB2.y, kc.y, sb);
            sa = fma2_(qA3.x, kd.x, sa);  sb = fma2_(qB3.x, kd.x, sb);
            sa = fma2_(qA3.y, kd.y, sa);  sb = fma2_(qB3.y, kd.y, sb);

            float mval = ms[jj];
            float alo, ahi, blo, bhi;
            upk2(alo, ahi, sa);
            upk2(blo, bhi, sb);
            float sA = fmaf(alo + ahi, scale, mval);
            float sB = fmaf(blo + bhi, scale, mval);

            if (sA > mA) {                       // ~H_2048 times total
                float corr = ex2f(mA - sA);
                u64 c2 = pk2(corr, corr);
                lA *= corr;
#pragma unroll
                for (int d = 0; d < 8; d++) oA[d] = mul2_(oA[d], c2);
                mA = sA;
            }
            if (sB > mB) {
                float corr = ex2f(mB - sB);
                u64 c2 = pk2(corr, corr);
                lB *= corr;
#pragma unroll
                for (int d = 0; d < 8; d++) oB[d] = mul2_(oB[d], c2);
                mB = sB;
            }
            float pA = ex2f(sA - mA);
            float pB = ex2f(sB - mB);
            lA += pA;
            lB += pB;
            u64 ppA = pk2(pA, pA);
            u64 ppB = pk2(pB, pB);

            const ulonglong2 va = Vs[jj * 4 + 0];
            const ulonglong2 vb = Vs[jj * 4 + 1];
            const ulonglong2 vc = Vs[jj * 4 + 2];
            const ulonglong2 vd = Vs[jj * 4 + 3];
            oA[0] = fma2_(ppA, va.x, oA[0]);  oB[0] = fma2_(ppB, va.x, oB[0]);
            oA[1] = fma2_(ppA, va.y, oA[1]);  oB[1] = fma2_(ppB, va.y, oB[1]);
            oA[2] = fma2_(ppA, vb.x, oA[2]);  oB[2] = fma2_(ppB, vb.x, oB[2]);
            oA[3] = fma2_(ppA, vb.y, oA[3]);  oB[3] = fma2_(ppB, vb.y, oB[3]);
            oA[4] = fma2_(ppA, vc.x, oA[4]);  oB[4] = fma2_(ppB, vc.x, oB[4]);
            oA[5] = fma2_(ppA, vc.y, oA[5]);  oB[5] = fma2_(ppB, vc.y, oB[5]);
            oA[6] = fma2_(ppA, vd.x, oA[6]);  oB[6] = fma2_(ppB, vd.x, oB[6]);
            oA[7] = fma2_(ppA, vd.y, oA[7]);  oB[7] = fma2_(ppB, vd.y, oB[7]);
        }
    }

    // write partials (unnormalized o, m, l)
    const int qA_idx = pair * SEQ + rowA;
    const int qB_idx = pair * SEQ + rowB;
    const int z      = blockIdx.z;

    ulonglong2* poA = (ulonglong2*)(g_po + ((size_t)z * QH + qA_idx) * HD);
    ulonglong2* poB = (ulonglong2*)(g_po + ((size_t)z * QH + qB_idx) * HD);
#pragma unroll
    for (int k4 = 0; k4 < 4; k4++) {
        ulonglong2 r;
        r.x = oA[k4 * 2]; r.y = oA[k4 * 2 + 1];
        poA[k4] = r;
    }
#pragma unroll
    for (int k4 = 0; k4 < 4; k4++) {
        ulonglong2 r;
        r.x = oB[k4 * 2]; r.y = oB[k4 * 2 + 1];
        poB[k4] = r;
    }
    g_pm[(size_t)z * QH + qA_idx] = mA;
    g_pl[(size_t)z * QH + qA_idx] = lA;
    g_pm[(size_t)z * QH + qB_idx] = mB;
    g_pl[(size_t)z * QH + qB_idx] = lB;
}

// ---------------------------------------------------------------------------
// Kernel 3b: merge the KSPLIT partials -> g_o (normalized)
// ---------------------------------------------------------------------------
__global__ __launch_bounds__(256) void merge_kernel()
{
    int qidx = blockIdx.x * 256 + threadIdx.x;
    if (qidx >= QH) return;
    const int pair = qidx >> 11;        // /2048
    const int row  = qidx & 2047;
    const int b    = pair >> 3;
    const int h    = pair & 7;

    float m0 = g_pm[qidx],      l0 = g_pl[qidx];
    float m1 = g_pm[QH + qidx], l1 = g_pl[QH + qidx];
    float mm = fmaxf(m0, m1);
    float c0 = ex2f(m0 - mm);
    float c1 = ex2f(m1 - mm);
    float inv = 1.0f / (l0 * c0 + l1 * c1);
    float s0 = c0 * inv, s1 = c1 * inv;

    const float4* p0 = (const float4*)(g_po + (size_t)qidx * HD);
    const float4* p1 = (const float4*)(g_po + ((size_t)QH + qidx) * HD);
    float4* out = (float4*)(g_o + ((size_t)(b * SEQ + row) * DIM + h * HD));
#pragma unroll
    for (int k4 = 0; k4 < 4; k4++) {
        float4 a = p0[k4], c = p1[k4], r;
        r.x = a.x * s0 + c.x * s1;
        r.y = a.y * s0 + c.y * s1;
        r.z = a.z * s0 + c.z * s1;
        r.w = a.w * s0 + c.w * s1;
        out[k4] = r;
    }
}

// ---------------------------------------------------------------------------
// Kernel 4: head-reordered gather + output projection (dup-packed smem).
// CTA 32 rows x 128 cols, 256 threads, thread = 2 cols x 8 rows.
// ---------------------------------------------------------------------------
__global__ __launch_bounds__(256) void proj_kernel(
    const float* __restrict__ lin_b,
    float* __restrict__ y)
{
    __shared__ u64 xd[32][128];
    const int tid  = threadIdx.x;
    const int row0 = blockIdx.x * 32;

    // gather 32x128 attn tile with head reorder; store duplicated
#pragma unroll
    for (int it = 0; it < 16; it++) {
        int i = tid + it * 256;
        int r = i >> 7, c = i & 127;
        int src = c_head_order[c >> 4] * HD + (c & 15);
        float v = g_o[(size_t)(row0 + r) * DIM + src];
        xd[r][c] = pk2(v, v);
    }
    __syncthreads();

    const int jh = tid & 63;
    const int rg = tid >> 6;

    float2 b2 = *(const float2*)&lin_b[jh * 2];
    const u64 bias = pk2(b2.x, b2.y);
    u64 acc[8];
#pragma unroll
    for (int r = 0; r < 8; r++) acc[r] = bias;

    const u64* Wp = (const u64*)g_lwT;
#pragma unroll 4
    for (int d = 0; d < 128; d++) {
        u64 wp = Wp[d * 64 + jh];
#pragma unroll
        for (int r = 0; r < 8; r++)
            acc[r] = fma2_(xd[rg + r * 4][d], wp, acc[r]);
    }
    u64* yp = (u64*)y;
#pragma unroll
    for (int r = 0; r < 8; r++)
        yp[(size_t)(row0 + rg + r * 4) * 64 + jh] = acc[r];
}

// ---------------------------------------------------------------------------
extern "C" void kernel_launch(void* const* d_in, const int* in_sizes, int n_in,
                              void* d_out, int out_size)
{
    const float* x    = (const float*)d_in[0];
    const int*   mraw = (const int*)  d_in[1];   // int32/int64 auto-detected
    const float* wq   = (const float*)d_in[2];
    const float* wk   = (const float*)d_in[3];
    const float* wv   = (const float*)d_in[4];
    const float* lw   = (const float*)d_in[5];
    const float* lb   = (const float*)d_in[6];
    float*       y    = (float*)d_out;

    qkv_kernel<<<dim3(ROWS / 32, 3), 256>>>(x, wq, wk, wv);
    prepW_kernel<<<64, 256>>>(lw);
    prepM_kernel<<<32, 256>>>(mraw);
    attn_kernel<<<dim3(SEQ / 256, 32, KSPLIT), 128>>>();   // app launch idx 5 (ncu target)
    merge_kernel<<<QH / 256, 256>>>();
    proj_kernel<<<ROWS / 32, 256>>>(lb, y);
}

// round 4
// speedup vs baseline: 1.3476x; 1.1402x over previous
#include <cuda_runtime.h>

// Problem constants
constexpr int BATCH = 4;
constexpr int SEQ   = 2048;
constexpr int DIM   = 128;
constexpr int HD    = 16;
constexpr int ROWS  = BATCH * SEQ;        // 8192
constexpr int QH    = BATCH * 8 * SEQ;    // 65536 query-head rows
constexpr int KSPLIT = 4;

// Scratch (device globals — no allocation allowed)
__device__ float g_q[ROWS * DIM];
__device__ float g_k[ROWS * DIM];     // pre-scaled by (1/sqrt(128))*log2(e)
__device__ float g_v[ROWS * DIM];
__device__ float g_o[ROWS * DIM];
__device__ float g_lwT[DIM * DIM];
__device__ float g_maskf[ROWS];
__device__ float g_po[KSPLIT * QH * HD];  // partial outputs (unnormalized)
__device__ float g_pm[KSPLIT * QH];
__device__ float g_pl[KSPLIT * QH];

__constant__ int c_head_order[8] = {0, 1, 1, 2, 3, 4, 5, 6};

// ---------------------------------------------------------------------------
// Packed fp32x2 helpers
// ---------------------------------------------------------------------------
typedef unsigned long long u64;

__device__ __forceinline__ u64 pk2(float lo, float hi) {
    u64 r; asm("mov.b64 %0,{%1,%2};" : "=l"(r) : "f"(lo), "f"(hi)); return r;
}
__device__ __forceinline__ void upk2(float& lo, float& hi, u64 v) {
    asm("mov.b64 {%0,%1},%2;" : "=f"(lo), "=f"(hi) : "l"(v));
}
__device__ __forceinline__ u64 fma2_(u64 a, u64 b, u64 c) {
    u64 d; asm("fma.rn.f32x2 %0,%1,%2,%3;" : "=l"(d) : "l"(a), "l"(b), "l"(c)); return d;
}
__device__ __forceinline__ u64 mul2_(u64 a, u64 b) {
    u64 d; asm("mul.rn.f32x2 %0,%1,%2;" : "=l"(d) : "l"(a), "l"(b)); return d;
}
__device__ __forceinline__ float ex2f(float x) {
    float y; asm("ex2.approx.ftz.f32 %0,%1;" : "=f"(y) : "f"(x)); return y;
}

// ---------------------------------------------------------------------------
// Kernel 1: fused QKV projection. CTA = 32 rows x 128 cols, 256 threads.
// K output is pre-scaled by (1/sqrt(128))*log2(e) so attention's score is a
// plain add of the (log2-space) mask.
// ---------------------------------------------------------------------------
__global__ __launch_bounds__(256) void qkv_kernel(
    const float* __restrict__ x,
    const float* __restrict__ wq,
    const float* __restrict__ wk,
    const float* __restrict__ wv)
{
    __shared__ u64 xd[32][128];   // 32KB duplicated x-tile
    const int tid  = threadIdx.x;
    const int row0 = blockIdx.x * 32;

    const float* W   = (blockIdx.y == 0) ? wq : (blockIdx.y == 1) ? wk : wv;
    float*       out = (blockIdx.y == 0) ? g_q : (blockIdx.y == 1) ? g_k : g_v;

    const float4* x4 = (const float4*)(x + (size_t)row0 * DIM);
#pragma unroll
    for (int it = 0; it < 4; it++) {
        int i = tid + it * 256;
        float4 v = x4[i];
        int r = i >> 5, c = (i & 31) * 4;
        xd[r][c + 0] = pk2(v.x, v.x);
        xd[r][c + 1] = pk2(v.y, v.y);
        xd[r][c + 2] = pk2(v.z, v.z);
        xd[r][c + 3] = pk2(v.w, v.w);
    }
    __syncthreads();

    const int jh = tid & 63;
    const int rg = tid >> 6;

    const u64* Wp = (const u64*)W;

    u64 acc[8];
#pragma unroll
    for (int r = 0; r < 8; r++) acc[r] = 0ull;

#pragma unroll 4
    for (int d = 0; d < 128; d++) {
        u64 wp = Wp[d * 64 + jh];
#pragma unroll
        for (int r = 0; r < 8; r++)
            acc[r] = fma2_(xd[rg + r * 4][d], wp, acc[r]);
    }

    if (blockIdx.y == 1) {       // pre-scale K
        const float sc = 0.08838834764831845f * 1.4426950408889634f;
        const u64 sc2 = pk2(sc, sc);
#pragma unroll
        for (int r = 0; r < 8; r++) acc[r] = mul2_(acc[r], sc2);
    }

    u64* outp = (u64*)out;
#pragma unroll
    for (int r = 0; r < 8; r++)
        outp[(size_t)(row0 + rg + r * 4) * 64 + jh] = acc[r];
}

// ---------------------------------------------------------------------------
// Kernel 2a: transpose lin_w -> g_lwT[c*128+j]
// ---------------------------------------------------------------------------
__global__ __launch_bounds__(256) void prepW_kernel(const float* __restrict__ lin_w)
{
    for (int idx = blockIdx.x * 256 + threadIdx.x; idx < DIM * DIM;
         idx += gridDim.x * 256) {
        int j = idx >> 7, c = idx & 127;
        g_lwT[c * 128 + j] = lin_w[idx];
    }
}

// ---------------------------------------------------------------------------
// Kernel 2b: mask -> additive log2-space float; dtype auto-detect.
// ---------------------------------------------------------------------------
__global__ __launch_bounds__(256) void prepM_kernel(const int* __restrict__ mraw)
{
    __shared__ int is64;
    if (threadIdx.x == 0) {
        int acc = 0;
        for (int i = 0; i < 64; i++) acc |= mraw[2 * i + 1];
        is64 = (acc == 0);
    }
    __syncthreads();
    for (int idx = blockIdx.x * 256 + threadIdx.x; idx < ROWS;
         idx += gridDim.x * 256) {
        int v = is64 ? mraw[2 * idx] : mraw[idx];
        g_maskf[idx] = (v == 0) ? -1442.6950408889634f : 0.0f; // -1000*log2(e)
    }
}

// ---------------------------------------------------------------------------
// Kernel 3: flash attention, 2 queries/thread, key-split by 4.
// grid (SEQ/256, 32, KSPLIT); block 128. K pre-scaled -> score = dot + mask.
// Single merged rescale branch per key (arm handles both queries branchlessly).
// ---------------------------------------------------------------------------
__global__ __launch_bounds__(128) void attn_kernel()
{
    __shared__ ulonglong2 Ks[256 * 4];   // 16KB
    __shared__ ulonglong2 Vs[256 * 4];   // 16KB
    __shared__ float      ms[256];

    const int tid   = threadIdx.x;
    const int pair  = blockIdx.y;           // b*8 + h
    const int b     = pair >> 3;
    const int h     = pair & 7;
    const int rowA  = blockIdx.x * 256 + tid;
    const int rowB  = rowA + 128;
    const int zbase = blockIdx.z * (SEQ / KSPLIT);

    const ulonglong2* qvA = (const ulonglong2*)(g_q + ((size_t)(b * SEQ + rowA) * DIM + h * HD));
    const ulonglong2* qvB = (const ulonglong2*)(g_q + ((size_t)(b * SEQ + rowB) * DIM + h * HD));
    ulonglong2 qA0 = qvA[0], qA1 = qvA[1], qA2 = qvA[2], qA3 = qvA[3];
    ulonglong2 qB0 = qvB[0], qB1 = qvB[1], qB2 = qvB[2], qB3 = qvB[3];

    float mA = -1e30f, lA = 0.f, mB = -1e30f, lB = 0.f;
    u64 oA[8], oB[8];
#pragma unroll
    for (int d = 0; d < 8; d++) { oA[d] = 0; oB[d] = 0; }

    for (int t0 = 0; t0 < SEQ / KSPLIT; t0 += 256) {
        __syncthreads();
        float4* Ksf = (float4*)Ks;
        float4* Vsf = (float4*)Vs;
#pragma unroll
        for (int it = 0; it < 8; it++) {
            int idx  = tid + it * 128;
            int key  = idx >> 2;
            int part = idx & 3;
            size_t base = (size_t)(b * SEQ + zbase + t0 + key) * DIM + h * HD;
            Ksf[idx] = ((const float4*)(g_k + base))[part];
            Vsf[idx] = ((const float4*)(g_v + base))[part];
        }
        ms[tid]       = g_maskf[b * SEQ + zbase + t0 + tid];
        ms[tid + 128] = g_maskf[b * SEQ + zbase + t0 + tid + 128];
        __syncthreads();

#pragma unroll 2
        for (int jj = 0; jj < 256; jj++) {
            const ulonglong2 ka = Ks[jj * 4 + 0];
            const ulonglong2 kb = Ks[jj * 4 + 1];
            const ulonglong2 kc = Ks[jj * 4 + 2];
            const ulonglong2 kd = Ks[jj * 4 + 3];

            u64 sa = mul2_(qA0.x, ka.x);
            u64 sb = mul2_(qB0.x, ka.x);
            sa = fma2_(qA0.y, ka.y, sa);  sb = fma2_(qB0.y, ka.y, sb);
            sa = fma2_(qA1.x, kb.x, sa);  sb = fma2_(qB1.x, kb.x, sb);
            sa = fma2_(qA1.y, kb.y, sa);  sb = fma2_(qB1.y, kb.y, sb);
            sa = fma2_(qA2.x, kc.x, sa);  sb = fma2_(qB2.x, kc.x, sb);
            sa = fma2_(qA2.y, kc.y, sa);  sb = fma2_(qB2.y, kc.y, sb);
            sa = fma2_(qA3.x, kd.x, sa);  sb = fma2_(qB3.x, kd.x, sb);
            sa = fma2_(qA3.y, kd.y, sa);  sb = fma2_(qB3.y, kd.y, sb);

            float mval = ms[jj];
            float alo, ahi, blo, bhi;
            upk2(alo, ahi, sa);
            upk2(blo, bhi, sb);
            float sA = (alo + ahi) + mval;   // K pre-scaled -> just adds
            float sB = (blo + bhi) + mval;

            // single branch envelope; arm is branchless for both queries
            if ((sA > mA) | (sB > mB)) {
                float mAn = fmaxf(mA, sA);
                float mBn = fmaxf(mB, sB);
                float cA = ex2f(mA - mAn);   // ==1 when this query didn't update
                float cB = ex2f(mB - mBn);
                u64 cA2 = pk2(cA, cA);
                u64 cB2 = pk2(cB, cB);
                lA *= cA; lB *= cB;
#pragma unroll
                for (int d = 0; d < 8; d++) {
                    oA[d] = mul2_(oA[d], cA2);
                    oB[d] = mul2_(oB[d], cB2);
                }
                mA = mAn; mB = mBn;
            }
            float pA = ex2f(sA - mA);
            float pB = ex2f(sB - mB);
            lA += pA;
            lB += pB;
            u64 ppA = pk2(pA, pA);
            u64 ppB = pk2(pB, pB);

            const ulonglong2 va = Vs[jj * 4 + 0];
            const ulonglong2 vb = Vs[jj * 4 + 1];
            const ulonglong2 vc = Vs[jj * 4 + 2];
            const ulonglong2 vd = Vs[jj * 4 + 3];
            oA[0] = fma2_(ppA, va.x, oA[0]);  oB[0] = fma2_(ppB, va.x, oB[0]);
            oA[1] = fma2_(ppA, va.y, oA[1]);  oB[1] = fma2_(ppB, va.y, oB[1]);
            oA[2] = fma2_(ppA, vb.x, oA[2]);  oB[2] = fma2_(ppB, vb.x, oB[2]);
            oA[3] = fma2_(ppA, vb.y, oA[3]);  oB[3] = fma2_(ppB, vb.y, oB[3]);
            oA[4] = fma2_(ppA, vc.x, oA[4]);  oB[4] = fma2_(ppB, vc.x, oB[4]);
            oA[5] = fma2_(ppA, vc.y, oA[5]);  oB[5] = fma2_(ppB, vc.y, oB[5]);
            oA[6] = fma2_(ppA, vd.x, oA[6]);  oB[6] = fma2_(ppB, vd.x, oB[6]);
            oA[7] = fma2_(ppA, vd.y, oA[7]);  oB[7] = fma2_(ppB, vd.y, oB[7]);
        }
    }

    const int qA_idx = pair * SEQ + rowA;
    const int qB_idx = pair * SEQ + rowB;
    const int z      = blockIdx.z;

    ulonglong2* poA = (ulonglong2*)(g_po + ((size_t)z * QH + qA_idx) * HD);
    ulonglong2* poB = (ulonglong2*)(g_po + ((size_t)z * QH + qB_idx) * HD);
#pragma unroll
    for (int k4 = 0; k4 < 4; k4++) {
        ulonglong2 r;
        r.x = oA[k4 * 2]; r.y = oA[k4 * 2 + 1];
        poA[k4] = r;
    }
#pragma unroll
    for (int k4 = 0; k4 < 4; k4++) {
        ulonglong2 r;
        r.x = oB[k4 * 2]; r.y = oB[k4 * 2 + 1];
        poB[k4] = r;
    }
    g_pm[(size_t)z * QH + qA_idx] = mA;
    g_pl[(size_t)z * QH + qA_idx] = lA;
    g_pm[(size_t)z * QH + qB_idx] = mB;
    g_pl[(size_t)z * QH + qB_idx] = lB;
}

// ---------------------------------------------------------------------------
// Kernel 3b: merge KSPLIT partials -> g_o (normalized)
// ---------------------------------------------------------------------------
__global__ __launch_bounds__(256) void merge_kernel()
{
    int qidx = blockIdx.x * 256 + threadIdx.x;
    if (qidx >= QH) return;
    const int pair = qidx >> 11;
    const int row  = qidx & 2047;
    const int b    = pair >> 3;
    const int h    = pair & 7;

    float m[KSPLIT], l[KSPLIT], c[KSPLIT];
    float mm = -1e30f;
#pragma unroll
    for (int z = 0; z < KSPLIT; z++) {
        m[z] = g_pm[(size_t)z * QH + qidx];
        l[z] = g_pl[(size_t)z * QH + qidx];
        mm = fmaxf(mm, m[z]);
    }
    float denom = 0.f;
#pragma unroll
    for (int z = 0; z < KSPLIT; z++) {
        c[z] = ex2f(m[z] - mm);
        denom += l[z] * c[z];
    }
    float inv = 1.0f / denom;
#pragma unroll
    for (int z = 0; z < KSPLIT; z++) c[z] *= inv;

    float4* out = (float4*)(g_o + ((size_t)(b * SEQ + row) * DIM + h * HD));
#pragma unroll
    for (int k4 = 0; k4 < 4; k4++) {
        float4 r = make_float4(0.f, 0.f, 0.f, 0.f);
#pragma unroll
        for (int z = 0; z < KSPLIT; z++) {
            const float4 a = ((const float4*)(g_po + ((size_t)z * QH + qidx) * HD))[k4];
            r.x = fmaf(a.x, c[z], r.x);
            r.y = fmaf(a.y, c[z], r.y);
            r.z = fmaf(a.z, c[z], r.z);
            r.w = fmaf(a.w, c[z], r.w);
        }
        out[k4] = r;
    }
}

// ---------------------------------------------------------------------------
// Kernel 4: head-reordered gather + output projection (dup-packed smem).
// ---------------------------------------------------------------------------
__global__ __launch_bounds__(256) void proj_kernel(
    const float* __restrict__ lin_b,
    float* __restrict__ y)
{
    __shared__ u64 xd[32][128];
    const int tid  = threadIdx.x;
    const int row0 = blockIdx.x * 32;

#pragma unroll
    for (int it = 0; it < 16; it++) {
        int i = tid + it * 256;
        int r = i >> 7, c = i & 127;
        int src = c_head_order[c >> 4] * HD + (c & 15);
        float v = g_o[(size_t)(row0 + r) * DIM + src];
        xd[r][c] = pk2(v, v);
    }
    __syncthreads();

    const int jh = tid & 63;
    const int rg = tid >> 6;

    float2 b2 = *(const float2*)&lin_b[jh * 2];
    const u64 bias = pk2(b2.x, b2.y);
    u64 acc[8];
#pragma unroll
    for (int r = 0; r < 8; r++) acc[r] = bias;

    const u64* Wp = (const u64*)g_lwT;
#pragma unroll 4
    for (int d = 0; d < 128; d++) {
        u64 wp = Wp[d * 64 + jh];
#pragma unroll
        for (int r = 0; r < 8; r++)
            acc[r] = fma2_(xd[rg + r * 4][d], wp, acc[r]);
    }
    u64* yp = (u64*)y;
#pragma unroll
    for (int r = 0; r < 8; r++)
        yp[(size_t)(row0 + rg + r * 4) * 64 + jh] = acc[r];
}

// ---------------------------------------------------------------------------
extern "C" void kernel_launch(void* const* d_in, const int* in_sizes, int n_in,
                              void* d_out, int out_size)
{
    const float* x    = (const float*)d_in[0];
    const int*   mraw = (const int*)  d_in[1];   // int32/int64 auto-detected
    const float* wq   = (const float*)d_in[2];
    const float* wk   = (const float*)d_in[3];
    const float* wv   = (const float*)d_in[4];
    const float* lw   = (const float*)d_in[5];
    const float* lb   = (const float*)d_in[6];
    float*       y    = (float*)d_out;

    qkv_kernel<<<dim3(ROWS / 32, 3), 256>>>(x, wq, wk, wv);
    prepW_kernel<<<64, 256>>>(lw);
    prepM_kernel<<<32, 256>>>(mraw);
    attn_kernel<<<dim3(SEQ / 256, 32, KSPLIT), 128>>>();
    merge_kernel<<<QH / 256, 256>>>();
    proj_kernel<<<ROWS / 32, 256>>>(lb, y);
}

// round 5
// speedup vs baseline: 1.5944x; 1.1831x over previous
#include <cuda_runtime.h>

// Problem constants
constexpr int BATCH = 4;
constexpr int SEQ   = 2048;
constexpr int DIM   = 128;
constexpr int HD    = 16;
constexpr int ROWS  = BATCH * SEQ;        // 8192
constexpr int QH    = BATCH * 8 * SEQ;    // 65536 query-head rows
constexpr int KSPLIT = 8;                 // 256 keys per CTA (one tile)

// Scratch (device globals — no allocation allowed)
__device__ float g_q[ROWS * DIM];
__device__ float g_k[ROWS * DIM];     // pre-scaled by (1/sqrt(128))*log2(e)
__device__ float g_v[ROWS * DIM];
__device__ float g_o[ROWS * DIM];
__device__ float g_lwT[DIM * DIM];
__device__ float g_maskf[ROWS];
__device__ float g_po[KSPLIT * QH * HD];  // partial outputs (unnormalized)
__device__ float g_pm[KSPLIT * QH];
__device__ float g_pl[KSPLIT * QH];

__constant__ int c_head_order[8] = {0, 1, 1, 2, 3, 4, 5, 6};

// ---------------------------------------------------------------------------
// Packed fp32x2 helpers
// ---------------------------------------------------------------------------
typedef unsigned long long u64;

__device__ __forceinline__ u64 pk2(float lo, float hi) {
    u64 r; asm("mov.b64 %0,{%1,%2};" : "=l"(r) : "f"(lo), "f"(hi)); return r;
}
__device__ __forceinline__ void upk2(float& lo, float& hi, u64 v) {
    asm("mov.b64 {%0,%1},%2;" : "=f"(lo), "=f"(hi) : "l"(v));
}
__device__ __forceinline__ u64 fma2_(u64 a, u64 b, u64 c) {
    u64 d; asm("fma.rn.f32x2 %0,%1,%2,%3;" : "=l"(d) : "l"(a), "l"(b), "l"(c)); return d;
}
__device__ __forceinline__ u64 mul2_(u64 a, u64 b) {
    u64 d; asm("mul.rn.f32x2 %0,%1,%2;" : "=l"(d) : "l"(a), "l"(b)); return d;
}
__device__ __forceinline__ float ex2f(float x) {
    float y; asm("ex2.approx.ftz.f32 %0,%1;" : "=f"(y) : "f"(x)); return y;
}

// ---------------------------------------------------------------------------
// Kernel 1: fused QKV projection. CTA = 32 rows x 128 cols, 256 threads.
// K output pre-scaled by (1/sqrt(128))*log2(e).
// ---------------------------------------------------------------------------
__global__ __launch_bounds__(256) void qkv_kernel(
    const float* __restrict__ x,
    const float* __restrict__ wq,
    const float* __restrict__ wk,
    const float* __restrict__ wv)
{
    __shared__ u64 xd[32][128];
    const int tid  = threadIdx.x;
    const int row0 = blockIdx.x * 32;

    const float* W   = (blockIdx.y == 0) ? wq : (blockIdx.y == 1) ? wk : wv;
    float*       out = (blockIdx.y == 0) ? g_q : (blockIdx.y == 1) ? g_k : g_v;

    const float4* x4 = (const float4*)(x + (size_t)row0 * DIM);
#pragma unroll
    for (int it = 0; it < 4; it++) {
        int i = tid + it * 256;
        float4 v = x4[i];
        int r = i >> 5, c = (i & 31) * 4;
        xd[r][c + 0] = pk2(v.x, v.x);
        xd[r][c + 1] = pk2(v.y, v.y);
        xd[r][c + 2] = pk2(v.z, v.z);
        xd[r][c + 3] = pk2(v.w, v.w);
    }
    __syncthreads();

    const int jh = tid & 63;
    const int rg = tid >> 6;

    const u64* Wp = (const u64*)W;

    u64 acc[8];
#pragma unroll
    for (int r = 0; r < 8; r++) acc[r] = 0ull;

#pragma unroll 4
    for (int d = 0; d < 128; d++) {
        u64 wp = Wp[d * 64 + jh];
#pragma unroll
        for (int r = 0; r < 8; r++)
            acc[r] = fma2_(xd[rg + r * 4][d], wp, acc[r]);
    }

    if (blockIdx.y == 1) {
        const float sc = 0.08838834764831845f * 1.4426950408889634f;
        const u64 sc2 = pk2(sc, sc);
#pragma unroll
        for (int r = 0; r < 8; r++) acc[r] = mul2_(acc[r], sc2);
    }

    u64* outp = (u64*)out;
#pragma unroll
    for (int r = 0; r < 8; r++)
        outp[(size_t)(row0 + rg + r * 4) * 64 + jh] = acc[r];
}

// ---------------------------------------------------------------------------
// Kernel 2a: transpose lin_w
// ---------------------------------------------------------------------------
__global__ __launch_bounds__(256) void prepW_kernel(const float* __restrict__ lin_w)
{
    for (int idx = blockIdx.x * 256 + threadIdx.x; idx < DIM * DIM;
         idx += gridDim.x * 256) {
        int j = idx >> 7, c = idx & 127;
        g_lwT[c * 128 + j] = lin_w[idx];
    }
}

// ---------------------------------------------------------------------------
// Kernel 2b: mask -> additive log2-space float; dtype auto-detect.
// ---------------------------------------------------------------------------
__global__ __launch_bounds__(256) void prepM_kernel(const int* __restrict__ mraw)
{
    __shared__ int is64;
    if (threadIdx.x == 0) {
        int acc = 0;
        for (int i = 0; i < 64; i++) acc |= mraw[2 * i + 1];
        is64 = (acc == 0);
    }
    __syncthreads();
    for (int idx = blockIdx.x * 256 + threadIdx.x; idx < ROWS;
         idx += gridDim.x * 256) {
        int v = is64 ? mraw[2 * idx] : mraw[idx];
        g_maskf[idx] = (v == 0) ? -1442.6950408889634f : 0.0f;
    }
}

// ---------------------------------------------------------------------------
// Kernel 3: flash attention; 2 queries/thread; one 256-key tile per CTA
// (KSPLIT=8). Group-of-8 deferred softmax: 8 score chains computed into regs
// (ILP), one group max + one rescale branch per 8 keys, then 8 independent
// exp+PV chains. grid (SEQ/256, 32, KSPLIT); block 128.
// ---------------------------------------------------------------------------
__global__ __launch_bounds__(128, 4) void attn_kernel()
{
    __shared__ ulonglong2 Ks[256 * 4];   // 16KB
    __shared__ ulonglong2 Vs[256 * 4];   // 16KB
    __shared__ float      ms[256];

    const int tid   = threadIdx.x;
    const int pair  = blockIdx.y;           // b*8 + h
    const int b     = pair >> 3;
    const int h     = pair & 7;
    const int rowA  = blockIdx.x * 256 + tid;
    const int rowB  = rowA + 128;
    const int kbase = blockIdx.z * 256;     // this CTA's key range

    const ulonglong2* qvA = (const ulonglong2*)(g_q + ((size_t)(b * SEQ + rowA) * DIM + h * HD));
    const ulonglong2* qvB = (const ulonglong2*)(g_q + ((size_t)(b * SEQ + rowB) * DIM + h * HD));
    ulonglong2 qA0 = qvA[0], qA1 = qvA[1], qA2 = qvA[2], qA3 = qvA[3];
    ulonglong2 qB0 = qvB[0], qB1 = qvB[1], qB2 = qvB[2], qB3 = qvB[3];

    // cooperative tile load
    {
        float4* Ksf = (float4*)Ks;
        float4* Vsf = (float4*)Vs;
#pragma unroll
        for (int it = 0; it < 8; it++) {
            int idx  = tid + it * 128;
            int key  = idx >> 2;
            int part = idx & 3;
            size_t base = (size_t)(b * SEQ + kbase + key) * DIM + h * HD;
            Ksf[idx] = ((const float4*)(g_k + base))[part];
            Vsf[idx] = ((const float4*)(g_v + base))[part];
        }
        ms[tid]       = g_maskf[b * SEQ + kbase + tid];
        ms[tid + 128] = g_maskf[b * SEQ + kbase + tid + 128];
        __syncthreads();
    }

    float mA = -1e30f, lA = 0.f, mB = -1e30f, lB = 0.f;
    u64 oA[8], oB[8];
#pragma unroll
    for (int d = 0; d < 8; d++) { oA[d] = 0; oB[d] = 0; }

    for (int g = 0; g < 256; g += 8) {
        float sAr[8], sBr[8];
        // ---- phase 1: 8 independent score chains ----
#pragma unroll
        for (int j = 0; j < 8; j++) {
            const int kk = g + j;
            const ulonglong2 ka = Ks[kk * 4 + 0];
            const ulonglong2 kb = Ks[kk * 4 + 1];
            const ulonglong2 kc = Ks[kk * 4 + 2];
            const ulonglong2 kd = Ks[kk * 4 + 3];

            u64 sa = mul2_(qA0.x, ka.x);
            u64 sb = mul2_(qB0.x, ka.x);
            sa = fma2_(qA0.y, ka.y, sa);  sb = fma2_(qB0.y, ka.y, sb);
            sa = fma2_(qA1.x, kb.x, sa);  sb = fma2_(qB1.x, kb.x, sb);
            sa = fma2_(qA1.y, kb.y, sa);  sb = fma2_(qB1.y, kb.y, sb);
            sa = fma2_(qA2.x, kc.x, sa);  sb = fma2_(qB2.x, kc.x, sb);
            sa = fma2_(qA2.y, kc.y, sa);  sb = fma2_(qB2.y, kc.y, sb);
            sa = fma2_(qA3.x, kd.x, sa);  sb = fma2_(qB3.x, kd.x, sb);
            sa = fma2_(qA3.y, kd.y, sa);  sb = fma2_(qB3.y, kd.y, sb);

            float mval = ms[kk];
            float alo, ahi, blo, bhi;
            upk2(alo, ahi, sa);
            upk2(blo, bhi, sb);
            sAr[j] = (alo + ahi) + mval;
            sBr[j] = (blo + bhi) + mval;
        }
        // ---- group max (tree) ----
        float gA01 = fmaxf(sAr[0], sAr[1]), gA23 = fmaxf(sAr[2], sAr[3]);
        float gA45 = fmaxf(sAr[4], sAr[5]), gA67 = fmaxf(sAr[6], sAr[7]);
        float gA = fmaxf(fmaxf(gA01, gA23), fmaxf(gA45, gA67));
        float gB01 = fmaxf(sBr[0], sBr[1]), gB23 = fmaxf(sBr[2], sBr[3]);
        float gB45 = fmaxf(sBr[4], sBr[5]), gB67 = fmaxf(sBr[6], sBr[7]);
        float gB = fmaxf(fmaxf(gB01, gB23), fmaxf(gB45, gB67));

        if ((gA > mA) | (gB > mB)) {          // ~13% of groups
            float mAn = fmaxf(mA, gA);
            float mBn = fmaxf(mB, gB);
            float cA = ex2f(mA - mAn);        // ==1 if no update for this query
            float cB = ex2f(mB - mBn);
            u64 cA2 = pk2(cA, cA);
            u64 cB2 = pk2(cB, cB);
            lA *= cA; lB *= cB;
#pragma unroll
            for (int d = 0; d < 8; d++) {
                oA[d] = mul2_(oA[d], cA2);
                oB[d] = mul2_(oB[d], cB2);
            }
            mA = mAn; mB = mBn;
        }
        // ---- phase 2: 8 independent exp + PV chains ----
#pragma unroll
        for (int j = 0; j < 8; j++) {
            const int kk = g + j;
            float pA = ex2f(sAr[j] - mA);
            float pB = ex2f(sBr[j] - mB);
            lA += pA;
            lB += pB;
            u64 ppA = pk2(pA, pA);
            u64 ppB = pk2(pB, pB);

            const ulonglong2 va = Vs[kk * 4 + 0];
            const ulonglong2 vb = Vs[kk * 4 + 1];
            const ulonglong2 vc = Vs[kk * 4 + 2];
            const ulonglong2 vd = Vs[kk * 4 + 3];
            oA[0] = fma2_(ppA, va.x, oA[0]);  oB[0] = fma2_(ppB, va.x, oB[0]);
            oA[1] = fma2_(ppA, va.y, oA[1]);  oB[1] = fma2_(ppB, va.y, oB[1]);
            oA[2] = fma2_(ppA, vb.x, oA[2]);  oB[2] = fma2_(ppB, vb.x, oB[2]);
            oA[3] = fma2_(ppA, vb.y, oA[3]);  oB[3] = fma2_(ppB, vb.y, oB[3]);
            oA[4] = fma2_(ppA, vc.x, oA[4]);  oB[4] = fma2_(ppB, vc.x, oB[4]);
            oA[5] = fma2_(ppA, vc.y, oA[5]);  oB[5] = fma2_(ppB, vc.y, oB[5]);
            oA[6] = fma2_(ppA, vd.x, oA[6]);  oB[6] = fma2_(ppB, vd.x, oB[6]);
            oA[7] = fma2_(ppA, vd.y, oA[7]);  oB[7] = fma2_(ppB, vd.y, oB[7]);
        }
    }

    const int qA_idx = pair * SEQ + rowA;
    const int qB_idx = pair * SEQ + rowB;
    const int z      = blockIdx.z;

    ulonglong2* poA = (ulonglong2*)(g_po + ((size_t)z * QH + qA_idx) * HD);
    ulonglong2* poB = (ulonglong2*)(g_po + ((size_t)z * QH + qB_idx) * HD);
#pragma unroll
    for (int k4 = 0; k4 < 4; k4++) {
        ulonglong2 r;
        r.x = oA[k4 * 2]; r.y = oA[k4 * 2 + 1];
        poA[k4] = r;
    }
#pragma unroll
    for (int k4 = 0; k4 < 4; k4++) {
        ulonglong2 r;
        r.x = oB[k4 * 2]; r.y = oB[k4 * 2 + 1];
        poB[k4] = r;
    }
    g_pm[(size_t)z * QH + qA_idx] = mA;
    g_pl[(size_t)z * QH + qA_idx] = lA;
    g_pm[(size_t)z * QH + qB_idx] = mB;
    g_pl[(size_t)z * QH + qB_idx] = lB;
}

// ---------------------------------------------------------------------------
// Kernel 3b: merge KSPLIT partials -> g_o (normalized)
// ---------------------------------------------------------------------------
__global__ __launch_bounds__(256) void merge_kernel()
{
    int qidx = blockIdx.x * 256 + threadIdx.x;
    if (qidx >= QH) return;
    const int pair = qidx >> 11;
    const int row  = qidx & 2047;
    const int b    = pair >> 3;
    const int h    = pair & 7;

    float m[KSPLIT], l[KSPLIT], c[KSPLIT];
    float mm = -1e30f;
#pragma unroll
    for (int z = 0; z < KSPLIT; z++) {
        m[z] = g_pm[(size_t)z * QH + qidx];
        l[z] = g_pl[(size_t)z * QH + qidx];
        mm = fmaxf(mm, m[z]);
    }
    float denom = 0.f;
#pragma unroll
    for (int z = 0; z < KSPLIT; z++) {
        c[z] = ex2f(m[z] - mm);
        denom += l[z] * c[z];
    }
    float inv = 1.0f / denom;
#pragma unroll
    for (int z = 0; z < KSPLIT; z++) c[z] *= inv;

    float4* out = (float4*)(g_o + ((size_t)(b * SEQ + row) * DIM + h * HD));
#pragma unroll
    for (int k4 = 0; k4 < 4; k4++) {
        float4 r = make_float4(0.f, 0.f, 0.f, 0.f);
#pragma unroll
        for (int z = 0; z < KSPLIT; z++) {
            const float4 a = ((const float4*)(g_po + ((size_t)z * QH + qidx) * HD))[k4];
            r.x = fmaf(a.x, c[z], r.x);
            r.y = fmaf(a.y, c[z], r.y);
            r.z = fmaf(a.z, c[z], r.z);
            r.w = fmaf(a.w, c[z], r.w);
        }
        out[k4] = r;
    }
}

// ---------------------------------------------------------------------------
// Kernel 4: head-reordered gather + output projection (dup-packed smem).
// ---------------------------------------------------------------------------
__global__ __launch_bounds__(256) void proj_kernel(
    const float* __restrict__ lin_b,
    float* __restrict__ y)
{
    __shared__ u64 xd[32][128];
    const int tid  = threadIdx.x;
    const int row0 = blockIdx.x * 32;

#pragma unroll
    for (int it = 0; it < 16; it++) {
        int i = tid + it * 256;
        int r = i >> 7, c = i & 127;
        int src = c_head_order[c >> 4] * HD + (c & 15);
        float v = g_o[(size_t)(row0 + r) * DIM + src];
        xd[r][c] = pk2(v, v);
    }
    __syncthreads();

    const int jh = tid & 63;
    const int rg = tid >> 6;

    float2 b2 = *(const float2*)&lin_b[jh * 2];
    const u64 bias = pk2(b2.x, b2.y);
    u64 acc[8];
#pragma unroll
    for (int r = 0; r < 8; r++) acc[r] = bias;

    const u64* Wp = (const u64*)g_lwT;
#pragma unroll 4
    for (int d = 0; d < 128; d++) {
        u64 wp = Wp[d * 64 + jh];
#pragma unroll
        for (int r = 0; r < 8; r++)
            acc[r] = fma2_(xd[rg + r * 4][d], wp, acc[r]);
    }
    u64* yp = (u64*)y;
#pragma unroll
    for (int r = 0; r < 8; r++)
        yp[(size_t)(row0 + rg + r * 4) * 64 + jh] = acc[r];
}

// ---------------------------------------------------------------------------
extern "C" void kernel_launch(void* const* d_in, const int* in_sizes, int n_in,
                              void* d_out, int out_size)
{
    const float* x    = (const float*)d_in[0];
    const int*   mraw = (const int*)  d_in[1];
    const float* wq   = (const float*)d_in[2];
    const float* wk   = (const float*)d_in[3];
    const float* wv   = (const float*)d_in[4];
    const float* lw   = (const float*)d_in[5];
    const float* lb   = (const float*)d_in[6];
    float*       y    = (float*)d_out;

    qkv_kernel<<<dim3(ROWS / 32, 3), 256>>>(x, wq, wk, wv);
    prepW_kernel<<<64, 256>>>(lw);
    prepM_kernel<<<32, 256>>>(mraw);
    attn_kernel<<<dim3(SEQ / 256, 32, KSPLIT), 128>>>();
    merge_kernel<<<QH / 256, 256>>>();
    proj_kernel<<<ROWS / 32, 256>>>(lb, y);
}

// round 7
// speedup vs baseline: 2.1886x; 1.3727x over previous
#include <cuda_runtime.h>
#include <cstdint>

// Problem constants
constexpr int BATCH = 4;
constexpr int SEQ   = 2048;
constexpr int DIM   = 128;
constexpr int HD    = 16;
constexpr int ROWS  = BATCH * SEQ;        // 8192
constexpr int QH    = BATCH * 8 * SEQ;    // 65536 query-head rows
constexpr int KSPLIT = 4;
constexpr int BK    = 32;                 // keys staged per block
constexpr int QTILE = 64;                 // queries per CTA (4 warps x 16)

// Scratch (device globals — no allocation allowed)
__device__ float g_q[ROWS * DIM];
__device__ float g_k[ROWS * DIM];     // pre-scaled by (1/sqrt(128))*log2(e)
__device__ float g_v[ROWS * DIM];
__device__ float g_o[ROWS * DIM];     // merge writes this HEAD-REORDERED
__device__ float g_lwT[DIM * DIM];
__device__ float g_maskf[ROWS];
__device__ float g_po[(size_t)KSPLIT * QH * HD];
__device__ float g_pm[(size_t)KSPLIT * QH];
__device__ float g_pl[(size_t)KSPLIT * QH];

__constant__ int c_head_order[8] = {0, 1, 1, 2, 3, 4, 5, 6};

// ---------------------------------------------------------------------------
// Helpers
// ---------------------------------------------------------------------------
typedef unsigned long long u64;

__device__ __forceinline__ u64 pk2(float lo, float hi) {
    u64 r; asm("mov.b64 %0,{%1,%2};" : "=l"(r) : "f"(lo), "f"(hi)); return r;
}
__device__ __forceinline__ void upk2(float& lo, float& hi, u64 v) {
    asm("mov.b64 {%0,%1},%2;" : "=f"(lo), "=f"(hi) : "l"(v));
}
__device__ __forceinline__ u64 fma2_(u64 a, u64 b, u64 c) {
    u64 d; asm("fma.rn.f32x2 %0,%1,%2,%3;" : "=l"(d) : "l"(a), "l"(b), "l"(c)); return d;
}
__device__ __forceinline__ u64 mul2_(u64 a, u64 b) {
    u64 d; asm("mul.rn.f32x2 %0,%1,%2;" : "=l"(d) : "l"(a), "l"(b)); return d;
}
__device__ __forceinline__ float ex2f(float x) {
    float y; asm("ex2.approx.ftz.f32 %0,%1;" : "=f"(y) : "f"(x)); return y;
}
__device__ __forceinline__ uint32_t cvt_tf32(float x) {
    uint32_t r; asm("cvt.rna.tf32.f32 %0,%1;" : "=r"(r) : "f"(x)); return r;
}
// D += A * B  (m16n8k8 tf32, f32 accumulate) — baseline PTX, no sm_103a needed
__device__ __forceinline__ void mma_tf32(float* d, const uint32_t* a,
                                         uint32_t b0, uint32_t b1) {
    asm volatile(
        "mma.sync.aligned.m16n8k8.row.col.f32.tf32.tf32.f32 "
        "{%0,%1,%2,%3},{%4,%5,%6,%7},{%8,%9},{%0,%1,%2,%3};"
        : "+f"(d[0]), "+f"(d[1]), "+f"(d[2]), "+f"(d[3])
        : "r"(a[0]), "r"(a[1]), "r"(a[2]), "r"(a[3]), "r"(b0), "r"(b1));
}

// ---------------------------------------------------------------------------
// Kernel 1: fused QKV projection (FFMA2 dup-packed). K pre-scaled.
// ---------------------------------------------------------------------------
__global__ __launch_bounds__(256) void qkv_kernel(
    const float* __restrict__ x,
    const float* __restrict__ wq,
    const float* __restrict__ wk,
    const float* __restrict__ wv)
{
    __shared__ u64 xd[32][128];
    const int tid  = threadIdx.x;
    const int row0 = blockIdx.x * 32;

    const float* W   = (blockIdx.y == 0) ? wq : (blockIdx.y == 1) ? wk : wv;
    float*       out = (blockIdx.y == 0) ? g_q : (blockIdx.y == 1) ? g_k : g_v;

    const float4* x4 = (const float4*)(x + (size_t)row0 * DIM);
#pragma unroll
    for (int it = 0; it < 4; it++) {
        int i = tid + it * 256;
        float4 v = x4[i];
        int r = i >> 5, c = (i & 31) * 4;
        xd[r][c + 0] = pk2(v.x, v.x);
        xd[r][c + 1] = pk2(v.y, v.y);
        xd[r][c + 2] = pk2(v.z, v.z);
        xd[r][c + 3] = pk2(v.w, v.w);
    }
    __syncthreads();

    const int jh = tid & 63;
    const int rg = tid >> 6;
    const u64* Wp = (const u64*)W;

    u64 acc[8];
#pragma unroll
    for (int r = 0; r < 8; r++) acc[r] = 0ull;

#pragma unroll 4
    for (int d = 0; d < 128; d++) {
        u64 wp = Wp[d * 64 + jh];
#pragma unroll
        for (int r = 0; r < 8; r++)
            acc[r] = fma2_(xd[rg + r * 4][d], wp, acc[r]);
    }

    if (blockIdx.y == 1) {
        const float sc = 0.08838834764831845f * 1.4426950408889634f;
        const u64 sc2 = pk2(sc, sc);
#pragma unroll
        for (int r = 0; r < 8; r++) acc[r] = mul2_(acc[r], sc2);
    }

    u64* outp = (u64*)out;
#pragma unroll
    for (int r = 0; r < 8; r++)
        outp[(size_t)(row0 + rg + r * 4) * 64 + jh] = acc[r];
}

// ---------------------------------------------------------------------------
// Kernel 2a/2b: prep
// ---------------------------------------------------------------------------
__global__ __launch_bounds__(256) void prepW_kernel(const float* __restrict__ lin_w)
{
    for (int idx = blockIdx.x * 256 + threadIdx.x; idx < DIM * DIM;
         idx += gridDim.x * 256) {
        int j = idx >> 7, c = idx & 127;
        g_lwT[c * 128 + j] = lin_w[idx];
    }
}

__global__ __launch_bounds__(256) void prepM_kernel(const int* __restrict__ mraw)
{
    __shared__ int is64;
    if (threadIdx.x == 0) {
        int acc = 0;
        for (int i = 0; i < 64; i++) acc |= mraw[2 * i + 1];
        is64 = (acc == 0);
    }
    __syncthreads();
    for (int idx = blockIdx.x * 256 + threadIdx.x; idx < ROWS;
         idx += gridDim.x * 256) {
        int v = is64 ? mraw[2 * idx] : mraw[idx];
        g_maskf[idx] = (v == 0) ? -1442.6950408889634f : 0.0f;
    }
}

// ---------------------------------------------------------------------------
// Kernel 3: flash attention on legacy tensor cores (mma.sync tf32).
// Block 128 (4 warps); warp owns 16 query rows. Keys swept in 32-key blocks:
//   QK^T: 8x mma m16n8k8 (2 hd-chunks x 4 key-tiles) -> S frags (f32)
//   softmax on fragments: quad-shfl row max, base-2 exp (K pre-scaled)
//   P rearranged acc->A layout via 8 shfl + selects per tile
//   P@V: 8x mma -> O accumulators (f32)
// grid (SEQ/QTILE, 32 bh-pairs, KSPLIT).
// Fragment layouts (PTX doc, m16n8k8 tf32):  g = lane>>2, q = lane&3
//   A: a0=[g][q] a1=[g+8][q] a2=[g][q+4] a3=[g+8][q+4]
//   B: b0=[k=q][n=g] b1=[k=q+4][n=g]
//   C: c0=[g][2q] c1=[g][2q+1] c2=[g+8][2q] c3=[g+8][2q+1]
// ---------------------------------------------------------------------------
__global__ __launch_bounds__(128, 6) void attn_kernel()
{
    __shared__ uint32_t Ksm[16][40];                 // [dim][key], tf32 bits
    __shared__ __align__(16) uint32_t Vsm[BK][40];   // [key][dim], tf32 bits
    __shared__ float ms[BK];

    const int tid  = threadIdx.x;
    const int w    = tid >> 5;
    const int lane = tid & 31;
    const int g    = lane >> 2;
    const int q4   = lane & 3;
    const int pair = blockIdx.y;      // b*8 + h
    const int b    = pair >> 3;
    const int h    = pair & 7;
    const int q0   = blockIdx.x * QTILE + w * 16;
    const int kstart = blockIdx.z * (SEQ / KSPLIT);

    const int row_lo = q0 + g;
    const int row_hi = row_lo + 8;

    // Q fragments (persistent, tf32)
    uint32_t aQ[2][4];
    {
        const float* qb = g_q + (size_t)b * SEQ * DIM + h * HD;
#pragma unroll
        for (int c = 0; c < 2; c++) {
            aQ[c][0] = cvt_tf32(qb[(size_t)row_lo * DIM + c * 8 + q4]);
            aQ[c][1] = cvt_tf32(qb[(size_t)row_hi * DIM + c * 8 + q4]);
            aQ[c][2] = cvt_tf32(qb[(size_t)row_lo * DIM + c * 8 + q4 + 4]);
            aQ[c][3] = cvt_tf32(qb[(size_t)row_hi * DIM + c * 8 + q4 + 4]);
        }
    }

    float m_lo = -1e30f, m_hi = -1e30f, l_lo = 0.f, l_hi = 0.f;
    float o[2][4];
#pragma unroll
    for (int nt = 0; nt < 2; nt++)
#pragma unroll
        for (int i = 0; i < 4; i++) o[nt][i] = 0.f;

    const int skey = tid >> 2;          // staging: key 0..31
    const int sd0  = (tid & 3) * 4;     // staging: dim group

    for (int kb = kstart; kb < kstart + SEQ / KSPLIT; kb += BK) {
        __syncthreads();   // previous block's consumers done
        // ---- stage K (transposed), V, mask ----
        {
            size_t base = (size_t)(b * SEQ + kb + skey) * DIM + h * HD + sd0;
            float4 kv = *(const float4*)(g_k + base);
            Ksm[sd0 + 0][skey] = cvt_tf32(kv.x);
            Ksm[sd0 + 1][skey] = cvt_tf32(kv.y);
            Ksm[sd0 + 2][skey] = cvt_tf32(kv.z);
            Ksm[sd0 + 3][skey] = cvt_tf32(kv.w);
            float4 vv = *(const float4*)(g_v + base);
            uint4 vu;
            vu.x = cvt_tf32(vv.x); vu.y = cvt_tf32(vv.y);
            vu.z = cvt_tf32(vv.z); vu.w = cvt_tf32(vv.w);
            *(uint4*)&Vsm[skey][sd0] = vu;
            if (tid < BK) ms[tid] = g_maskf[b * SEQ + kb + tid];
        }
        __syncthreads();

        // ---- QK^T: 4 key-tiles x 2 hd-chunks ----
        float s[4][4];
#pragma unroll
        for (int t = 0; t < 4; t++) {
            s[t][0] = s[t][1] = s[t][2] = s[t][3] = 0.f;
#pragma unroll
            for (int c = 0; c < 2; c++) {
                uint32_t b0 = Ksm[c * 8 + q4][t * 8 + g];
                uint32_t b1 = Ksm[c * 8 + q4 + 4][t * 8 + g];
                mma_tf32(s[t], aQ[c], b0, b1);
            }
            float2 mk = *(const float2*)&ms[t * 8 + 2 * q4];
            s[t][0] += mk.x; s[t][1] += mk.y;
            s[t][2] += mk.x; s[t][3] += mk.y;
        }

        // ---- block row max (in-thread tree + quad shfl) ----
        float bm_lo = fmaxf(fmaxf(fmaxf(s[0][0], s[0][1]), fmaxf(s[1][0], s[1][1])),
                            fmaxf(fmaxf(s[2][0], s[2][1]), fmaxf(s[3][0], s[3][1])));
        float bm_hi = fmaxf(fmaxf(fmaxf(s[0][2], s[0][3]), fmaxf(s[1][2], s[1][3])),
                            fmaxf(fmaxf(s[2][2], s[2][3]), fmaxf(s[3][2], s[3][3])));
        bm_lo = fmaxf(bm_lo, __shfl_xor_sync(0xffffffffu, bm_lo, 1));
        bm_lo = fmaxf(bm_lo, __shfl_xor_sync(0xffffffffu, bm_lo, 2));
        bm_hi = fmaxf(bm_hi, __shfl_xor_sync(0xffffffffu, bm_hi, 1));
        bm_hi = fmaxf(bm_hi, __shfl_xor_sync(0xffffffffu, bm_hi, 2));

        if ((bm_lo > m_lo) | (bm_hi > m_hi)) {
            float mn_lo = fmaxf(m_lo, bm_lo);
            float mn_hi = fmaxf(m_hi, bm_hi);
            float c_lo = ex2f(m_lo - mn_lo);   // 1 if no update; 0 on first block
            float c_hi = ex2f(m_hi - mn_hi);
            l_lo *= c_lo; l_hi *= c_hi;
#pragma unroll
            for (int nt = 0; nt < 2; nt++) {
                o[nt][0] *= c_lo; o[nt][1] *= c_lo;
                o[nt][2] *= c_hi; o[nt][3] *= c_hi;
            }
            m_lo = mn_lo; m_hi = mn_hi;
        }

        // ---- exp, l, P rearrange, P@V ----
        const int s0l = (lane & ~3) | (q4 >> 1);   // 4g + q/2
        const int s1l = s0l + 2;
        const bool odd = (q4 & 1);
#pragma unroll
        for (int t = 0; t < 4; t++) {
            float p0 = ex2f(s[t][0] - m_lo);
            float p1 = ex2f(s[t][1] - m_lo);
            float p2 = ex2f(s[t][2] - m_hi);
            float p3 = ex2f(s[t][3] - m_hi);
            l_lo += p0 + p1;
            l_hi += p2 + p3;

            float t0 = __shfl_sync(0xffffffffu, p0, s0l);
            float t1 = __shfl_sync(0xffffffffu, p1, s0l);
            float t2 = __shfl_sync(0xffffffffu, p0, s1l);
            float t3 = __shfl_sync(0xffffffffu, p1, s1l);
            float t4 = __shfl_sync(0xffffffffu, p2, s0l);
            float t5 = __shfl_sync(0xffffffffu, p3, s0l);
            float t6 = __shfl_sync(0xffffffffu, p2, s1l);
            float t7 = __shfl_sync(0xffffffffu, p3, s1l);

            uint32_t aP[4];
            aP[0] = cvt_tf32(odd ? t1 : t0);   // P[g][q]
            aP[1] = cvt_tf32(odd ? t5 : t4);   // P[g+8][q]
            aP[2] = cvt_tf32(odd ? t3 : t2);   // P[g][q+4]
            aP[3] = cvt_tf32(odd ? t7 : t6);   // P[g+8][q+4]

#pragma unroll
            for (int nt = 0; nt < 2; nt++) {
                uint32_t vb0 = Vsm[t * 8 + q4][nt * 8 + g];
                uint32_t vb1 = Vsm[t * 8 + q4 + 4][nt * 8 + g];
                mma_tf32(o[nt], aP, vb0, vb1);
            }
        }
    }

    // ---- finalize: quad-reduce l, write partials ----
    l_lo += __shfl_xor_sync(0xffffffffu, l_lo, 1);
    l_lo += __shfl_xor_sync(0xffffffffu, l_lo, 2);
    l_hi += __shfl_xor_sync(0xffffffffu, l_hi, 1);
    l_hi += __shfl_xor_sync(0xffffffffu, l_hi, 2);

    const int z = blockIdx.z;
    const size_t qlo = (size_t)pair * SEQ + row_lo;
    const size_t qhi = (size_t)pair * SEQ + row_hi;
    float* plo = g_po + ((size_t)z * QH + qlo) * HD;
    float* phi = g_po + ((size_t)z * QH + qhi) * HD;
    *(float2*)&plo[2 * q4]     = make_float2(o[0][0], o[0][1]);
    *(float2*)&plo[8 + 2 * q4] = make_float2(o[1][0], o[1][1]);
    *(float2*)&phi[2 * q4]     = make_float2(o[0][2], o[0][3]);
    *(float2*)&phi[8 + 2 * q4] = make_float2(o[1][2], o[1][3]);
    if (q4 == 0) {
        g_pm[(size_t)z * QH + qlo] = m_lo;
        g_pl[(size_t)z * QH + qlo] = l_lo;
        g_pm[(size_t)z * QH + qhi] = m_hi;
        g_pl[(size_t)z * QH + qhi] = l_hi;
    }
}

// ---------------------------------------------------------------------------
// Kernel 3b: merge KSPLIT partials -> g_o, written HEAD-REORDERED.
// ---------------------------------------------------------------------------
__global__ __launch_bounds__(256) void merge_kernel()
{
    int qidx = blockIdx.x * 256 + threadIdx.x;
    if (qidx >= QH) return;
    const int pair = qidx >> 11;
    const int row  = qidx & 2047;
    const int b    = pair >> 3;
    const int h    = pair & 7;

    float m[KSPLIT], l[KSPLIT], c[KSPLIT];
    float mm = -1e30f;
#pragma unroll
    for (int z = 0; z < KSPLIT; z++) {
        m[z] = g_pm[(size_t)z * QH + qidx];
        l[z] = g_pl[(size_t)z * QH + qidx];
        mm = fmaxf(mm, m[z]);
    }
    float denom = 0.f;
#pragma unroll
    for (int z = 0; z < KSPLIT; z++) {
        c[z] = ex2f(m[z] - mm);
        denom += l[z] * c[z];
    }
    float inv = 1.0f / denom;
#pragma unroll
    for (int z = 0; z < KSPLIT; z++) c[z] *= inv;

    float4 out[4];
#pragma unroll
    for (int k4 = 0; k4 < 4; k4++) {
        float4 r = make_float4(0.f, 0.f, 0.f, 0.f);
#pragma unroll
        for (int z = 0; z < KSPLIT; z++) {
            const float4 a = ((const float4*)(g_po + ((size_t)z * QH + qidx) * HD))[k4];
            r.x = fmaf(a.x, c[z], r.x);
            r.y = fmaf(a.y, c[z], r.y);
            r.z = fmaf(a.z, c[z], r.z);
            r.w = fmaf(a.w, c[z], r.w);
        }
        out[k4] = r;
    }

#pragma unroll
    for (int slot = 0; slot < 8; slot++) {
        if (c_head_order[slot] == h) {
            float4* dst = (float4*)(g_o + ((size_t)(b * SEQ + row) * DIM + slot * HD));
            dst[0] = out[0]; dst[1] = out[1]; dst[2] = out[2]; dst[3] = out[3];
        }
    }
}

// ---------------------------------------------------------------------------
// Kernel 4: output projection (g_o already head-reordered), 8-deep W-load ILP.
// ---------------------------------------------------------------------------
__global__ __launch_bounds__(256) void proj_kernel(
    const float* __restrict__ lin_b,
    float* __restrict__ y)
{
    __shared__ u64 xd[32][128];
    const int tid  = threadIdx.x;
    const int row0 = blockIdx.x * 32;

    const float4* g4 = (const float4*)(g_o + (size_t)row0 * DIM);
#pragma unroll
    for (int it = 0; it < 4; it++) {
        int i = tid + it * 256;
        float4 v = g4[i];
        int r = i >> 5, c = (i & 31) * 4;
        xd[r][c + 0] = pk2(v.x, v.x);
        xd[r][c + 1] = pk2(v.y, v.y);
        xd[r][c + 2] = pk2(v.z, v.z);
        xd[r][c + 3] = pk2(v.w, v.w);
    }
    __syncthreads();

    const int jh = tid & 63;
    const int rg = tid >> 6;

    float2 b2 = *(const float2*)&lin_b[jh * 2];
    const u64 bias = pk2(b2.x, b2.y);
    u64 acc[8];
#pragma unroll
    for (int r = 0; r < 8; r++) acc[r] = bias;

    const u64* Wp = (const u64*)g_lwT;
#pragma unroll
    for (int d0 = 0; d0 < 128; d0 += 8) {
        u64 w[8];
#pragma unroll
        for (int i = 0; i < 8; i++) w[i] = Wp[(d0 + i) * 64 + jh];
#pragma unroll
        for (int i = 0; i < 8; i++) {
#pragma unroll
            for (int r = 0; r < 8; r++)
                acc[r] = fma2_(xd[rg + r * 4][d0 + i], w[i], acc[r]);
        }
    }
    u64* yp = (u64*)y;
#pragma unroll
    for (int r = 0; r < 8; r++)
        yp[(size_t)(row0 + rg + r * 4) * 64 + jh] = acc[r];
}

// ---------------------------------------------------------------------------
extern "C" void kernel_launch(void* const* d_in, const int* in_sizes, int n_in,
                              void* d_out, int out_size)
{
    const float* x    = (const float*)d_in[0];
    const int*   mraw = (const int*)  d_in[1];
    const float* wq   = (const float*)d_in[2];
    const float* wk   = (const float*)d_in[3];
    const float* wv   = (const float*)d_in[4];
    const float* lw   = (const float*)d_in[5];
    const float* lb   = (const float*)d_in[6];
    float*       y    = (float*)d_out;

    qkv_kernel<<<dim3(ROWS / 32, 3), 256>>>(x, wq, wk, wv);
    prepW_kernel<<<64, 256>>>(lw);
    prepM_kernel<<<32, 256>>>(mraw);
    attn_kernel<<<dim3(SEQ / QTILE, 32, KSPLIT), 128>>>();
    merge_kernel<<<QH / 256, 256>>>();
    proj_kernel<<<ROWS / 32, 256>>>(lb, y);
}

// round 8
// speedup vs baseline: 2.6083x; 1.1917x over previous
#include <cuda_runtime.h>
#include <cuda_fp16.h>
#include <cstdint>

// Problem constants
constexpr int BATCH = 4;
constexpr int SEQ   = 2048;
constexpr int DIM   = 128;
constexpr int HD    = 16;
constexpr int ROWS  = BATCH * SEQ;        // 8192
constexpr int QH    = BATCH * 8 * SEQ;    // 65536 query-head rows
constexpr int KSPLIT = 4;
constexpr int BK    = 32;                 // keys staged per block
constexpr int QTILE = 64;                 // queries per CTA (4 warps x 16)

// Scratch (device globals — no allocation allowed)
__device__ float g_q[ROWS * DIM];
__device__ float g_k[ROWS * DIM];     // pre-scaled by (1/sqrt(128))*log2(e)
__device__ float g_v[ROWS * DIM];
__device__ float g_o[ROWS * DIM];     // merge writes this HEAD-REORDERED
__device__ float g_lwT[DIM * DIM];
__device__ float g_maskf[ROWS];
__device__ float g_po[(size_t)KSPLIT * QH * HD];
__device__ float g_pm[(size_t)KSPLIT * QH];
__device__ float g_pl[(size_t)KSPLIT * QH];

__constant__ int c_head_order[8] = {0, 1, 1, 2, 3, 4, 5, 6};

// ---------------------------------------------------------------------------
// Helpers
// ---------------------------------------------------------------------------
typedef unsigned long long u64;

__device__ __forceinline__ u64 pk2(float lo, float hi) {
    u64 r; asm("mov.b64 %0,{%1,%2};" : "=l"(r) : "f"(lo), "f"(hi)); return r;
}
__device__ __forceinline__ u64 fma2_(u64 a, u64 b, u64 c) {
    u64 d; asm("fma.rn.f32x2 %0,%1,%2,%3;" : "=l"(d) : "l"(a), "l"(b), "l"(c)); return d;
}
__device__ __forceinline__ u64 mul2_(u64 a, u64 b) {
    u64 d; asm("mul.rn.f32x2 %0,%1,%2;" : "=l"(d) : "l"(a), "l"(b)); return d;
}
__device__ __forceinline__ float ex2f(float x) {
    float y; asm("ex2.approx.ftz.f32 %0,%1;" : "=f"(y) : "f"(x)); return y;
}
__device__ __forceinline__ uint32_t cvt_tf32(float x) {
    uint32_t r; asm("cvt.rna.tf32.f32 %0,%1;" : "=r"(r) : "f"(x)); return r;
}
__device__ __forceinline__ uint32_t h2pack(float lo, float hi) {
    uint32_t r;
    asm("cvt.rn.f16x2.f32 %0, %1, %2;" : "=r"(r) : "f"(hi), "f"(lo));  // %1=hi, %2=lo
    return r;
}
// D += A * B  (m16n8k8 tf32, f32 accumulate)
__device__ __forceinline__ void mma_tf32(float* d, const uint32_t* a,
                                         uint32_t b0, uint32_t b1) {
    asm volatile(
        "mma.sync.aligned.m16n8k8.row.col.f32.tf32.tf32.f32 "
        "{%0,%1,%2,%3},{%4,%5,%6,%7},{%8,%9},{%0,%1,%2,%3};"
        : "+f"(d[0]), "+f"(d[1]), "+f"(d[2]), "+f"(d[3])
        : "r"(a[0]), "r"(a[1]), "r"(a[2]), "r"(a[3]), "r"(b0), "r"(b1));
}
// D += A * B  (m16n8k16 f16, f32 accumulate)
__device__ __forceinline__ void mma_f16(float* d, const uint32_t* a,
                                        uint32_t b0, uint32_t b1) {
    asm volatile(
        "mma.sync.aligned.m16n8k16.row.col.f32.f16.f16.f32 "
        "{%0,%1,%2,%3},{%4,%5,%6,%7},{%8,%9},{%0,%1,%2,%3};"
        : "+f"(d[0]), "+f"(d[1]), "+f"(d[2]), "+f"(d[3])
        : "r"(a[0]), "r"(a[1]), "r"(a[2]), "r"(a[3]), "r"(b0), "r"(b1));
}

// ---------------------------------------------------------------------------
// Kernel 1: fused QKV projection (FFMA2 dup-packed). K pre-scaled.
// ---------------------------------------------------------------------------
__global__ __launch_bounds__(256) void qkv_kernel(
    const float* __restrict__ x,
    const float* __restrict__ wq,
    const float* __restrict__ wk,
    const float* __restrict__ wv)
{
    __shared__ u64 xd[32][128];
    const int tid  = threadIdx.x;
    const int row0 = blockIdx.x * 32;

    const float* W   = (blockIdx.y == 0) ? wq : (blockIdx.y == 1) ? wk : wv;
    float*       out = (blockIdx.y == 0) ? g_q : (blockIdx.y == 1) ? g_k : g_v;

    const float4* x4 = (const float4*)(x + (size_t)row0 * DIM);
#pragma unroll
    for (int it = 0; it < 4; it++) {
        int i = tid + it * 256;
        float4 v = x4[i];
        int r = i >> 5, c = (i & 31) * 4;
        xd[r][c + 0] = pk2(v.x, v.x);
        xd[r][c + 1] = pk2(v.y, v.y);
        xd[r][c + 2] = pk2(v.z, v.z);
        xd[r][c + 3] = pk2(v.w, v.w);
    }
    __syncthreads();

    const int jh = tid & 63;
    const int rg = tid >> 6;
    const u64* Wp = (const u64*)W;

    u64 acc[8];
#pragma unroll
    for (int r = 0; r < 8; r++) acc[r] = 0ull;

#pragma unroll 4
    for (int d = 0; d < 128; d++) {
        u64 wp = Wp[d * 64 + jh];
#pragma unroll
        for (int r = 0; r < 8; r++)
            acc[r] = fma2_(xd[rg + r * 4][d], wp, acc[r]);
    }

    if (blockIdx.y == 1) {
        const float sc = 0.08838834764831845f * 1.4426950408889634f;
        const u64 sc2 = pk2(sc, sc);
#pragma unroll
        for (int r = 0; r < 8; r++) acc[r] = mul2_(acc[r], sc2);
    }

    u64* outp = (u64*)out;
#pragma unroll
    for (int r = 0; r < 8; r++)
        outp[(size_t)(row0 + rg + r * 4) * 64 + jh] = acc[r];
}

// ---------------------------------------------------------------------------
// Kernel 2a/2b: prep
// ---------------------------------------------------------------------------
__global__ __launch_bounds__(256) void prepW_kernel(const float* __restrict__ lin_w)
{
    for (int idx = blockIdx.x * 256 + threadIdx.x; idx < DIM * DIM;
         idx += gridDim.x * 256) {
        int j = idx >> 7, c = idx & 127;
        g_lwT[c * 128 + j] = lin_w[idx];
    }
}

__global__ __launch_bounds__(256) void prepM_kernel(const int* __restrict__ mraw)
{
    __shared__ int is64;
    if (threadIdx.x == 0) {
        int acc = 0;
        for (int i = 0; i < 64; i++) acc |= mraw[2 * i + 1];
        is64 = (acc == 0);
    }
    __syncthreads();
    for (int idx = blockIdx.x * 256 + threadIdx.x; idx < ROWS;
         idx += gridDim.x * 256) {
        int v = is64 ? mraw[2 * idx] : mraw[idx];
        g_maskf[idx] = (v == 0) ? -1442.6950408889634f : 0.0f;
    }
}

// ---------------------------------------------------------------------------
// Kernel 3: flash attention on mma.sync. QK^T in tf32; P@V in f16 with the
// C-frag == A-frag layout identity (no shuffles):
//   m16n8k16.f16 A-frag a0=[g][2q,2q+1] (half2)  ==  packed m16n8k8 C-frag.
// V staged transposed f16 [dim][key], stride 40 halves (conflict-free b-frags).
// ---------------------------------------------------------------------------
__global__ __launch_bounds__(128, 6) void attn_kernel()
{
    __shared__ uint32_t Ksm[16][40];      // [dim][key], tf32 bits
    __shared__ __half   VsmT[16][40];     // [dim][key], f16 (stride 40 halves)
    __shared__ float    ms[BK];

    const int tid  = threadIdx.x;
    const int w    = tid >> 5;
    const int lane = tid & 31;
    const int g    = lane >> 2;
    const int q4   = lane & 3;
    const int pair = blockIdx.y;      // b*8 + h
    const int b    = pair >> 3;
    const int h    = pair & 7;
    const int q0   = blockIdx.x * QTILE + w * 16;
    const int kstart = blockIdx.z * (SEQ / KSPLIT);

    const int row_lo = q0 + g;
    const int row_hi = row_lo + 8;

    // Q fragments (persistent, tf32)
    uint32_t aQ[2][4];
    {
        const float* qb = g_q + (size_t)b * SEQ * DIM + h * HD;
#pragma unroll
        for (int c = 0; c < 2; c++) {
            aQ[c][0] = cvt_tf32(qb[(size_t)row_lo * DIM + c * 8 + q4]);
            aQ[c][1] = cvt_tf32(qb[(size_t)row_hi * DIM + c * 8 + q4]);
            aQ[c][2] = cvt_tf32(qb[(size_t)row_lo * DIM + c * 8 + q4 + 4]);
            aQ[c][3] = cvt_tf32(qb[(size_t)row_hi * DIM + c * 8 + q4 + 4]);
        }
    }

    float m_lo = -1e30f, m_hi = -1e30f, l_lo = 0.f, l_hi = 0.f;
    float o[2][4];
#pragma unroll
    for (int nt = 0; nt < 2; nt++)
#pragma unroll
        for (int i = 0; i < 4; i++) o[nt][i] = 0.f;

    const int skey = tid >> 2;          // staging: key 0..31
    const int sd0  = (tid & 3) * 4;     // staging: dim group

    for (int kb = kstart; kb < kstart + SEQ / KSPLIT; kb += BK) {
        __syncthreads();
        // ---- stage K^T (tf32), V^T (f16), mask ----
        {
            size_t base = (size_t)(b * SEQ + kb + skey) * DIM + h * HD + sd0;
            float4 kv = *(const float4*)(g_k + base);
            Ksm[sd0 + 0][skey] = cvt_tf32(kv.x);
            Ksm[sd0 + 1][skey] = cvt_tf32(kv.y);
            Ksm[sd0 + 2][skey] = cvt_tf32(kv.z);
            Ksm[sd0 + 3][skey] = cvt_tf32(kv.w);
            float4 vv = *(const float4*)(g_v + base);
            VsmT[sd0 + 0][skey] = __float2half_rn(vv.x);
            VsmT[sd0 + 1][skey] = __float2half_rn(vv.y);
            VsmT[sd0 + 2][skey] = __float2half_rn(vv.z);
            VsmT[sd0 + 3][skey] = __float2half_rn(vv.w);
            if (tid < BK) ms[tid] = g_maskf[b * SEQ + kb + tid];
        }
        __syncthreads();

        // ---- QK^T: 4 key-tiles x 2 hd-chunks (tf32) ----
        float s[4][4];
#pragma unroll
        for (int t = 0; t < 4; t++) {
            s[t][0] = s[t][1] = s[t][2] = s[t][3] = 0.f;
#pragma unroll
            for (int c = 0; c < 2; c++) {
                uint32_t b0 = Ksm[c * 8 + q4][t * 8 + g];
                uint32_t b1 = Ksm[c * 8 + q4 + 4][t * 8 + g];
                mma_tf32(s[t], aQ[c], b0, b1);
            }
            float2 mk = *(const float2*)&ms[t * 8 + 2 * q4];
            s[t][0] += mk.x; s[t][1] += mk.y;
            s[t][2] += mk.x; s[t][3] += mk.y;
        }

        // ---- block row max ----
        float bm_lo = fmaxf(fmaxf(fmaxf(s[0][0], s[0][1]), fmaxf(s[1][0], s[1][1])),
                            fmaxf(fmaxf(s[2][0], s[2][1]), fmaxf(s[3][0], s[3][1])));
        float bm_hi = fmaxf(fmaxf(fmaxf(s[0][2], s[0][3]), fmaxf(s[1][2], s[1][3])),
                            fmaxf(fmaxf(s[2][2], s[2][3]), fmaxf(s[3][2], s[3][3])));
        bm_lo = fmaxf(bm_lo, __shfl_xor_sync(0xffffffffu, bm_lo, 1));
        bm_lo = fmaxf(bm_lo, __shfl_xor_sync(0xffffffffu, bm_lo, 2));
        bm_hi = fmaxf(bm_hi, __shfl_xor_sync(0xffffffffu, bm_hi, 1));
        bm_hi = fmaxf(bm_hi, __shfl_xor_sync(0xffffffffu, bm_hi, 2));

        if ((bm_lo > m_lo) | (bm_hi > m_hi)) {
            float mn_lo = fmaxf(m_lo, bm_lo);
            float mn_hi = fmaxf(m_hi, bm_hi);
            float c_lo = ex2f(m_lo - mn_lo);
            float c_hi = ex2f(m_hi - mn_hi);
            l_lo *= c_lo; l_hi *= c_hi;
#pragma unroll
            for (int nt = 0; nt < 2; nt++) {
                o[nt][0] *= c_lo; o[nt][1] *= c_lo;
                o[nt][2] *= c_hi; o[nt][3] *= c_hi;
            }
            m_lo = mn_lo; m_hi = mn_hi;
        }

        // ---- exp (base 2) ----
        float p[4][4];
#pragma unroll
        for (int t = 0; t < 4; t++) {
            p[t][0] = ex2f(s[t][0] - m_lo);
            p[t][1] = ex2f(s[t][1] - m_lo);
            p[t][2] = ex2f(s[t][2] - m_hi);
            p[t][3] = ex2f(s[t][3] - m_hi);
            l_lo += p[t][0] + p[t][1];
            l_hi += p[t][2] + p[t][3];
        }

        // ---- P@V: 2 k16-groups x 2 dim-tiles, f16 (no shuffles) ----
#pragma unroll
        for (int G = 0; G < 2; G++) {
            uint32_t aP[4];
            aP[0] = h2pack(p[2 * G][0],     p[2 * G][1]);      // [g][2q,2q+1]
            aP[1] = h2pack(p[2 * G][2],     p[2 * G][3]);      // [g+8][2q,2q+1]
            aP[2] = h2pack(p[2 * G + 1][0], p[2 * G + 1][1]);  // [g][2q+8,+9]
            aP[3] = h2pack(p[2 * G + 1][2], p[2 * G + 1][3]);  // [g+8][2q+8,+9]
#pragma unroll
            for (int nt = 0; nt < 2; nt++) {
                const int n = nt * 8 + g;
                uint32_t vb0 = *(const uint32_t*)&VsmT[n][G * 16 + 2 * q4];
                uint32_t vb1 = *(const uint32_t*)&VsmT[n][G * 16 + 2 * q4 + 8];
                mma_f16(o[nt], aP, vb0, vb1);
            }
        }
    }

    // ---- finalize: quad-reduce l, write partials ----
    l_lo += __shfl_xor_sync(0xffffffffu, l_lo, 1);
    l_lo += __shfl_xor_sync(0xffffffffu, l_lo, 2);
    l_hi += __shfl_xor_sync(0xffffffffu, l_hi, 1);
    l_hi += __shfl_xor_sync(0xffffffffu, l_hi, 2);

    const int z = blockIdx.z;
    const size_t qlo = (size_t)pair * SEQ + row_lo;
    const size_t qhi = (size_t)pair * SEQ + row_hi;
    float* plo = g_po + ((size_t)z * QH + qlo) * HD;
    float* phi = g_po + ((size_t)z * QH + qhi) * HD;
    *(float2*)&plo[2 * q4]     = make_float2(o[0][0], o[0][1]);
    *(float2*)&plo[8 + 2 * q4] = make_float2(o[1][0], o[1][1]);
    *(float2*)&phi[2 * q4]     = make_float2(o[0][2], o[0][3]);
    *(float2*)&phi[8 + 2 * q4] = make_float2(o[1][2], o[1][3]);
    if (q4 == 0) {
        g_pm[(size_t)z * QH + qlo] = m_lo;
        g_pl[(size_t)z * QH + qlo] = l_lo;
        g_pm[(size_t)z * QH + qhi] = m_hi;
        g_pl[(size_t)z * QH + qhi] = l_hi;
    }
}

// ---------------------------------------------------------------------------
// Kernel 3b: merge KSPLIT partials -> g_o, written HEAD-REORDERED.
// ---------------------------------------------------------------------------
__global__ __launch_bounds__(256) void merge_kernel()
{
    int qidx = blockIdx.x * 256 + threadIdx.x;
    if (qidx >= QH) return;
    const int pair = qidx >> 11;
    const int row  = qidx & 2047;
    const int b    = pair >> 3;
    const int h    = pair & 7;

    float m[KSPLIT], l[KSPLIT], c[KSPLIT];
    float mm = -1e30f;
#pragma unroll
    for (int z = 0; z < KSPLIT; z++) {
        m[z] = g_pm[(size_t)z * QH + qidx];
        l[z] = g_pl[(size_t)z * QH + qidx];
        mm = fmaxf(mm, m[z]);
    }
    float denom = 0.f;
#pragma unroll
    for (int z = 0; z < KSPLIT; z++) {
        c[z] = ex2f(m[z] - mm);
        denom += l[z] * c[z];
    }
    float inv = 1.0f / denom;
#pragma unroll
    for (int z = 0; z < KSPLIT; z++) c[z] *= inv;

    float4 out[4];
#pragma unroll
    for (int k4 = 0; k4 < 4; k4++) {
        float4 r = make_float4(0.f, 0.f, 0.f, 0.f);
#pragma unroll
        for (int z = 0; z < KSPLIT; z++) {
            const float4 a = ((const float4*)(g_po + ((size_t)z * QH + qidx) * HD))[k4];
            r.x = fmaf(a.x, c[z], r.x);
            r.y = fmaf(a.y, c[z], r.y);
            r.z = fmaf(a.z, c[z], r.z);
            r.w = fmaf(a.w, c[z], r.w);
        }
        out[k4] = r;
    }

#pragma unroll
    for (int slot = 0; slot < 8; slot++) {
        if (c_head_order[slot] == h) {
            float4* dst = (float4*)(g_o + ((size_t)(b * SEQ + row) * DIM + slot * HD));
            dst[0] = out[0]; dst[1] = out[1]; dst[2] = out[2]; dst[3] = out[3];
        }
    }
}

// ---------------------------------------------------------------------------
// Kernel 4: output projection (g_o already head-reordered), 8-deep W-load ILP.
// ---------------------------------------------------------------------------
__global__ __launch_bounds__(256) void proj_kernel(
    const float* __restrict__ lin_b,
    float* __restrict__ y)
{
    __shared__ u64 xd[32][128];
    const int tid  = threadIdx.x;
    const int row0 = blockIdx.x * 32;

    const float4* g4 = (const float4*)(g_o + (size_t)row0 * DIM);
#pragma unroll
    for (int it = 0; it < 4; it++) {
        int i = tid + it * 256;
        float4 v = g4[i];
        int r = i >> 5, c = (i & 31) * 4;
        xd[r][c + 0] = pk2(v.x, v.x);
        xd[r][c + 1] = pk2(v.y, v.y);
        xd[r][c + 2] = pk2(v.z, v.z);
        xd[r][c + 3] = pk2(v.w, v.w);
    }
    __syncthreads();

    const int jh = tid & 63;
    const int rg = tid >> 6;

    float2 b2 = *(const float2*)&lin_b[jh * 2];
    const u64 bias = pk2(b2.x, b2.y);
    u64 acc[8];
#pragma unroll
    for (int r = 0; r < 8; r++) acc[r] = bias;

    const u64* Wp = (const u64*)g_lwT;
#pragma unroll
    for (int d0 = 0; d0 < 128; d0 += 8) {
        u64 w[8];
#pragma unroll
        for (int i = 0; i < 8; i++) w[i] = Wp[(d0 + i) * 64 + jh];
#pragma unroll
        for (int i = 0; i < 8; i++) {
#pragma unroll
            for (int r = 0; r < 8; r++)
                acc[r] = fma2_(xd[rg + r * 4][d0 + i], w[i], acc[r]);
        }
    }
    u64* yp = (u64*)y;
#pragma unroll
    for (int r = 0; r < 8; r++)
        yp[(size_t)(row0 + rg + r * 4) * 64 + jh] = acc[r];
}

// ---------------------------------------------------------------------------
extern "C" void kernel_launch(void* const* d_in, const int* in_sizes, int n_in,
                              void* d_out, int out_size)
{
    const float* x    = (const float*)d_in[0];
    const int*   mraw = (const int*)  d_in[1];
    const float* wq   = (const float*)d_in[2];
    const float* wk   = (const float*)d_in[3];
    const float* wv   = (const float*)d_in[4];
    const float* lw   = (const float*)d_in[5];
    const float* lb   = (const float*)d_in[6];
    float*       y    = (float*)d_out;

    qkv_kernel<<<dim3(ROWS / 32, 3), 256>>>(x, wq, wk, wv);
    prepW_kernel<<<64, 256>>>(lw);
    prepM_kernel<<<32, 256>>>(mraw);
    attn_kernel<<<dim3(SEQ / QTILE, 32, KSPLIT), 128>>>();
    merge_kernel<<<QH / 256, 256>>>();
    proj_kernel<<<ROWS / 32, 256>>>(lb, y);
}

// round 9
// speedup vs baseline: 3.0519x; 1.1701x over previous
#include <cuda_runtime.h>
#include <cuda_fp16.h>
#include <cstdint>

// Problem constants
constexpr int BATCH = 4;
constexpr int SEQ   = 2048;
constexpr int DIM   = 128;
constexpr int HD    = 16;
constexpr int ROWS  = BATCH * SEQ;        // 8192
constexpr int QH    = BATCH * 8 * SEQ;    // 65536 query-head rows
constexpr int KSPLIT = 4;
constexpr int BK    = 32;                 // keys staged per block
constexpr int QTILE = 64;                 // queries per CTA (4 warps x 16)

// Scratch (device globals — no allocation allowed)
__device__ uint32_t g_qh[ROWS * 64];      // Q as packed half2 (col pairs)
__device__ uint32_t g_kh[ROWS * 64];      // K f16, pre-scaled by (1/sqrt(128))*log2(e)
__device__ uint32_t g_vh[ROWS * 64];      // V f16
__device__ float g_o[ROWS * DIM];         // merge writes this HEAD-REORDERED
__device__ float g_lwT[DIM * DIM];
__device__ float g_maskf[ROWS];
__device__ float g_po[(size_t)KSPLIT * QH * HD];
__device__ float g_pm[(size_t)KSPLIT * QH];
__device__ float g_pl[(size_t)KSPLIT * QH];

__constant__ int c_head_order[8] = {0, 1, 1, 2, 3, 4, 5, 6};

// ---------------------------------------------------------------------------
// Helpers
// ---------------------------------------------------------------------------
typedef unsigned long long u64;

__device__ __forceinline__ u64 pk2(float lo, float hi) {
    u64 r; asm("mov.b64 %0,{%1,%2};" : "=l"(r) : "f"(lo), "f"(hi)); return r;
}
__device__ __forceinline__ void upk2(float& lo, float& hi, u64 v) {
    asm("mov.b64 {%0,%1},%2;" : "=f"(lo), "=f"(hi) : "l"(v));
}
__device__ __forceinline__ u64 fma2_(u64 a, u64 b, u64 c) {
    u64 d; asm("fma.rn.f32x2 %0,%1,%2,%3;" : "=l"(d) : "l"(a), "l"(b), "l"(c)); return d;
}
__device__ __forceinline__ u64 mul2_(u64 a, u64 b) {
    u64 d; asm("mul.rn.f32x2 %0,%1,%2;" : "=l"(d) : "l"(a), "l"(b)); return d;
}
__device__ __forceinline__ float ex2f(float x) {
    float y; asm("ex2.approx.ftz.f32 %0,%1;" : "=f"(y) : "f"(x)); return y;
}
__device__ __forceinline__ uint32_t h2pack(float lo, float hi) {
    uint32_t r;
    asm("cvt.rn.f16x2.f32 %0, %1, %2;" : "=r"(r) : "f"(hi), "f"(lo));
    return r;
}
// D += A * B  (m16n8k16 f16, f32 accumulate)
__device__ __forceinline__ void mma_f16(float* d, const uint32_t* a,
                                        uint32_t b0, uint32_t b1) {
    asm volatile(
        "mma.sync.aligned.m16n8k16.row.col.f32.f16.f16.f32 "
        "{%0,%1,%2,%3},{%4,%5,%6,%7},{%8,%9},{%0,%1,%2,%3};"
        : "+f"(d[0]), "+f"(d[1]), "+f"(d[2]), "+f"(d[3])
        : "r"(a[0]), "r"(a[1]), "r"(a[2]), "r"(a[3]), "r"(b0), "r"(b1));
}

// ---------------------------------------------------------------------------
// Kernel 1: fused QKV projection (FFMA2 dup-packed), f16 packed output.
// K pre-scaled by (1/sqrt(128))*log2(e).
// ---------------------------------------------------------------------------
__global__ __launch_bounds__(256) void qkv_kernel(
    const float* __restrict__ x,
    const float* __restrict__ wq,
    const float* __restrict__ wk,
    const float* __restrict__ wv)
{
    __shared__ u64 xd[32][128];
    const int tid  = threadIdx.x;
    const int row0 = blockIdx.x * 32;

    const float* W    = (blockIdx.y == 0) ? wq : (blockIdx.y == 1) ? wk : wv;
    uint32_t*    outh = (blockIdx.y == 0) ? g_qh : (blockIdx.y == 1) ? g_kh : g_vh;

    const float4* x4 = (const float4*)(x + (size_t)row0 * DIM);
#pragma unroll
    for (int it = 0; it < 4; it++) {
        int i = tid + it * 256;
        float4 v = x4[i];
        int r = i >> 5, c = (i & 31) * 4;
        xd[r][c + 0] = pk2(v.x, v.x);
        xd[r][c + 1] = pk2(v.y, v.y);
        xd[r][c + 2] = pk2(v.z, v.z);
        xd[r][c + 3] = pk2(v.w, v.w);
    }
    __syncthreads();

    const int jh = tid & 63;
    const int rg = tid >> 6;
    const u64* Wp = (const u64*)W;

    u64 acc[8];
#pragma unroll
    for (int r = 0; r < 8; r++) acc[r] = 0ull;

#pragma unroll 4
    for (int d = 0; d < 128; d++) {
        u64 wp = Wp[d * 64 + jh];
#pragma unroll
        for (int r = 0; r < 8; r++)
            acc[r] = fma2_(xd[rg + r * 4][d], wp, acc[r]);
    }

    if (blockIdx.y == 1) {
        const float sc = 0.08838834764831845f * 1.4426950408889634f;
        const u64 sc2 = pk2(sc, sc);
#pragma unroll
        for (int r = 0; r < 8; r++) acc[r] = mul2_(acc[r], sc2);
    }

#pragma unroll
    for (int r = 0; r < 8; r++) {
        float lo, hi; upk2(lo, hi, acc[r]);
        outh[(size_t)(row0 + rg + r * 4) * 64 + jh] = h2pack(lo, hi);
    }
}

// ---------------------------------------------------------------------------
// Kernel 2a/2b: prep
// ---------------------------------------------------------------------------
__global__ __launch_bounds__(256) void prepW_kernel(const float* __restrict__ lin_w)
{
    for (int idx = blockIdx.x * 256 + threadIdx.x; idx < DIM * DIM;
         idx += gridDim.x * 256) {
        int j = idx >> 7, c = idx & 127;
        g_lwT[c * 128 + j] = lin_w[idx];
    }
}

__global__ __launch_bounds__(256) void prepM_kernel(const int* __restrict__ mraw)
{
    __shared__ int is64;
    if (threadIdx.x == 0) {
        int acc = 0;
        for (int i = 0; i < 64; i++) acc |= mraw[2 * i + 1];
        is64 = (acc == 0);
    }
    __syncthreads();
    for (int idx = blockIdx.x * 256 + threadIdx.x; idx < ROWS;
         idx += gridDim.x * 256) {
        int v = is64 ? mraw[2 * idx] : mraw[idx];
        g_maskf[idx] = (v == 0) ? -1442.6950408889634f : 0.0f;
    }
}

// ---------------------------------------------------------------------------
// Kernel 3: flash attention, all-f16 mma.sync m16n8k16.
// QK^T: K staged [key][dim] f16 (stride 40 halves, conflict-free half2 frags);
//       4 MMAs per 32-key block.
// P@V:  C-frag == A-frag identity (no shuffles); V staged [dim][key] f16.
// Q/K/V pre-converted to f16 by qkv_kernel -> zero cvt in the hot loop.
// ---------------------------------------------------------------------------
__global__ __launch_bounds__(128, 8) void attn_kernel()
{
    __shared__ __half Ksm[BK][40];    // [key][dim], stride 40 halves
    __shared__ __half Vsm[16][40];    // [dim][key], stride 40 halves
    __shared__ float  ms[BK];

    const int tid  = threadIdx.x;
    const int w    = tid >> 5;
    const int lane = tid & 31;
    const int g    = lane >> 2;
    const int q4   = lane & 3;
    const int pair = blockIdx.y;      // b*8 + h
    const int b    = pair >> 3;
    const int h    = pair & 7;
    const int q0   = blockIdx.x * QTILE + w * 16;
    const int kstart = blockIdx.z * (SEQ / KSPLIT);

    const int row_lo = q0 + g;
    const int row_hi = row_lo + 8;

    // Q fragments: direct packed-half2 loads (layout identity with g_qh)
    uint32_t aQ[4];
    aQ[0] = g_qh[(size_t)(b * SEQ + row_lo) * 64 + h * 8 + q4];
    aQ[1] = g_qh[(size_t)(b * SEQ + row_hi) * 64 + h * 8 + q4];
    aQ[2] = g_qh[(size_t)(b * SEQ + row_lo) * 64 + h * 8 + q4 + 4];
    aQ[3] = g_qh[(size_t)(b * SEQ + row_hi) * 64 + h * 8 + q4 + 4];

    float m_lo = -1e30f, m_hi = -1e30f, l_lo = 0.f, l_hi = 0.f;
    float o[2][4];
#pragma unroll
    for (int nt = 0; nt < 2; nt++)
#pragma unroll
        for (int i = 0; i < 4; i++) o[nt][i] = 0.f;

    const int skey = tid >> 2;          // staging: key 0..31
    const int sd0  = (tid & 3) * 4;     // staging: dim group {0,4,8,12}

    for (int kb = kstart; kb < kstart + SEQ / KSPLIT; kb += BK) {
        __syncthreads();
        // ---- stage K [key][dim] (LDG.64 -> STS.64), V transposed, mask ----
        {
            size_t base = (size_t)(b * SEQ + kb + skey) * 64 + h * 8 + (sd0 >> 1);
            uint2 kv = *(const uint2*)&g_kh[base];
            *(uint2*)&Ksm[skey][sd0] = kv;
            uint2 vv = *(const uint2*)&g_vh[base];
            __half2 v0 = *(__half2*)&vv.x;
            __half2 v1 = *(__half2*)&vv.y;
            Vsm[sd0 + 0][skey] = __low2half(v0);
            Vsm[sd0 + 1][skey] = __high2half(v0);
            Vsm[sd0 + 2][skey] = __low2half(v1);
            Vsm[sd0 + 3][skey] = __high2half(v1);
            if (tid < BK) ms[tid] = g_maskf[b * SEQ + kb + tid];
        }
        __syncthreads();

        // ---- QK^T: 4 key-tiles, one f16 MMA each (k=16 = full HD) ----
        float s[4][4];
#pragma unroll
        for (int t = 0; t < 4; t++) {
            s[t][0] = s[t][1] = s[t][2] = s[t][3] = 0.f;
            uint32_t b0 = *(const uint32_t*)&Ksm[t * 8 + g][2 * q4];
            uint32_t b1 = *(const uint32_t*)&Ksm[t * 8 + g][2 * q4 + 8];
            mma_f16(s[t], aQ, b0, b1);
            float2 mk = *(const float2*)&ms[t * 8 + 2 * q4];
            s[t][0] += mk.x; s[t][1] += mk.y;
            s[t][2] += mk.x; s[t][3] += mk.y;
        }

        // ---- block row max ----
        float bm_lo = fmaxf(fmaxf(fmaxf(s[0][0], s[0][1]), fmaxf(s[1][0], s[1][1])),
                            fmaxf(fmaxf(s[2][0], s[2][1]), fmaxf(s[3][0], s[3][1])));
        float bm_hi = fmaxf(fmaxf(fmaxf(s[0][2], s[0][3]), fmaxf(s[1][2], s[1][3])),
                            fmaxf(fmaxf(s[2][2], s[2][3]), fmaxf(s[3][2], s[3][3])));
        bm_lo = fmaxf(bm_lo, __shfl_xor_sync(0xffffffffu, bm_lo, 1));
        bm_lo = fmaxf(bm_lo, __shfl_xor_sync(0xffffffffu, bm_lo, 2));
        bm_hi = fmaxf(bm_hi, __shfl_xor_sync(0xffffffffu, bm_hi, 1));
        bm_hi = fmaxf(bm_hi, __shfl_xor_sync(0xffffffffu, bm_hi, 2));

        if ((bm_lo > m_lo) | (bm_hi > m_hi)) {
            float mn_lo = fmaxf(m_lo, bm_lo);
            float mn_hi = fmaxf(m_hi, bm_hi);
            float c_lo = ex2f(m_lo - mn_lo);
            float c_hi = ex2f(m_hi - mn_hi);
            l_lo *= c_lo; l_hi *= c_hi;
#pragma unroll
            for (int nt = 0; nt < 2; nt++) {
                o[nt][0] *= c_lo; o[nt][1] *= c_lo;
                o[nt][2] *= c_hi; o[nt][3] *= c_hi;
            }
            m_lo = mn_lo; m_hi = mn_hi;
        }

        // ---- exp (base 2) ----
        float p[4][4];
#pragma unroll
        for (int t = 0; t < 4; t++) {
            p[t][0] = ex2f(s[t][0] - m_lo);
            p[t][1] = ex2f(s[t][1] - m_lo);
            p[t][2] = ex2f(s[t][2] - m_hi);
            p[t][3] = ex2f(s[t][3] - m_hi);
            l_lo += p[t][0] + p[t][1];
            l_hi += p[t][2] + p[t][3];
        }

        // ---- P@V: 2 k16-groups x 2 dim-tiles (C-frag==A-frag, no shuffles) ----
#pragma unroll
        for (int G = 0; G < 2; G++) {
            uint32_t aP[4];
            aP[0] = h2pack(p[2 * G][0],     p[2 * G][1]);
            aP[1] = h2pack(p[2 * G][2],     p[2 * G][3]);
            aP[2] = h2pack(p[2 * G + 1][0], p[2 * G + 1][1]);
            aP[3] = h2pack(p[2 * G + 1][2], p[2 * G + 1][3]);
#pragma unroll
            for (int nt = 0; nt < 2; nt++) {
                const int n = nt * 8 + g;
                uint32_t vb0 = *(const uint32_t*)&Vsm[n][G * 16 + 2 * q4];
                uint32_t vb1 = *(const uint32_t*)&Vsm[n][G * 16 + 2 * q4 + 8];
                mma_f16(o[nt], aP, vb0, vb1);
            }
        }
    }

    // ---- finalize ----
    l_lo += __shfl_xor_sync(0xffffffffu, l_lo, 1);
    l_lo += __shfl_xor_sync(0xffffffffu, l_lo, 2);
    l_hi += __shfl_xor_sync(0xffffffffu, l_hi, 1);
    l_hi += __shfl_xor_sync(0xffffffffu, l_hi, 2);

    const int z = blockIdx.z;
    const size_t qlo = (size_t)pair * SEQ + row_lo;
    const size_t qhi = (size_t)pair * SEQ + row_hi;
    float* plo = g_po + ((size_t)z * QH + qlo) * HD;
    float* phi = g_po + ((size_t)z * QH + qhi) * HD;
    *(float2*)&plo[2 * q4]     = make_float2(o[0][0], o[0][1]);
    *(float2*)&plo[8 + 2 * q4] = make_float2(o[1][0], o[1][1]);
    *(float2*)&phi[2 * q4]     = make_float2(o[0][2], o[0][3]);
    *(float2*)&phi[8 + 2 * q4] = make_float2(o[1][2], o[1][3]);
    if (q4 == 0) {
        g_pm[(size_t)z * QH + qlo] = m_lo;
        g_pl[(size_t)z * QH + qlo] = l_lo;
        g_pm[(size_t)z * QH + qhi] = m_hi;
        g_pl[(size_t)z * QH + qhi] = l_hi;
    }
}

// ---------------------------------------------------------------------------
// Kernel 3b: merge KSPLIT partials -> g_o, written HEAD-REORDERED.
// ---------------------------------------------------------------------------
__global__ __launch_bounds__(256) void merge_kernel()
{
    int qidx = blockIdx.x * 256 + threadIdx.x;
    if (qidx >= QH) return;
    const int pair = qidx >> 11;
    const int row  = qidx & 2047;
    const int b    = pair >> 3;
    const int h    = pair & 7;

    float m[KSPLIT], l[KSPLIT], c[KSPLIT];
    float mm = -1e30f;
#pragma unroll
    for (int z = 0; z < KSPLIT; z++) {
        m[z] = g_pm[(size_t)z * QH + qidx];
        l[z] = g_pl[(size_t)z * QH + qidx];
        mm = fmaxf(mm, m[z]);
    }
    float denom = 0.f;
#pragma unroll
    for (int z = 0; z < KSPLIT; z++) {
        c[z] = ex2f(m[z] - mm);
        denom += l[z] * c[z];
    }
    float inv = 1.0f / denom;
#pragma unroll
    for (int z = 0; z < KSPLIT; z++) c[z] *= inv;

    float4 out[4];
#pragma unroll
    for (int k4 = 0; k4 < 4; k4++) {
        float4 r = make_float4(0.f, 0.f, 0.f, 0.f);
#pragma unroll
        for (int z = 0; z < KSPLIT; z++) {
            const float4 a = ((const float4*)(g_po + ((size_t)z * QH + qidx) * HD))[k4];
            r.x = fmaf(a.x, c[z], r.x);
            r.y = fmaf(a.y, c[z], r.y);
            r.z = fmaf(a.z, c[z], r.z);
            r.w = fmaf(a.w, c[z], r.w);
        }
        out[k4] = r;
    }

#pragma unroll
    for (int slot = 0; slot < 8; slot++) {
        if (c_head_order[slot] == h) {
            float4* dst = (float4*)(g_o + ((size_t)(b * SEQ + row) * DIM + slot * HD));
            dst[0] = out[0]; dst[1] = out[1]; dst[2] = out[2]; dst[3] = out[3];
        }
    }
}

// ---------------------------------------------------------------------------
// Kernel 4: output projection (g_o already head-reordered), 8-deep W-load ILP.
// ---------------------------------------------------------------------------
__global__ __launch_bounds__(256) void proj_kernel(
    const float* __restrict__ lin_b,
    float* __restrict__ y)
{
    __shared__ u64 xd[32][128];
    const int tid  = threadIdx.x;
    const int row0 = blockIdx.x * 32;

    const float4* g4 = (const float4*)(g_o + (size_t)row0 * DIM);
#pragma unroll
    for (int it = 0; it < 4; it++) {
        int i = tid + it * 256;
        float4 v = g4[i];
        int r = i >> 5, c = (i & 31) * 4;
        xd[r][c + 0] = pk2(v.x, v.x);
        xd[r][c + 1] = pk2(v.y, v.y);
        xd[r][c + 2] = pk2(v.z, v.z);
        xd[r][c + 3] = pk2(v.w, v.w);
    }
    __syncthreads();

    const int jh = tid & 63;
    const int rg = tid >> 6;

    float2 b2 = *(const float2*)&lin_b[jh * 2];
    const u64 bias = pk2(b2.x, b2.y);
    u64 acc[8];
#pragma unroll
    for (int r = 0; r < 8; r++) acc[r] = bias;

    const u64* Wp = (const u64*)g_lwT;
#pragma unroll
    for (int d0 = 0; d0 < 128; d0 += 8) {
        u64 w[8];
#pragma unroll
        for (int i = 0; i < 8; i++) w[i] = Wp[(d0 + i) * 64 + jh];
#pragma unroll
        for (int i = 0; i < 8; i++) {
#pragma unroll
            for (int r = 0; r < 8; r++)
                acc[r] = fma2_(xd[rg + r * 4][d0 + i], w[i], acc[r]);
        }
    }
    u64* yp = (u64*)y;
#pragma unroll
    for (int r = 0; r < 8; r++)
        yp[(size_t)(row0 + rg + r * 4) * 64 + jh] = acc[r];
}

// ---------------------------------------------------------------------------
extern "C" void kernel_launch(void* const* d_in, const int* in_sizes, int n_in,
                              void* d_out, int out_size)
{
    const float* x    = (const float*)d_in[0];
    const int*   mraw = (const int*)  d_in[1];
    const float* wq   = (const float*)d_in[2];
    const float* wk   = (const float*)d_in[3];
    const float* wv   = (const float*)d_in[4];
    const float* lw   = (const float*)d_in[5];
    const float* lb   = (const float*)d_in[6];
    float*       y    = (float*)d_out;

    qkv_kernel<<<dim3(ROWS / 32, 3), 256>>>(x, wq, wk, wv);
    prepW_kernel<<<64, 256>>>(lw);
    prepM_kernel<<<32, 256>>>(mraw);
    attn_kernel<<<dim3(SEQ / QTILE, 32, KSPLIT), 128>>>();
    merge_kernel<<<QH / 256, 256>>>();
    proj_kernel<<<ROWS / 32, 256>>>(lb, y);
}

// round 10
// speedup vs baseline: 3.2407x; 1.0619x over previous
#include <cuda_runtime.h>
#include <cuda_fp16.h>
#include <cstdint>

// Problem constants
constexpr int BATCH = 4;
constexpr int SEQ   = 2048;
constexpr int DIM   = 128;
constexpr int HD    = 16;
constexpr int ROWS  = BATCH * SEQ;        // 8192
constexpr int NPAIR = BATCH * 7;          // head 7 is dead (never concatenated)
constexpr int QH    = BATCH * 8 * SEQ;    // partial-array stride (roomy)
constexpr int KSPLIT = 4;
constexpr int BK    = 64;                 // keys staged per block
constexpr int QTILE = 64;                 // queries per CTA (4 warps x 16)

// Scratch (device globals — no allocation allowed)
__device__ uint32_t g_qh[ROWS * 64];      // Q packed half2
__device__ uint32_t g_kh[ROWS * 64];      // K f16, pre-scaled by (1/sqrt(128))*log2(e)
__device__ uint32_t g_vh[ROWS * 64];      // V f16
__device__ float g_lwT[DIM * DIM];
__device__ float g_maskf[ROWS];
__device__ float g_po[(size_t)KSPLIT * QH * HD];
__device__ float g_pm[(size_t)KSPLIT * QH];
__device__ float g_pl[(size_t)KSPLIT * QH];

__constant__ int c_head_order[8] = {0, 1, 1, 2, 3, 4, 5, 6};

// ---------------------------------------------------------------------------
// Helpers
// ---------------------------------------------------------------------------
typedef unsigned long long u64;

__device__ __forceinline__ u64 pk2(float lo, float hi) {
    u64 r; asm("mov.b64 %0,{%1,%2};" : "=l"(r) : "f"(lo), "f"(hi)); return r;
}
__device__ __forceinline__ void upk2(float& lo, float& hi, u64 v) {
    asm("mov.b64 {%0,%1},%2;" : "=f"(lo), "=f"(hi) : "l"(v));
}
__device__ __forceinline__ u64 fma2_(u64 a, u64 b, u64 c) {
    u64 d; asm("fma.rn.f32x2 %0,%1,%2,%3;" : "=l"(d) : "l"(a), "l"(b), "l"(c)); return d;
}
__device__ __forceinline__ u64 mul2_(u64 a, u64 b) {
    u64 d; asm("mul.rn.f32x2 %0,%1,%2;" : "=l"(d) : "l"(a), "l"(b)); return d;
}
__device__ __forceinline__ float ex2f(float x) {
    float y; asm("ex2.approx.ftz.f32 %0,%1;" : "=f"(y) : "f"(x)); return y;
}
__device__ __forceinline__ uint32_t h2pack(float lo, float hi) {
    uint32_t r;
    asm("cvt.rn.f16x2.f32 %0, %1, %2;" : "=r"(r) : "f"(hi), "f"(lo));
    return r;
}
__device__ __forceinline__ void mma_f16(float* d, const uint32_t* a,
                                        uint32_t b0, uint32_t b1) {
    asm volatile(
        "mma.sync.aligned.m16n8k16.row.col.f32.f16.f16.f32 "
        "{%0,%1,%2,%3},{%4,%5,%6,%7},{%8,%9},{%0,%1,%2,%3};"
        : "+f"(d[0]), "+f"(d[1]), "+f"(d[2]), "+f"(d[3])
        : "r"(a[0]), "r"(a[1]), "r"(a[2]), "r"(a[3]), "r"(b0), "r"(b1));
}

// ---------------------------------------------------------------------------
// Kernel 1: fused QKV projection (FFMA2 dup-packed), f16 packed output.
// ---------------------------------------------------------------------------
__global__ __launch_bounds__(256) void qkv_kernel(
    const float* __restrict__ x,
    const float* __restrict__ wq,
    const float* __restrict__ wk,
    const float* __restrict__ wv)
{
    __shared__ u64 xd[32][128];
    const int tid  = threadIdx.x;
    const int row0 = blockIdx.x * 32;

    const float* W    = (blockIdx.y == 0) ? wq : (blockIdx.y == 1) ? wk : wv;
    uint32_t*    outh = (blockIdx.y == 0) ? g_qh : (blockIdx.y == 1) ? g_kh : g_vh;

    const float4* x4 = (const float4*)(x + (size_t)row0 * DIM);
#pragma unroll
    for (int it = 0; it < 4; it++) {
        int i = tid + it * 256;
        float4 v = x4[i];
        int r = i >> 5, c = (i & 31) * 4;
        xd[r][c + 0] = pk2(v.x, v.x);
        xd[r][c + 1] = pk2(v.y, v.y);
        xd[r][c + 2] = pk2(v.z, v.z);
        xd[r][c + 3] = pk2(v.w, v.w);
    }
    __syncthreads();

    const int jh = tid & 63;
    const int rg = tid >> 6;
    const u64* Wp = (const u64*)W;

    u64 acc[8];
#pragma unroll
    for (int r = 0; r < 8; r++) acc[r] = 0ull;

#pragma unroll 4
    for (int d = 0; d < 128; d++) {
        u64 wp = Wp[d * 64 + jh];
#pragma unroll
        for (int r = 0; r < 8; r++)
            acc[r] = fma2_(xd[rg + r * 4][d], wp, acc[r]);
    }

    if (blockIdx.y == 1) {
        const float sc = 0.08838834764831845f * 1.4426950408889634f;
        const u64 sc2 = pk2(sc, sc);
#pragma unroll
        for (int r = 0; r < 8; r++) acc[r] = mul2_(acc[r], sc2);
    }

#pragma unroll
    for (int r = 0; r < 8; r++) {
        float lo, hi; upk2(lo, hi, acc[r]);
        outh[(size_t)(row0 + rg + r * 4) * 64 + jh] = h2pack(lo, hi);
    }
}

// ---------------------------------------------------------------------------
// Kernel 2a/2b: prep
// ---------------------------------------------------------------------------
__global__ __launch_bounds__(256) void prepW_kernel(const float* __restrict__ lin_w)
{
    for (int idx = blockIdx.x * 256 + threadIdx.x; idx < DIM * DIM;
         idx += gridDim.x * 256) {
        int j = idx >> 7, c = idx & 127;
        g_lwT[c * 128 + j] = lin_w[idx];
    }
}

__global__ __launch_bounds__(256) void prepM_kernel(const int* __restrict__ mraw)
{
    __shared__ int is64;
    if (threadIdx.x == 0) {
        int acc = 0;
        for (int i = 0; i < 64; i++) acc |= mraw[2 * i + 1];
        is64 = (acc == 0);
    }
    __syncthreads();
    for (int idx = blockIdx.x * 256 + threadIdx.x; idx < ROWS;
         idx += gridDim.x * 256) {
        int v = is64 ? mraw[2 * idx] : mraw[idx];
        g_maskf[idx] = (v == 0) ? -1442.6950408889634f : 0.0f;
    }
}

// ---------------------------------------------------------------------------
// Kernel 3: flash attention, all-f16 mma.sync, BK=64, head 7 skipped.
// grid (SEQ/QTILE, 28 pairs, KSPLIT); pair -> (b = pair/7, h = pair%7).
// Exp overwrites score regs in place (peak live set unchanged vs BK=32).
// ---------------------------------------------------------------------------
__global__ __launch_bounds__(128, 8) void attn_kernel()
{
    __shared__ __half Ksm[BK][40];    // [key][dim], stride 40 halves
    __shared__ __half Vsm[16][72];    // [dim][key], stride 72 halves
    __shared__ float  ms[BK];

    const int tid  = threadIdx.x;
    const int lane = tid & 31;
    const int g    = lane >> 2;
    const int q4   = lane & 3;
    const int pair = blockIdx.y;          // 0..27
    const int b    = pair / 7;
    const int h    = pair - b * 7;        // 0..6 (head 7 dead)
    const int q0   = blockIdx.x * QTILE + (tid >> 5) * 16;
    const int kstart = blockIdx.z * (SEQ / KSPLIT);

    const int row_lo = q0 + g;
    const int row_hi = row_lo + 8;

    uint32_t aQ[4];
    aQ[0] = g_qh[(size_t)(b * SEQ + row_lo) * 64 + h * 8 + q4];
    aQ[1] = g_qh[(size_t)(b * SEQ + row_hi) * 64 + h * 8 + q4];
    aQ[2] = g_qh[(size_t)(b * SEQ + row_lo) * 64 + h * 8 + q4 + 4];
    aQ[3] = g_qh[(size_t)(b * SEQ + row_hi) * 64 + h * 8 + q4 + 4];

    float m_lo = -1e30f, m_hi = -1e30f, l_lo = 0.f, l_hi = 0.f;
    float o[2][4];
#pragma unroll
    for (int nt = 0; nt < 2; nt++)
#pragma unroll
        for (int i = 0; i < 4; i++) o[nt][i] = 0.f;

    const int skey = tid >> 1;            // staging key 0..63
    const int koff = (tid & 1) * 4;       // uint32 offset within head row

    for (int kb = kstart; kb < kstart + SEQ / KSPLIT; kb += BK) {
        __syncthreads();
        // ---- stage K [key][dim] (LDG.128->STS.128), V transposed, mask ----
        {
            size_t base = (size_t)(b * SEQ + kb + skey) * 64 + h * 8 + koff;
            uint4 kv = *(const uint4*)&g_kh[base];
            *(uint4*)&Ksm[skey][koff * 2] = kv;
            uint4 vv = *(const uint4*)&g_vh[base];
            const int d0 = koff * 2;
            __half2 v0 = *(__half2*)&vv.x;
            __half2 v1 = *(__half2*)&vv.y;
            __half2 v2 = *(__half2*)&vv.z;
            __half2 v3 = *(__half2*)&vv.w;
            Vsm[d0 + 0][skey] = __low2half(v0);
            Vsm[d0 + 1][skey] = __high2half(v0);
            Vsm[d0 + 2][skey] = __low2half(v1);
            Vsm[d0 + 3][skey] = __high2half(v1);
            Vsm[d0 + 4][skey] = __low2half(v2);
            Vsm[d0 + 5][skey] = __high2half(v2);
            Vsm[d0 + 6][skey] = __low2half(v3);
            Vsm[d0 + 7][skey] = __high2half(v3);
            if (tid < BK) ms[tid] = g_maskf[b * SEQ + kb + tid];
        }
        __syncthreads();

        // ---- QK^T: 8 key-tiles, one f16 MMA each ----
        float s[8][4];
#pragma unroll
        for (int t = 0; t < 8; t++) {
            s[t][0] = s[t][1] = s[t][2] = s[t][3] = 0.f;
            uint32_t b0 = *(const uint32_t*)&Ksm[t * 8 + g][2 * q4];
            uint32_t b1 = *(const uint32_t*)&Ksm[t * 8 + g][2 * q4 + 8];
            mma_f16(s[t], aQ, b0, b1);
            float2 mk = *(const float2*)&ms[t * 8 + 2 * q4];
            s[t][0] += mk.x; s[t][1] += mk.y;
            s[t][2] += mk.x; s[t][3] += mk.y;
        }

        // ---- block row max ----
        float bm_lo = -1e30f, bm_hi = -1e30f;
#pragma unroll
        for (int t = 0; t < 8; t++) {
            bm_lo = fmaxf(bm_lo, fmaxf(s[t][0], s[t][1]));
            bm_hi = fmaxf(bm_hi, fmaxf(s[t][2], s[t][3]));
        }
        bm_lo = fmaxf(bm_lo, __shfl_xor_sync(0xffffffffu, bm_lo, 1));
        bm_lo = fmaxf(bm_lo, __shfl_xor_sync(0xffffffffu, bm_lo, 2));
        bm_hi = fmaxf(bm_hi, __shfl_xor_sync(0xffffffffu, bm_hi, 1));
        bm_hi = fmaxf(bm_hi, __shfl_xor_sync(0xffffffffu, bm_hi, 2));

        if ((bm_lo > m_lo) | (bm_hi > m_hi)) {
            float mn_lo = fmaxf(m_lo, bm_lo);
            float mn_hi = fmaxf(m_hi, bm_hi);
            float c_lo = ex2f(m_lo - mn_lo);
            float c_hi = ex2f(m_hi - mn_hi);
            l_lo *= c_lo; l_hi *= c_hi;
#pragma unroll
            for (int nt = 0; nt < 2; nt++) {
                o[nt][0] *= c_lo; o[nt][1] *= c_lo;
                o[nt][2] *= c_hi; o[nt][3] *= c_hi;
            }
            m_lo = mn_lo; m_hi = mn_hi;
        }

        // ---- exp in place ----
#pragma unroll
        for (int t = 0; t < 8; t++) {
            s[t][0] = ex2f(s[t][0] - m_lo);
            s[t][1] = ex2f(s[t][1] - m_lo);
            s[t][2] = ex2f(s[t][2] - m_hi);
            s[t][3] = ex2f(s[t][3] - m_hi);
            l_lo += s[t][0] + s[t][1];
            l_hi += s[t][2] + s[t][3];
        }

        // ---- P@V: 4 k16-groups x 2 dim-tiles (C-frag==A-frag) ----
#pragma unroll
        for (int G = 0; G < 4; G++) {
            uint32_t aP[4];
            aP[0] = h2pack(s[2 * G][0],     s[2 * G][1]);
            aP[1] = h2pack(s[2 * G][2],     s[2 * G][3]);
            aP[2] = h2pack(s[2 * G + 1][0], s[2 * G + 1][1]);
            aP[3] = h2pack(s[2 * G + 1][2], s[2 * G + 1][3]);
#pragma unroll
            for (int nt = 0; nt < 2; nt++) {
                const int n = nt * 8 + g;
                uint32_t vb0 = *(const uint32_t*)&Vsm[n][G * 16 + 2 * q4];
                uint32_t vb1 = *(const uint32_t*)&Vsm[n][G * 16 + 2 * q4 + 8];
                mma_f16(o[nt], aP, vb0, vb1);
            }
        }
    }

    // ---- finalize ----
    l_lo += __shfl_xor_sync(0xffffffffu, l_lo, 1);
    l_lo += __shfl_xor_sync(0xffffffffu, l_lo, 2);
    l_hi += __shfl_xor_sync(0xffffffffu, l_hi, 1);
    l_hi += __shfl_xor_sync(0xffffffffu, l_hi, 2);

    const int z = blockIdx.z;
    const size_t qlo = (size_t)pair * SEQ + row_lo;
    const size_t qhi = (size_t)pair * SEQ + row_hi;
    float* plo = g_po + ((size_t)z * QH + qlo) * HD;
    float* phi = g_po + ((size_t)z * QH + qhi) * HD;
    *(float2*)&plo[2 * q4]     = make_float2(o[0][0], o[0][1]);
    *(float2*)&plo[8 + 2 * q4] = make_float2(o[1][0], o[1][1]);
    *(float2*)&phi[2 * q4]     = make_float2(o[0][2], o[0][3]);
    *(float2*)&phi[8 + 2 * q4] = make_float2(o[1][2], o[1][3]);
    if (q4 == 0) {
        g_pm[(size_t)z * QH + qlo] = m_lo;
        g_pl[(size_t)z * QH + qlo] = l_lo;
        g_pm[(size_t)z * QH + qhi] = m_hi;
        g_pl[(size_t)z * QH + qhi] = l_hi;
    }
}

// ---------------------------------------------------------------------------
// Kernel 4: FUSED merge + head-reorder gather + output projection.
// Thread (r, slot): computes split-softmax coefficients for its (row, head),
// gathers+normalizes 16 dims from g_po into dup-packed smem, then GEMM.
// ---------------------------------------------------------------------------
__global__ __launch_bounds__(256) void proj_kernel(
    const float* __restrict__ lin_b,
    float* __restrict__ y)
{
    __shared__ u64 xd[32][128];
    const int tid  = threadIdx.x;
    const int row0 = blockIdx.x * 32;
    const int b    = row0 >> 11;          // row0 / SEQ
    const int rin0 = row0 & 2047;

    // ---- gather phase: thread owns (r, slot) ----
    {
        const int r    = tid >> 3;
        const int slot = tid & 7;
        const int hh   = c_head_order[slot];
        const size_t qidx = (size_t)(b * 7 + hh) * SEQ + rin0 + r;

        float m[KSPLIT], l[KSPLIT], c[KSPLIT];
        float mm = -1e30f;
#pragma unroll
        for (int z = 0; z < KSPLIT; z++) {
            m[z] = g_pm[(size_t)z * QH + qidx];
            l[z] = g_pl[(size_t)z * QH + qidx];
            mm = fmaxf(mm, m[z]);
        }
        float denom = 0.f;
#pragma unroll
        for (int z = 0; z < KSPLIT; z++) {
            c[z] = ex2f(m[z] - mm);
            denom += l[z] * c[z];
        }
        float inv = 1.0f / denom;
#pragma unroll
        for (int z = 0; z < KSPLIT; z++) c[z] *= inv;

        float acc[16];
#pragma unroll
        for (int j = 0; j < 16; j++) acc[j] = 0.f;
#pragma unroll
        for (int z = 0; z < KSPLIT; z++) {
            const float4* po = (const float4*)(g_po + ((size_t)z * QH + qidx) * HD);
#pragma unroll
            for (int k4 = 0; k4 < 4; k4++) {
                float4 a = po[k4];
                acc[k4 * 4 + 0] = fmaf(a.x, c[z], acc[k4 * 4 + 0]);
                acc[k4 * 4 + 1] = fmaf(a.y, c[z], acc[k4 * 4 + 1]);
                acc[k4 * 4 + 2] = fmaf(a.z, c[z], acc[k4 * 4 + 2]);
                acc[k4 * 4 + 3] = fmaf(a.w, c[z], acc[k4 * 4 + 3]);
            }
        }
#pragma unroll
        for (int j = 0; j < 16; j++)
            xd[r][slot * 16 + j] = pk2(acc[j], acc[j]);
    }
    __syncthreads();

    // ---- GEMM phase ----
    const int jh = tid & 63;
    const int rg = tid >> 6;

    float2 b2 = *(const float2*)&lin_b[jh * 2];
    const u64 bias = pk2(b2.x, b2.y);
    u64 acc[8];
#pragma unroll
    for (int r = 0; r < 8; r++) acc[r] = bias;

    const u64* Wp = (const u64*)g_lwT;
#pragma unroll
    for (int d0 = 0; d0 < 128; d0 += 8) {
        u64 w[8];
#pragma unroll
        for (int i = 0; i < 8; i++) w[i] = Wp[(d0 + i) * 64 + jh];
#pragma unroll
        for (int i = 0; i < 8; i++) {
#pragma unroll
            for (int r = 0; r < 8; r++)
                acc[r] = fma2_(xd[rg + r * 4][d0 + i], w[i], acc[r]);
        }
    }
    u64* yp = (u64*)y;
#pragma unroll
    for (int r = 0; r < 8; r++)
        yp[(size_t)(row0 + rg + r * 4) * 64 + jh] = acc[r];
}

// ---------------------------------------------------------------------------
extern "C" void kernel_launch(void* const* d_in, const int* in_sizes, int n_in,
                              void* d_out, int out_size)
{
    const float* x    = (const float*)d_in[0];
    const int*   mraw = (const int*)  d_in[1];
    const float* wq   = (const float*)d_in[2];
    const float* wk   = (const float*)d_in[3];
    const float* wv   = (const float*)d_in[4];
    const float* lw   = (const float*)d_in[5];
    const float* lb   = (const float*)d_in[6];
    float*       y    = (float*)d_out;

    qkv_kernel<<<dim3(ROWS / 32, 3), 256>>>(x, wq, wk, wv);
    prepW_kernel<<<64, 256>>>(lw);
    prepM_kernel<<<32, 256>>>(mraw);
    attn_kernel<<<dim3(SEQ / QTILE, NPAIR, KSPLIT), 128>>>();
    proj_kernel<<<ROWS / 32, 256>>>(lb, y);
}

// round 11
// speedup vs baseline: 4.4672x; 1.3785x over previous
#include <cuda_runtime.h>
#include <cuda_fp16.h>
#include <cstdint>

// Problem constants
constexpr int BATCH = 4;
constexpr int SEQ   = 2048;
constexpr int DIM   = 128;
constexpr int HD    = 16;
constexpr int ROWS  = BATCH * SEQ;        // 8192
constexpr int NPAIR = BATCH * 7;          // head 7 is dead
constexpr int QH    = BATCH * 8 * SEQ;    // partial-array stride
constexpr int KSPLIT = 4;
constexpr int BK    = 64;
constexpr int QTILE = 64;

// Scratch (device globals — no allocation allowed)
__device__ uint32_t g_xh[ROWS * 64];          // x as packed f16 pairs
__device__ uint32_t g_wh[3][DIM * 64];        // Wq/Wk/Wv f16 pairs (Wk pre-scaled)
__device__ uint32_t g_qh[ROWS * 64];          // Q f16 pairs
__device__ uint32_t g_kh[ROWS * 64];          // K f16 pairs (scaled)
__device__ uint32_t g_vh[ROWS * 64];          // V f16 pairs
__device__ float g_lwT[DIM * DIM];
__device__ float g_maskf[ROWS];
__device__ float g_po[(size_t)KSPLIT * QH * HD];
__device__ float g_pm[(size_t)KSPLIT * QH];
__device__ float g_pl[(size_t)KSPLIT * QH];

__constant__ int c_head_order[8] = {0, 1, 1, 2, 3, 4, 5, 6};

// ---------------------------------------------------------------------------
// Helpers
// ---------------------------------------------------------------------------
typedef unsigned long long u64;

__device__ __forceinline__ u64 pk2(float lo, float hi) {
    u64 r; asm("mov.b64 %0,{%1,%2};" : "=l"(r) : "f"(lo), "f"(hi)); return r;
}
__device__ __forceinline__ u64 fma2_(u64 a, u64 b, u64 c) {
    u64 d; asm("fma.rn.f32x2 %0,%1,%2,%3;" : "=l"(d) : "l"(a), "l"(b), "l"(c)); return d;
}
__device__ __forceinline__ float ex2f(float x) {
    float y; asm("ex2.approx.ftz.f32 %0,%1;" : "=f"(y) : "f"(x)); return y;
}
__device__ __forceinline__ uint32_t ex2h2(uint32_t x) {
    uint32_t y; asm("ex2.approx.f16x2 %0,%1;" : "=r"(y) : "r"(x)); return y;
}
__device__ __forceinline__ uint32_t h2pack(float lo, float hi) {
    uint32_t r;
    asm("cvt.rn.f16x2.f32 %0, %1, %2;" : "=r"(r) : "f"(hi), "f"(lo));
    return r;
}
__device__ __forceinline__ uint32_t smem_u32(const void* p) {
    uint32_t a;
    asm("{ .reg .u64 t; cvta.to.shared.u64 t, %1; cvt.u32.u64 %0, t; }"
        : "=r"(a) : "l"(p));
    return a;
}
__device__ __forceinline__ void ldsm4(uint32_t* r, uint32_t addr) {
    asm volatile("ldmatrix.sync.aligned.m8n8.x4.shared.b16 {%0,%1,%2,%3}, [%4];"
                 : "=r"(r[0]), "=r"(r[1]), "=r"(r[2]), "=r"(r[3]) : "r"(addr));
}
__device__ __forceinline__ void ldsm4t(uint32_t* r, uint32_t addr) {
    asm volatile("ldmatrix.sync.aligned.m8n8.x4.trans.shared.b16 {%0,%1,%2,%3}, [%4];"
                 : "=r"(r[0]), "=r"(r[1]), "=r"(r[2]), "=r"(r[3]) : "r"(addr));
}
__device__ __forceinline__ void mma_f16(float* d, const uint32_t* a,
                                        uint32_t b0, uint32_t b1) {
    asm volatile(
        "mma.sync.aligned.m16n8k16.row.col.f32.f16.f16.f32 "
        "{%0,%1,%2,%3},{%4,%5,%6,%7},{%8,%9},{%0,%1,%2,%3};"
        : "+f"(d[0]), "+f"(d[1]), "+f"(d[2]), "+f"(d[3])
        : "r"(a[0]), "r"(a[1]), "r"(a[2]), "r"(a[3]), "r"(b0), "r"(b1));
}

constexpr uint32_t ONES_H2 = 0x3C003C00u;  // (1.0h, 1.0h)

// ---------------------------------------------------------------------------
// Kernel 0: convert x -> f16 pairs
// ---------------------------------------------------------------------------
__global__ __launch_bounds__(256) void xcvt_kernel(const float* __restrict__ x)
{
    int i = blockIdx.x * 256 + threadIdx.x;   // over ROWS*64
    float2 v = *(const float2*)&x[(size_t)i * 2];
    g_xh[i] = h2pack(v.x, v.y);
}

// ---------------------------------------------------------------------------
// Kernel 2a: transpose lin_w + convert Wq/Wk/Wv to f16 (Wk pre-scaled)
// ---------------------------------------------------------------------------
__global__ __launch_bounds__(256) void prepW_kernel(
    const float* __restrict__ wq, const float* __restrict__ wk,
    const float* __restrict__ wv, const float* __restrict__ lin_w)
{
    for (int idx = blockIdx.x * 256 + threadIdx.x; idx < DIM * DIM;
         idx += gridDim.x * 256) {
        int j = idx >> 7, c = idx & 127;
        g_lwT[c * 128 + j] = lin_w[idx];
    }
    const float sc = 0.08838834764831845f * 1.4426950408889634f;
    for (int idx = blockIdx.x * 256 + threadIdx.x; idx < 3 * DIM * 64;
         idx += gridDim.x * 256) {
        int s = idx / (DIM * 64);
        int r = idx - s * (DIM * 64);
        const float* W = (s == 0) ? wq : (s == 1) ? wk : wv;
        float2 w2 = *(const float2*)&W[(size_t)r * 2];
        float f = (s == 1) ? sc : 1.0f;
        g_wh[s][r] = h2pack(w2.x * f, w2.y * f);
    }
}

// ---------------------------------------------------------------------------
// Kernel 2b: mask -> additive log2-space float; dtype auto-detect.
// ---------------------------------------------------------------------------
__global__ __launch_bounds__(256) void prepM_kernel(const int* __restrict__ mraw)
{
    __shared__ int is64;
    if (threadIdx.x == 0) {
        int acc = 0;
        for (int i = 0; i < 64; i++) acc |= mraw[2 * i + 1];
        is64 = (acc == 0);
    }
    __syncthreads();
    for (int idx = blockIdx.x * 256 + threadIdx.x; idx < ROWS;
         idx += gridDim.x * 256) {
        int v = is64 ? mraw[2 * idx] : mraw[idx];
        g_maskf[idx] = (v == 0) ? -1442.6950408889634f : 0.0f;
    }
}

// ---------------------------------------------------------------------------
// Kernel 1: QKV projection on tensor cores (f16 mma, ldmatrix).
// CTA = 32 rows x 128 cols of one output; 8 warps = 2 row-groups x 4 col-groups
// (warp: 16 rows x 32 cols). Head-7 columns (112-127) skipped (dead).
// ---------------------------------------------------------------------------
__global__ __launch_bounds__(256) void qkv_kernel()
{
    __shared__ uint32_t xs[32 * 68];    // [row][68 words] (64 data + pad)
    __shared__ uint32_t ws[128 * 68];   // [d][68 words]

    const int tid  = threadIdx.x;
    const int row0 = blockIdx.x * 32;
    const int s    = blockIdx.y;        // 0=Q 1=K 2=V
    uint32_t* out  = (s == 0) ? g_qh : (s == 1) ? g_kh : g_vh;
    const uint32_t* wsrc = g_wh[s];

    // stage x tile (2048 words) and W (8192 words)
#pragma unroll
    for (int it = 0; it < 2; it++) {
        int j = tid + it * 256;
        int w4 = j * 4, r = w4 >> 6, c = w4 & 63;
        *(uint4*)&xs[r * 68 + c] = *(const uint4*)&g_xh[(size_t)(row0 + r) * 64 + c];
    }
#pragma unroll
    for (int it = 0; it < 8; it++) {
        int j = tid + it * 256;
        int w4 = j * 4, d = w4 >> 6, c = w4 & 63;
        *(uint4*)&ws[d * 68 + c] = *(const uint4*)&wsrc[d * 64 + c];
    }
    __syncthreads();

    const int w    = tid >> 5;
    const int lane = tid & 31;
    const int g    = lane >> 2;
    const int q4   = lane & 3;
    const int rowg = (w & 1) * 16;
    const int colg = (w >> 1) * 32;

    const uint32_t xs_base = smem_u32(xs);
    const uint32_t ws_base = smem_u32(ws);
    const uint32_t aaddr = xs_base + (uint32_t)((rowg + (lane & 15)) * 68 + ((lane >= 16) ? 4 : 0)) * 4;
    const uint32_t baddr = ws_base + (uint32_t)((lane & 15) * 68 + ((lane >= 16) ? 4 : 0)) * 4;

    float c[4][4];
#pragma unroll
    for (int t = 0; t < 4; t++)
#pragma unroll
        for (int i = 0; i < 4; i++) c[t][i] = 0.f;

#pragma unroll
    for (int kc = 0; kc < 8; kc++) {
        uint32_t a[4];
        ldsm4(a, aaddr + kc * 32);
#pragma unroll
        for (int np = 0; np < 2; np++) {
            const int n0 = colg + np * 16;
            if (n0 >= 112) continue;     // head 7 dead
            uint32_t bb[4];
            ldsm4t(bb, baddr + (uint32_t)kc * 16 * 272 + (uint32_t)(n0 >> 1) * 4);
            mma_f16(c[np * 2],     a, bb[0], bb[1]);
            mma_f16(c[np * 2 + 1], a, bb[2], bb[3]);
        }
    }

    const int row = row0 + rowg + g;
#pragma unroll
    for (int np = 0; np < 2; np++) {
#pragma unroll
        for (int nt = 0; nt < 2; nt++) {
            const int n0t = colg + np * 16 + nt * 8;
            if (n0t >= 112) continue;
            const int cp = (n0t >> 1) + q4;
            const int t = np * 2 + nt;
            out[(size_t)row * 64 + cp]       = h2pack(c[t][0], c[t][1]);
            out[(size_t)(row + 8) * 64 + cp] = h2pack(c[t][2], c[t][3]);
        }
    }
}

// ---------------------------------------------------------------------------
// Kernel 3: flash attention; ldmatrix frags, f16x2 exp, ones-mma for l.
// K and V staged identically [key][dim] f16 stride 40 halves.
// ---------------------------------------------------------------------------
__global__ __launch_bounds__(128, 8) void attn_kernel()
{
    __shared__ __half Ksm[BK][40];
    __shared__ __half Vsm[BK][40];
    __shared__ float  ms[BK];

    const int tid  = threadIdx.x;
    const int lane = tid & 31;
    const int g    = lane >> 2;
    const int q4   = lane & 3;
    const int pair = blockIdx.y;          // 0..27
    const int b    = pair / 7;
    const int h    = pair - b * 7;
    const int q0   = blockIdx.x * QTILE + (tid >> 5) * 16;
    const int kstart = blockIdx.z * (SEQ / KSPLIT);

    const int row_lo = q0 + g;
    const int row_hi = row_lo + 8;

    uint32_t aQ[4];
    aQ[0] = g_qh[(size_t)(b * SEQ + row_lo) * 64 + h * 8 + q4];
    aQ[1] = g_qh[(size_t)(b * SEQ + row_hi) * 64 + h * 8 + q4];
    aQ[2] = g_qh[(size_t)(b * SEQ + row_lo) * 64 + h * 8 + q4 + 4];
    aQ[3] = g_qh[(size_t)(b * SEQ + row_hi) * 64 + h * 8 + q4 + 4];

    float m_lo = -1e30f, m_hi = -1e30f;
    float o[2][4], lacc[4];
#pragma unroll
    for (int nt = 0; nt < 2; nt++)
#pragma unroll
        for (int i = 0; i < 4; i++) o[nt][i] = 0.f;
#pragma unroll
    for (int i = 0; i < 4; i++) lacc[i] = 0.f;

    // ldmatrix lane base addresses
    const uint32_t kb0 = smem_u32(Ksm);
    const uint32_t vb0 = smem_u32(Vsm);
    const uint32_t kaddr = kb0 + (uint32_t)(((lane & 7) + ((lane & 16) ? 8 : 0)) * 80
                                           + ((lane & 8) ? 16 : 0));
    const uint32_t vaddr = vb0 + (uint32_t)((lane & 15) * 80 + ((lane & 16) ? 16 : 0));

    const int skey = tid >> 1;
    const int koff = (tid & 1) * 4;

    for (int kb = kstart; kb < kstart + SEQ / KSPLIT; kb += BK) {
        __syncthreads();
        {
            size_t base = (size_t)(b * SEQ + kb + skey) * 64 + h * 8 + koff;
            *(uint4*)&Ksm[skey][koff * 2] = *(const uint4*)&g_kh[base];
            *(uint4*)&Vsm[skey][koff * 2] = *(const uint4*)&g_vh[base];
            if (tid < BK) ms[tid] = g_maskf[b * SEQ + kb + tid];
        }
        __syncthreads();

        // ---- QK^T: 8 tiles via 4 ldmatrix.x4; mask initializes accumulators ----
        float s[8][4];
#pragma unroll
        for (int tp = 0; tp < 4; tp++) {
            uint32_t kf[4];
            ldsm4(kf, kaddr + (uint32_t)tp * 1280);
            float2 mk0 = *(const float2*)&ms[(2 * tp) * 8 + 2 * q4];
            float2 mk1 = *(const float2*)&ms[(2 * tp + 1) * 8 + 2 * q4];
            s[2 * tp][0] = mk0.x; s[2 * tp][1] = mk0.y;
            s[2 * tp][2] = mk0.x; s[2 * tp][3] = mk0.y;
            s[2 * tp + 1][0] = mk1.x; s[2 * tp + 1][1] = mk1.y;
            s[2 * tp + 1][2] = mk1.x; s[2 * tp + 1][3] = mk1.y;
            mma_f16(s[2 * tp],     aQ, kf[0], kf[1]);
            mma_f16(s[2 * tp + 1], aQ, kf[2], kf[3]);
        }

        // ---- block row max ----
        float bm_lo = -1e30f, bm_hi = -1e30f;
#pragma unroll
        for (int t = 0; t < 8; t++) {
            bm_lo = fmaxf(bm_lo, fmaxf(s[t][0], s[t][1]));
            bm_hi = fmaxf(bm_hi, fmaxf(s[t][2], s[t][3]));
        }
        bm_lo = fmaxf(bm_lo, __shfl_xor_sync(0xffffffffu, bm_lo, 1));
        bm_lo = fmaxf(bm_lo, __shfl_xor_sync(0xffffffffu, bm_lo, 2));
        bm_hi = fmaxf(bm_hi, __shfl_xor_sync(0xffffffffu, bm_hi, 1));
        bm_hi = fmaxf(bm_hi, __shfl_xor_sync(0xffffffffu, bm_hi, 2));

        if ((bm_lo > m_lo) | (bm_hi > m_hi)) {
            float mn_lo = fmaxf(m_lo, bm_lo);
            float mn_hi = fmaxf(m_hi, bm_hi);
            float c_lo = ex2f(m_lo - mn_lo);
            float c_hi = ex2f(m_hi - mn_hi);
            lacc[0] *= c_lo; lacc[2] *= c_hi;
#pragma unroll
            for (int nt = 0; nt < 2; nt++) {
                o[nt][0] *= c_lo; o[nt][1] *= c_lo;
                o[nt][2] *= c_hi; o[nt][3] *= c_hi;
            }
            m_lo = mn_lo; m_hi = mn_hi;
        }

        // ---- exp (f16x2) + PV + l per 16-key group ----
#pragma unroll
        for (int G = 0; G < 4; G++) {
            uint32_t aP[4];
#pragma unroll
            for (int u = 0; u < 2; u++) {
                const int t = 2 * G + u;
                float d0 = s[t][0] - m_lo, d1 = s[t][1] - m_lo;
                float d2 = s[t][2] - m_hi, d3 = s[t][3] - m_hi;
                aP[u * 2 + 0] = ex2h2(h2pack(d0, d1));
                aP[u * 2 + 1] = ex2h2(h2pack(d2, d3));
            }
            // reorder to A-frag: a0=lo(2G), a1=hi(2G), a2=lo(2G+1), a3=hi(2G+1)
            uint32_t aF[4] = {aP[0], aP[1], aP[2], aP[3]};
            uint32_t vf[4];
            ldsm4t(vf, vaddr + (uint32_t)G * 1280);
            mma_f16(o[0], aF, vf[0], vf[1]);
            mma_f16(o[1], aF, vf[2], vf[3]);
            mma_f16(lacc, aF, ONES_H2, ONES_H2);
        }
    }

    // ---- finalize: l comes fully reduced from the ones-mma ----
    const int z = blockIdx.z;
    const size_t qlo = (size_t)pair * SEQ + row_lo;
    const size_t qhi = (size_t)pair * SEQ + row_hi;
    float* plo = g_po + ((size_t)z * QH + qlo) * HD;
    float* phi = g_po + ((size_t)z * QH + qhi) * HD;
    *(float2*)&plo[2 * q4]     = make_float2(o[0][0], o[0][1]);
    *(float2*)&plo[8 + 2 * q4] = make_float2(o[1][0], o[1][1]);
    *(float2*)&phi[2 * q4]     = make_float2(o[0][2], o[0][3]);
    *(float2*)&phi[8 + 2 * q4] = make_float2(o[1][2], o[1][3]);
    if (q4 == 0) {
        g_pm[(size_t)z * QH + qlo] = m_lo;
        g_pl[(size_t)z * QH + qlo] = lacc[0];
        g_pm[(size_t)z * QH + qhi] = m_hi;
        g_pl[(size_t)z * QH + qhi] = lacc[2];
    }
}

// ---------------------------------------------------------------------------
// Kernel 4: FUSED merge + head-reorder gather + output projection.
// ---------------------------------------------------------------------------
__global__ __launch_bounds__(256) void proj_kernel(
    const float* __restrict__ lin_b,
    float* __restrict__ y)
{
    __shared__ u64 xd[32][128];
    const int tid  = threadIdx.x;
    const int row0 = blockIdx.x * 32;
    const int b    = row0 >> 11;
    const int rin0 = row0 & 2047;

    {
        const int r    = tid >> 3;
        const int slot = tid & 7;
        const int hh   = c_head_order[slot];
        const size_t qidx = (size_t)(b * 7 + hh) * SEQ + rin0 + r;

        float m[KSPLIT], l[KSPLIT], c[KSPLIT];
        float mm = -1e30f;
#pragma unroll
        for (int z = 0; z < KSPLIT; z++) {
            m[z] = g_pm[(size_t)z * QH + qidx];
            l[z] = g_pl[(size_t)z * QH + qidx];
            mm = fmaxf(mm, m[z]);
        }
        float denom = 0.f;
#pragma unroll
        for (int z = 0; z < KSPLIT; z++) {
            c[z] = ex2f(m[z] - mm);
            denom += l[z] * c[z];
        }
        float inv = 1.0f / denom;
#pragma unroll
        for (int z = 0; z < KSPLIT; z++) c[z] *= inv;

        float acc[16];
#pragma unroll
        for (int j = 0; j < 16; j++) acc[j] = 0.f;
#pragma unroll
        for (int z = 0; z < KSPLIT; z++) {
            const float4* po = (const float4*)(g_po + ((size_t)z * QH + qidx) * HD);
#pragma unroll
            for (int k4 = 0; k4 < 4; k4++) {
                float4 a = po[k4];
                acc[k4 * 4 + 0] = fmaf(a.x, c[z], acc[k4 * 4 + 0]);
                acc[k4 * 4 + 1] = fmaf(a.y, c[z], acc[k4 * 4 + 1]);
                acc[k4 * 4 + 2] = fmaf(a.z, c[z], acc[k4 * 4 + 2]);
                acc[k4 * 4 + 3] = fmaf(a.w, c[z], acc[k4 * 4 + 3]);
            }
        }
#pragma unroll
        for (int j = 0; j < 16; j++)
            xd[r][slot * 16 + j] = pk2(acc[j], acc[j]);
    }
    __syncthreads();

    const int jh = tid & 63;
    const int rg = tid >> 6;

    float2 b2 = *(const float2*)&lin_b[jh * 2];
    const u64 bias = pk2(b2.x, b2.y);
    u64 acc[8];
#pragma unroll
    for (int r = 0; r < 8; r++) acc[r] = bias;

    const u64* Wp = (const u64*)g_lwT;
#pragma unroll
    for (int d0 = 0; d0 < 128; d0 += 8) {
        u64 w[8];
#pragma unroll
        for (int i = 0; i < 8; i++) w[i] = Wp[(d0 + i) * 64 + jh];
#pragma unroll
        for (int i = 0; i < 8; i++) {
#pragma unroll
            for (int r = 0; r < 8; r++)
                acc[r] = fma2_(xd[rg + r * 4][d0 + i], w[i], acc[r]);
        }
    }
    u64* yp = (u64*)y;
#pragma unroll
    for (int r = 0; r < 8; r++)
        yp[(size_t)(row0 + rg + r * 4) * 64 + jh] = acc[r];
}

// ---------------------------------------------------------------------------
extern "C" void kernel_launch(void* const* d_in, const int* in_sizes, int n_in,
                              void* d_out, int out_size)
{
    const float* x    = (const float*)d_in[0];
    const int*   mraw = (const int*)  d_in[1];
    const float* wq   = (const float*)d_in[2];
    const float* wk   = (const float*)d_in[3];
    const float* wv   = (const float*)d_in[4];
    const float* lw   = (const float*)d_in[5];
    const float* lb   = (const float*)d_in[6];
    float*       y    = (float*)d_out;

    xcvt_kernel<<<ROWS * 64 / 256, 256>>>(x);
    prepW_kernel<<<64, 256>>>(wq, wk, wv, lw);
    prepM_kernel<<<32, 256>>>(mraw);
    qkv_kernel<<<dim3(ROWS / 32, 3), 256>>>();
    attn_kernel<<<dim3(SEQ / QTILE, NPAIR, KSPLIT), 128>>>();
    proj_kernel<<<ROWS / 32, 256>>>(lb, y);
}

// round 12
// speedup vs baseline: 4.8290x; 1.0810x over previous
#include <cuda_runtime.h>
#include <cuda_fp16.h>
#include <cstdint>

// Problem constants
constexpr int BATCH = 4;
constexpr int SEQ   = 2048;
constexpr int DIM   = 128;
constexpr int HD    = 16;
constexpr int ROWS  = BATCH * SEQ;        // 8192
constexpr int NPAIR = BATCH * 7;          // head 7 is dead
constexpr int QH    = BATCH * 8 * SEQ;    // partial-array stride
constexpr int KSPLIT = 4;
constexpr int BK    = 64;
constexpr int QTILE = 64;
constexpr int NB    = (SEQ / KSPLIT) / BK;   // 8 key-blocks per CTA

// Scratch (device globals — no allocation allowed)
__device__ uint32_t g_xh[ROWS * 64];          // x as packed f16 pairs
__device__ uint32_t g_wh[3][DIM * 64];        // Wq/Wk/Wv f16 pairs (Wk pre-scaled)
__device__ uint32_t g_qh[ROWS * 64];
__device__ uint32_t g_kh[ROWS * 64];
__device__ uint32_t g_vh[ROWS * 64];
__device__ float g_lwT[DIM * DIM];
__device__ float g_maskf[ROWS];
__device__ float g_po[(size_t)KSPLIT * QH * HD];
__device__ float g_pm[(size_t)KSPLIT * QH];
__device__ float g_pl[(size_t)KSPLIT * QH];

__constant__ int c_head_order[8] = {0, 1, 1, 2, 3, 4, 5, 6};

// ---------------------------------------------------------------------------
// Helpers
// ---------------------------------------------------------------------------
typedef unsigned long long u64;

__device__ __forceinline__ u64 pk2(float lo, float hi) {
    u64 r; asm("mov.b64 %0,{%1,%2};" : "=l"(r) : "f"(lo), "f"(hi)); return r;
}
__device__ __forceinline__ u64 fma2_(u64 a, u64 b, u64 c) {
    u64 d; asm("fma.rn.f32x2 %0,%1,%2,%3;" : "=l"(d) : "l"(a), "l"(b), "l"(c)); return d;
}
__device__ __forceinline__ float ex2f(float x) {
    float y; asm("ex2.approx.ftz.f32 %0,%1;" : "=f"(y) : "f"(x)); return y;
}
__device__ __forceinline__ uint32_t ex2h2(uint32_t x) {
    uint32_t y; asm("ex2.approx.f16x2 %0,%1;" : "=r"(y) : "r"(x)); return y;
}
__device__ __forceinline__ uint32_t h2pack(float lo, float hi) {
    uint32_t r;
    asm("cvt.rn.f16x2.f32 %0, %1, %2;" : "=r"(r) : "f"(hi), "f"(lo));
    return r;
}
__device__ __forceinline__ uint32_t smem_u32(const void* p) {
    uint32_t a;
    asm("{ .reg .u64 t; cvta.to.shared.u64 t, %1; cvt.u32.u64 %0, t; }"
        : "=r"(a) : "l"(p));
    return a;
}
__device__ __forceinline__ void ldsm4(uint32_t* r, uint32_t addr) {
    asm volatile("ldmatrix.sync.aligned.m8n8.x4.shared.b16 {%0,%1,%2,%3}, [%4];"
                 : "=r"(r[0]), "=r"(r[1]), "=r"(r[2]), "=r"(r[3]) : "r"(addr));
}
__device__ __forceinline__ void ldsm4t(uint32_t* r, uint32_t addr) {
    asm volatile("ldmatrix.sync.aligned.m8n8.x4.trans.shared.b16 {%0,%1,%2,%3}, [%4];"
                 : "=r"(r[0]), "=r"(r[1]), "=r"(r[2]), "=r"(r[3]) : "r"(addr));
}
__device__ __forceinline__ void mma_f16(float* d, const uint32_t* a,
                                        uint32_t b0, uint32_t b1) {
    asm volatile(
        "mma.sync.aligned.m16n8k16.row.col.f32.f16.f16.f32 "
        "{%0,%1,%2,%3},{%4,%5,%6,%7},{%8,%9},{%0,%1,%2,%3};"
        : "+f"(d[0]), "+f"(d[1]), "+f"(d[2]), "+f"(d[3])
        : "r"(a[0]), "r"(a[1]), "r"(a[2]), "r"(a[3]), "r"(b0), "r"(b1));
}
__device__ __forceinline__ void cp16(uint32_t dst, const void* src) {
    asm volatile("cp.async.ca.shared.global [%0], [%1], 16;"
                 :: "r"(dst), "l"(src) : "memory");
}
__device__ __forceinline__ void cp_commit() {
    asm volatile("cp.async.commit_group;" ::: "memory");
}
template <int N> __device__ __forceinline__ void cp_wait() {
    asm volatile("cp.async.wait_group %0;" :: "n"(N) : "memory");
}

constexpr uint32_t ONES_H2 = 0x3C003C00u;  // (1.0h, 1.0h)

// ---------------------------------------------------------------------------
// Kernel A: fused prep — x->f16, W->f16 (Wk pre-scaled), lin_w transpose, mask.
// ---------------------------------------------------------------------------
__global__ __launch_bounds__(256) void prep_kernel(
    const float* __restrict__ x,
    const float* __restrict__ wq, const float* __restrict__ wk,
    const float* __restrict__ wv, const float* __restrict__ lin_w,
    const int*   __restrict__ mraw)
{
    const int gid = blockIdx.x * 256 + threadIdx.x;
    const int nth = gridDim.x * 256;

    // x -> f16 pairs
    for (int i = gid; i < ROWS * 64; i += nth) {
        float2 v = *(const float2*)&x[(size_t)i * 2];
        g_xh[i] = h2pack(v.x, v.y);
    }
    // W -> f16 pairs (Wk scaled)
    const float sc = 0.08838834764831845f * 1.4426950408889634f;
    for (int idx = gid; idx < 3 * DIM * 64; idx += nth) {
        int s = idx / (DIM * 64);
        int r = idx - s * (DIM * 64);
        const float* W = (s == 0) ? wq : (s == 1) ? wk : wv;
        float2 w2 = *(const float2*)&W[(size_t)r * 2];
        float f = (s == 1) ? sc : 1.0f;
        g_wh[s][r] = h2pack(w2.x * f, w2.y * f);
    }
    // lin_w transpose
    for (int idx = gid; idx < DIM * DIM; idx += nth) {
        int j = idx >> 7, c = idx & 127;
        g_lwT[c * 128 + j] = lin_w[idx];
    }
    // mask (dtype auto-detect: int64 LE high words all zero)
    __shared__ int is64;
    if (threadIdx.x == 0) {
        int acc = 0;
        for (int i = 0; i < 64; i++) acc |= mraw[2 * i + 1];
        is64 = (acc == 0);
    }
    __syncthreads();
    for (int idx = gid; idx < ROWS; idx += nth) {
        int v = is64 ? mraw[2 * idx] : mraw[idx];
        g_maskf[idx] = (v == 0) ? -1442.6950408889634f : 0.0f;
    }
}

// ---------------------------------------------------------------------------
// Kernel 1: QKV projection on tensor cores (f16 mma, ldmatrix).
// ---------------------------------------------------------------------------
__global__ __launch_bounds__(256) void qkv_kernel()
{
    __shared__ uint32_t xs[32 * 68];
    __shared__ uint32_t ws[128 * 68];

    const int tid  = threadIdx.x;
    const int row0 = blockIdx.x * 32;
    const int s    = blockIdx.y;
    uint32_t* out  = (s == 0) ? g_qh : (s == 1) ? g_kh : g_vh;
    const uint32_t* wsrc = g_wh[s];

#pragma unroll
    for (int it = 0; it < 2; it++) {
        int j = tid + it * 256;
        int w4 = j * 4, r = w4 >> 6, c = w4 & 63;
        *(uint4*)&xs[r * 68 + c] = *(const uint4*)&g_xh[(size_t)(row0 + r) * 64 + c];
    }
#pragma unroll
    for (int it = 0; it < 8; it++) {
        int j = tid + it * 256;
        int w4 = j * 4, d = w4 >> 6, c = w4 & 63;
        *(uint4*)&ws[d * 68 + c] = *(const uint4*)&wsrc[d * 64 + c];
    }
    __syncthreads();

    const int w    = tid >> 5;
    const int lane = tid & 31;
    const int g    = lane >> 2;
    const int q4   = lane & 3;
    const int rowg = (w & 1) * 16;
    const int colg = (w >> 1) * 32;

    const uint32_t xs_base = smem_u32(xs);
    const uint32_t ws_base = smem_u32(ws);
    const uint32_t aaddr = xs_base + (uint32_t)((rowg + (lane & 15)) * 68 + ((lane >= 16) ? 4 : 0)) * 4;
    const uint32_t baddr = ws_base + (uint32_t)((lane & 15) * 68 + ((lane >= 16) ? 4 : 0)) * 4;

    float c[4][4];
#pragma unroll
    for (int t = 0; t < 4; t++)
#pragma unroll
        for (int i = 0; i < 4; i++) c[t][i] = 0.f;

#pragma unroll
    for (int kc = 0; kc < 8; kc++) {
        uint32_t a[4];
        ldsm4(a, aaddr + kc * 32);
#pragma unroll
        for (int np = 0; np < 2; np++) {
            const int n0 = colg + np * 16;
            if (n0 >= 112) continue;
            uint32_t bb[4];
            ldsm4t(bb, baddr + (uint32_t)kc * 16 * 272 + (uint32_t)(n0 >> 1) * 4);
            mma_f16(c[np * 2],     a, bb[0], bb[1]);
            mma_f16(c[np * 2 + 1], a, bb[2], bb[3]);
        }
    }

    const int row = row0 + rowg + g;
#pragma unroll
    for (int np = 0; np < 2; np++) {
#pragma unroll
        for (int nt = 0; nt < 2; nt++) {
            const int n0t = colg + np * 16 + nt * 8;
            if (n0t >= 112) continue;
            const int cp = (n0t >> 1) + q4;
            const int t = np * 2 + nt;
            out[(size_t)row * 64 + cp]       = h2pack(c[t][0], c[t][1]);
            out[(size_t)(row + 8) * 64 + cp] = h2pack(c[t][2], c[t][3]);
        }
    }
}

// ---------------------------------------------------------------------------
// Kernel 3: flash attention; cp.async double-buffered staging.
// Math identical to R11 (ldmatrix frags, f16x2 exp, ones-mma for l).
// ---------------------------------------------------------------------------
__global__ __launch_bounds__(128, 8) void attn_kernel()
{
    __shared__ __align__(16) __half Ksm[2][BK][40];
    __shared__ __align__(16) __half Vsm[2][BK][40];
    __shared__ __align__(16) float  ms[2][BK];

    const int tid  = threadIdx.x;
    const int lane = tid & 31;
    const int g    = lane >> 2;
    const int q4   = lane & 3;
    const int pair = blockIdx.y;
    const int b    = pair / 7;
    const int h    = pair - b * 7;
    const int q0   = blockIdx.x * QTILE + (tid >> 5) * 16;
    const int kstart = blockIdx.z * (SEQ / KSPLIT);

    const int row_lo = q0 + g;
    const int row_hi = row_lo + 8;

    uint32_t aQ[4];
    aQ[0] = g_qh[(size_t)(b * SEQ + row_lo) * 64 + h * 8 + q4];
    aQ[1] = g_qh[(size_t)(b * SEQ + row_hi) * 64 + h * 8 + q4];
    aQ[2] = g_qh[(size_t)(b * SEQ + row_lo) * 64 + h * 8 + q4 + 4];
    aQ[3] = g_qh[(size_t)(b * SEQ + row_hi) * 64 + h * 8 + q4 + 4];

    float m_lo = -1e30f, m_hi = -1e30f;
    float o[2][4], lacc[4];
#pragma unroll
    for (int nt = 0; nt < 2; nt++)
#pragma unroll
        for (int i = 0; i < 4; i++) o[nt][i] = 0.f;
#pragma unroll
    for (int i = 0; i < 4; i++) lacc[i] = 0.f;

    const uint32_t ksm0 = smem_u32(Ksm);
    const uint32_t vsm0 = smem_u32(Vsm);
    const uint32_t msm0 = smem_u32(ms);
    const uint32_t laneK = (uint32_t)(((lane & 7) + ((lane & 16) ? 8 : 0)) * 80
                                      + ((lane & 8) ? 16 : 0));
    const uint32_t laneV = (uint32_t)((lane & 15) * 80 + ((lane & 16) ? 16 : 0));

    const int skey = tid >> 1;
    const int koff = (tid & 1) * 4;
    const uint32_t sdst = (uint32_t)(skey * 80 + koff * 4);

    auto stage = [&](int buf, int kb) {
        size_t base = (size_t)(b * SEQ + kb + skey) * 64 + h * 8 + koff;
        cp16(ksm0 + (uint32_t)buf * 5120u + sdst, &g_kh[base]);
        cp16(vsm0 + (uint32_t)buf * 5120u + sdst, &g_vh[base]);
        if (tid < 16)
            cp16(msm0 + (uint32_t)buf * 256u + (uint32_t)tid * 16u,
                 &g_maskf[b * SEQ + kb + tid * 4]);
        cp_commit();
    };

    stage(0, kstart);
    stage(1, kstart + BK);

    for (int i = 0; i < NB; i++) {
        if (i < NB - 1) cp_wait<1>(); else cp_wait<0>();
        __syncthreads();
        const int buf = i & 1;
        const uint32_t kaddr = ksm0 + (uint32_t)buf * 5120u + laneK;
        const uint32_t vaddr = vsm0 + (uint32_t)buf * 5120u + laneV;
        const float* msp = ms[buf];

        // ---- QK^T: 8 tiles via 4 ldmatrix.x4; mask initializes accumulators ----
        float s[8][4];
#pragma unroll
        for (int tp = 0; tp < 4; tp++) {
            uint32_t kf[4];
            ldsm4(kf, kaddr + (uint32_t)tp * 1280);
            float2 mk0 = *(const float2*)&msp[(2 * tp) * 8 + 2 * q4];
            float2 mk1 = *(const float2*)&msp[(2 * tp + 1) * 8 + 2 * q4];
            s[2 * tp][0] = mk0.x; s[2 * tp][1] = mk0.y;
            s[2 * tp][2] = mk0.x; s[2 * tp][3] = mk0.y;
            s[2 * tp + 1][0] = mk1.x; s[2 * tp + 1][1] = mk1.y;
            s[2 * tp + 1][2] = mk1.x; s[2 * tp + 1][3] = mk1.y;
            mma_f16(s[2 * tp],     aQ, kf[0], kf[1]);
            mma_f16(s[2 * tp + 1], aQ, kf[2], kf[3]);
        }

        // ---- block row max ----
        float bm_lo = -1e30f, bm_hi = -1e30f;
#pragma unroll
        for (int t = 0; t < 8; t++) {
            bm_lo = fmaxf(bm_lo, fmaxf(s[t][0], s[t][1]));
            bm_hi = fmaxf(bm_hi, fmaxf(s[t][2], s[t][3]));
        }
        bm_lo = fmaxf(bm_lo, __shfl_xor_sync(0xffffffffu, bm_lo, 1));
        bm_lo = fmaxf(bm_lo, __shfl_xor_sync(0xffffffffu, bm_lo, 2));
        bm_hi = fmaxf(bm_hi, __shfl_xor_sync(0xffffffffu, bm_hi, 1));
        bm_hi = fmaxf(bm_hi, __shfl_xor_sync(0xffffffffu, bm_hi, 2));

        if ((bm_lo > m_lo) | (bm_hi > m_hi)) {
            float mn_lo = fmaxf(m_lo, bm_lo);
            float mn_hi = fmaxf(m_hi, bm_hi);
            float c_lo = ex2f(m_lo - mn_lo);
            float c_hi = ex2f(m_hi - mn_hi);
            lacc[0] *= c_lo; lacc[2] *= c_hi;
#pragma unroll
            for (int nt = 0; nt < 2; nt++) {
                o[nt][0] *= c_lo; o[nt][1] *= c_lo;
                o[nt][2] *= c_hi; o[nt][3] *= c_hi;
            }
            m_lo = mn_lo; m_hi = mn_hi;
        }

        // ---- exp (f16x2) + PV + l per 16-key group ----
#pragma unroll
        for (int G = 0; G < 4; G++) {
            uint32_t aF[4];
#pragma unroll
            for (int u = 0; u < 2; u++) {
                const int t = 2 * G + u;
                float d0 = s[t][0] - m_lo, d1 = s[t][1] - m_lo;
                float d2 = s[t][2] - m_hi, d3 = s[t][3] - m_hi;
                aF[u * 2 + 0] = ex2h2(h2pack(d0, d1));
                aF[u * 2 + 1] = ex2h2(h2pack(d2, d3));
            }
            uint32_t vf[4];
            ldsm4t(vf, vaddr + (uint32_t)G * 1280);
            mma_f16(o[0], aF, vf[0], vf[1]);
            mma_f16(o[1], aF, vf[2], vf[3]);
            mma_f16(lacc, aF, ONES_H2, ONES_H2);
        }

        __syncthreads();
        if (i + 2 < NB) stage(buf, kstart + (i + 2) * BK);
    }

    // ---- finalize ----
    const int z = blockIdx.z;
    const size_t qlo = (size_t)pair * SEQ + row_lo;
    const size_t qhi = (size_t)pair * SEQ + row_hi;
    float* plo = g_po + ((size_t)z * QH + qlo) * HD;
    float* phi = g_po + ((size_t)z * QH + qhi) * HD;
    *(float2*)&plo[2 * q4]     = make_float2(o[0][0], o[0][1]);
    *(float2*)&plo[8 + 2 * q4] = make_float2(o[1][0], o[1][1]);
    *(float2*)&phi[2 * q4]     = make_float2(o[0][2], o[0][3]);
    *(float2*)&phi[8 + 2 * q4] = make_float2(o[1][2], o[1][3]);
    if (q4 == 0) {
        g_pm[(size_t)z * QH + qlo] = m_lo;
        g_pl[(size_t)z * QH + qlo] = lacc[0];
        g_pm[(size_t)z * QH + qhi] = m_hi;
        g_pl[(size_t)z * QH + qhi] = lacc[2];
    }
}

// ---------------------------------------------------------------------------
// Kernel 4: FUSED merge + gather + output projection. 16-row tiles (512 CTAs).
// Gather thread = (row, slot, half): all 256 threads active.
// ---------------------------------------------------------------------------
__global__ __launch_bounds__(256) void proj_kernel(
    const float* __restrict__ lin_b,
    float* __restrict__ y)
{
    __shared__ u64 xd[16][128];
    const int tid  = threadIdx.x;
    const int row0 = blockIdx.x * 16;
    const int b    = row0 >> 11;
    const int rin0 = row0 & 2047;

    {
        const int r    = tid >> 4;          // 0..15
        const int slot = (tid >> 1) & 7;    // 0..7
        const int half = tid & 1;           // 0..1
        const int hh   = c_head_order[slot];
        const size_t qidx = (size_t)(b * 7 + hh) * SEQ + rin0 + r;

        float m[KSPLIT], l[KSPLIT], c[KSPLIT];
        float mm = -1e30f;
#pragma unroll
        for (int z = 0; z < KSPLIT; z++) {
            m[z] = g_pm[(size_t)z * QH + qidx];
            l[z] = g_pl[(size_t)z * QH + qidx];
            mm = fmaxf(mm, m[z]);
        }
        float denom = 0.f;
#pragma unroll
        for (int z = 0; z < KSPLIT; z++) {
            c[z] = ex2f(m[z] - mm);
            denom += l[z] * c[z];
        }
        float inv = 1.0f / denom;
#pragma unroll
        for (int z = 0; z < KSPLIT; z++) c[z] *= inv;

        float acc[8];
#pragma unroll
        for (int j = 0; j < 8; j++) acc[j] = 0.f;
#pragma unroll
        for (int z = 0; z < KSPLIT; z++) {
            const float4* po = (const float4*)(g_po + ((size_t)z * QH + qidx) * HD + half * 8);
#pragma unroll
            for (int k4 = 0; k4 < 2; k4++) {
                float4 a = po[k4];
                acc[k4 * 4 + 0] = fmaf(a.x, c[z], acc[k4 * 4 + 0]);
                acc[k4 * 4 + 1] = fmaf(a.y, c[z], acc[k4 * 4 + 1]);
                acc[k4 * 4 + 2] = fmaf(a.z, c[z], acc[k4 * 4 + 2]);
                acc[k4 * 4 + 3] = fmaf(a.w, c[z], acc[k4 * 4 + 3]);
            }
        }
#pragma unroll
        for (int j = 0; j < 8; j++)
            xd[r][slot * 16 + half * 8 + j] = pk2(acc[j], acc[j]);
    }
    __syncthreads();

    const int jh = tid & 63;
    const int rg = tid >> 6;            // 0..3; rows rg, rg+4, rg+8, rg+12

    float2 b2 = *(const float2*)&lin_b[jh * 2];
    const u64 bias = pk2(b2.x, b2.y);
    u64 acc[4];
#pragma unroll
    for (int r = 0; r < 4; r++) acc[r] = bias;

    const u64* Wp = (const u64*)g_lwT;
#pragma unroll
    for (int d0 = 0; d0 < 128; d0 += 8) {
        u64 w[8];
#pragma unroll
        for (int i = 0; i < 8; i++) w[i] = Wp[(d0 + i) * 64 + jh];
#pragma unroll
        for (int i = 0; i < 8; i++) {
#pragma unroll
            for (int r = 0; r < 4; r++)
                acc[r] = fma2_(xd[rg + r * 4][d0 + i], w[i], acc[r]);
        }
    }
    u64* yp = (u64*)y;
#pragma unroll
    for (int r = 0; r < 4; r++)
        yp[(size_t)(row0 + rg + r * 4) * 64 + jh] = acc[r];
}

// ---------------------------------------------------------------------------
extern "C" void kernel_launch(void* const* d_in, const int* in_sizes, int n_in,
                              void* d_out, int out_size)
{
    const float* x    = (const float*)d_in[0];
    const int*   mraw = (const int*)  d_in[1];
    const float* wq   = (const float*)d_in[2];
    const float* wk   = (const float*)d_in[3];
    const float* wv   = (const float*)d_in[4];
    const float* lw   = (const float*)d_in[5];
    const float* lb   = (const float*)d_in[6];
    float*       y    = (float*)d_out;

    prep_kernel<<<256, 256>>>(x, wq, wk, wv, lw, mraw);
    qkv_kernel<<<dim3(ROWS / 32, 3), 256>>>();
    attn_kernel<<<dim3(SEQ / QTILE, NPAIR, KSPLIT), 128>>>();
    proj_kernel<<<ROWS / 16, 256>>>(lb, y);
}